// round 5
// baseline (speedup 1.0000x reference)
#include <cuda_runtime.h>
#include <cuda_bf16.h>
#include <math.h>
#include <stdint.h>

// ---------------------------------------------------------------------------
// Problem constants
// ---------------------------------------------------------------------------
#define BB   4
#define SS   1024
#define DD   1024
#define HH   16
#define HD   64
#define FFD  4096
#define NT   (BB*SS)
#define INV_SCALE 0.125f
#define LAM_EFF   0.5f

// ---------------------------------------------------------------------------
// Scratch (device globals)
// ---------------------------------------------------------------------------
__device__ float buf_xn  [NT*DD];
__device__ float buf_Q   [NT*DD];
__device__ float buf_K   [NT*DD];
__device__ float buf_tK  [NT*DD];
__device__ float buf_V   [NT*DD];
__device__ float buf_tQJ [NT*DD];
__device__ float buf_ao  [NT*DD];
__device__ float buf_x1  [NT*DD];
__device__ float buf_th  [NT*DD];
__device__ float buf_hhat[NT*FFD];
__device__ float buf_dlt [NT*FFD];
__device__ float buf_h1  [NT*FFD];
__device__ float buf_th1 [NT*FFD];

// ---------------------------------------------------------------------------
// Async-copy + mma helpers
// ---------------------------------------------------------------------------
__device__ __forceinline__ void cp16(uint32_t smem_dst, const void* gsrc)
{
    asm volatile("cp.async.cg.shared.global [%0], [%1], 16;\n"
                 :: "r"(smem_dst), "l"(gsrc));
}
__device__ __forceinline__ void cp_commit()
{
    asm volatile("cp.async.commit_group;\n");
}
template<int N> __device__ __forceinline__ void cp_wait()
{
    asm volatile("cp.async.wait_group %0;\n" :: "n"(N));
}

__device__ __forceinline__ void mma8(float* c,
    uint32_t a0, uint32_t a1, uint32_t a2, uint32_t a3,
    uint32_t b0, uint32_t b1)
{
    asm volatile(
        "mma.sync.aligned.m16n8k8.row.col.f32.tf32.tf32.f32 "
        "{%0,%1,%2,%3},{%4,%5,%6,%7},{%8,%9},{%0,%1,%2,%3};"
        : "+f"(c[0]), "+f"(c[1]), "+f"(c[2]), "+f"(c[3])
        : "r"(a0), "r"(a1), "r"(a2), "r"(a3), "r"(b0), "r"(b1));
}

// ---------------------------------------------------------------------------
// TF32 GEMM v3: 128x128x32 block, 3-stage cp.async, frag double-buffer.
// 8 warps (2 M x 4 N), warp tile 64x32 (4x4 m16n8k8).
// ---------------------------------------------------------------------------
#define BM 128
#define BN 128
#define BK 32
#define ASTR 36
#define BSTR 136
#define ASZ (BM*ASTR)
#define BSZ (BK*BSTR)
#define NSTG 3
#define GEMM_SMEM (NSTG*(ASZ + BSZ) * 4)   // 107520 bytes

template<bool BIAS, bool RES, bool TOUT>
__global__ void __launch_bounds__(256) gemm_tf32_kernel(
    const float* __restrict__ A, const float* __restrict__ Bm,
    const float* __restrict__ bias, const float* __restrict__ Res,
    float* __restrict__ C, float* __restrict__ CT,
    int M, int N, int K)
{
    extern __shared__ float smem[];
    float* As = smem;
    float* Bs = smem + NSTG * ASZ;
    const uint32_t smem_u = (uint32_t)__cvta_generic_to_shared(smem);
    const uint32_t As_u = smem_u;
    const uint32_t Bs_u = smem_u + NSTG * ASZ * 4;

    const int tid = threadIdx.x;
    const int bn = blockIdx.x * BN, bm = blockIdx.y * BM;
    const int wid = tid >> 5, lane = tid & 31;
    const int wm = wid & 1, wn = wid >> 1;
    const int gid = lane >> 2, tig = lane & 3;

    float c[4][4][4] = {};

    auto load_stage = [&](int k0, int st) {
        uint32_t a_base = As_u + st * ASZ * 4;
        uint32_t b_base = Bs_u + st * BSZ * 4;
        #pragma unroll
        for (int i = 0; i < 4; i++) {
            int idx = tid + (i << 8);
            int r = idx >> 3, cq = (idx & 7) << 2;
            cp16(a_base + (r * ASTR + cq) * 4,
                 &A[(size_t)(bm + r) * K + k0 + cq]);
        }
        #pragma unroll
        for (int i = 0; i < 4; i++) {
            int idx = tid + (i << 8);
            int r = idx >> 5, cq = (idx & 31) << 2;
            cp16(b_base + (r * BSTR + cq) * 4,
                 &Bm[(size_t)(k0 + r) * N + bn + cq]);
        }
        cp_commit();
    };

    const int KT = K / BK;
    load_stage(0, 0);
    load_stage(BK, 1);

    uint32_t a[2][4][4], b[2][4][2];
    const uint32_t* Au;
    const uint32_t* Bu;

    auto ldfrag = [&](int kk, int buf) {
        int kb = kk << 3;
        #pragma unroll
        for (int mt = 0; mt < 4; mt++) {
            int ar = wm * 64 + mt * 16 + gid;
            a[buf][mt][0] = Au[(ar    ) * ASTR + kb + tig];
            a[buf][mt][1] = Au[(ar + 8) * ASTR + kb + tig];
            a[buf][mt][2] = Au[(ar    ) * ASTR + kb + tig + 4];
            a[buf][mt][3] = Au[(ar + 8) * ASTR + kb + tig + 4];
        }
        #pragma unroll
        for (int nt = 0; nt < 4; nt++) {
            int bc = wn * 32 + nt * 8 + gid;
            b[buf][nt][0] = Bu[(kb + tig    ) * BSTR + bc];
            b[buf][nt][1] = Bu[(kb + tig + 4) * BSTR + bc];
        }
    };

    for (int kt = 0; kt < KT; kt++) {
        if (kt + 1 < KT) cp_wait<1>(); else cp_wait<0>();
        __syncthreads();
        if (kt + 2 < KT) load_stage((kt + 2) * BK, (kt + 2) % NSTG);

        int st = kt % NSTG;
        Au = (const uint32_t*)(As + st * ASZ);
        Bu = (const uint32_t*)(Bs + st * BSZ);

        ldfrag(0, 0);
        #pragma unroll
        for (int kk = 0; kk < 4; kk++) {
            if (kk < 3) ldfrag(kk + 1, (kk + 1) & 1);
            int cb = kk & 1;
            #pragma unroll
            for (int mt = 0; mt < 4; mt++)
                #pragma unroll
                for (int nt = 0; nt < 4; nt++)
                    mma8(c[mt][nt], a[cb][mt][0], a[cb][mt][1],
                         a[cb][mt][2], a[cb][mt][3],
                         b[cb][nt][0], b[cb][nt][1]);
        }
        __syncthreads();
    }

    #pragma unroll
    for (int mt = 0; mt < 4; mt++) {
        #pragma unroll
        for (int nt = 0; nt < 4; nt++) {
            int col = bn + wn * 32 + nt * 8 + tig * 2;
            float2 bi = make_float2(0.f, 0.f);
            if (BIAS) bi = *(const float2*)&bias[col];
            #pragma unroll
            for (int half = 0; half < 2; half++) {
                int row = bm + wm * 64 + mt * 16 + gid + half * 8;
                float2 v;
                v.x = c[mt][nt][half * 2 + 0] + bi.x;
                v.y = c[mt][nt][half * 2 + 1] + bi.y;
                if (RES) {
                    float2 r = *(const float2*)&Res[(size_t)row * N + col];
                    v.x += r.x; v.y += r.y;
                }
                *(float2*)&C[(size_t)row * N + col] = v;
                if (TOUT) {
                    float2 t; t.x = tanhf(v.x); t.y = tanhf(v.y);
                    *(float2*)&CT[(size_t)row * N + col] = t;
                }
            }
        }
    }
}

// ---------------------------------------------------------------------------
// Tensor-core flash attention with tanh-Hopfield correction.
// Block: 128 threads (4 warps), 64 queries; iterate 64-key tiles.
// All tiles natural [token][d] layout, row pad 68 (conflict-free frags).
// ---------------------------------------------------------------------------
#define AT_STR 68
#define ATT_SMEM (6 * 64 * AT_STR * 4)   // Q,T,P,K,tK,V = 104448 B

__global__ void __launch_bounds__(128) attn_mma_kernel(
    const float* __restrict__ Q,  const float* __restrict__ K,
    const float* __restrict__ TK, const float* __restrict__ V,
    const float* __restrict__ TQJ, float* __restrict__ O,
    const float* __restrict__ lam_p)
{
    extern __shared__ float sm[];
    float* Qs  = sm;
    float* Ts  = Qs + 64 * AT_STR;
    float* Ps  = Ts + 64 * AT_STR;
    float* Ks  = Ps + 64 * AT_STR;
    float* tKs = Ks + 64 * AT_STR;
    float* Vs  = tKs + 64 * AT_STR;
    const uint32_t smem_u = (uint32_t)__cvta_generic_to_shared(sm);
    const uint32_t Qs_u  = smem_u;
    const uint32_t Ts_u  = Qs_u + 64 * AT_STR * 4;
    const uint32_t Ks_u  = Ts_u + 2 * 64 * AT_STR * 4;
    const uint32_t tKs_u = Ks_u + 64 * AT_STR * 4;
    const uint32_t Vs_u  = tKs_u + 64 * AT_STR * 4;

    const int tid = threadIdx.x;
    const int wid = tid >> 5, lane = tid & 31;
    const int gid = lane >> 2, tig = lane & 3;
    const int mrow = wid * 16;
    const int bh = blockIdx.y, b = bh >> 4, h = bh & 15;
    const int q0 = blockIdx.x << 6;
    const float lam = __ldg(lam_p);

    // Stage Q and tQJ tiles (once)
    #pragma unroll
    for (int i = tid; i < 1024; i += 128) {
        int r = i >> 4, c = (i & 15) << 2;
        size_t g = ((size_t)(b * SS + q0 + r)) * DD + h * HD + c;
        cp16(Qs_u + (r * AT_STR + c) * 4, &Q[g]);
        cp16(Ts_u + (r * AT_STR + c) * 4, &TQJ[g]);
    }
    cp_commit();

    float m0 = -1e30f, m1 = -1e30f, l0 = 0.f, l1 = 0.f;
    float o[8][4] = {};

    for (int k0 = 0; k0 < SS; k0 += 64) {
        __syncthreads();           // previous tile fully consumed
        #pragma unroll
        for (int i = tid; i < 1024; i += 128) {
            int r = i >> 4, c = (i & 15) << 2;
            size_t g = ((size_t)(b * SS + k0 + r)) * DD + h * HD + c;
            cp16(Ks_u  + (r * AT_STR + c) * 4, &K[g]);
            cp16(tKs_u + (r * AT_STR + c) * 4, &TK[g]);
            cp16(Vs_u  + (r * AT_STR + c) * 4, &V[g]);
        }
        cp_commit();
        cp_wait<0>();
        __syncthreads();

        // --- S = Q K^T, D = tQJ tanhK^T ---
        float cs[8][4] = {}, cd[8][4] = {};
        const uint32_t* Qu  = (const uint32_t*)Qs;
        const uint32_t* Tu  = (const uint32_t*)Ts;
        const uint32_t* Ku  = (const uint32_t*)Ks;
        const uint32_t* tKu = (const uint32_t*)tKs;
        #pragma unroll
        for (int kg = 0; kg < 8; kg++) {
            int kb = kg << 3;
            uint32_t aq[4], at[4];
            aq[0] = Qu[(mrow + gid    ) * AT_STR + kb + tig];
            aq[1] = Qu[(mrow + gid + 8) * AT_STR + kb + tig];
            aq[2] = Qu[(mrow + gid    ) * AT_STR + kb + tig + 4];
            aq[3] = Qu[(mrow + gid + 8) * AT_STR + kb + tig + 4];
            at[0] = Tu[(mrow + gid    ) * AT_STR + kb + tig];
            at[1] = Tu[(mrow + gid + 8) * AT_STR + kb + tig];
            at[2] = Tu[(mrow + gid    ) * AT_STR + kb + tig + 4];
            at[3] = Tu[(mrow + gid + 8) * AT_STR + kb + tig + 4];
            #pragma unroll
            for (int nt = 0; nt < 8; nt++) {
                int bc = nt * 8 + gid;
                uint32_t b0 = Ku[bc * AT_STR + kb + tig];
                uint32_t b1 = Ku[bc * AT_STR + kb + tig + 4];
                mma8(cs[nt], aq[0], aq[1], aq[2], aq[3], b0, b1);
                uint32_t d0 = tKu[bc * AT_STR + kb + tig];
                uint32_t d1 = tKu[bc * AT_STR + kb + tig + 4];
                mma8(cd[nt], at[0], at[1], at[2], at[3], d0, d1);
            }
        }

        // --- scores + online softmax ---
        float s[8][4];
        float mx0 = -1e30f, mx1 = -1e30f;
        #pragma unroll
        for (int nt = 0; nt < 8; nt++) {
            #pragma unroll
            for (int e = 0; e < 4; e++)
                s[nt][e] = fmaf(lam, cd[nt][e], cs[nt][e] * INV_SCALE);
            mx0 = fmaxf(mx0, fmaxf(s[nt][0], s[nt][1]));
            mx1 = fmaxf(mx1, fmaxf(s[nt][2], s[nt][3]));
        }
        mx0 = fmaxf(mx0, __shfl_xor_sync(0xffffffffu, mx0, 1));
        mx0 = fmaxf(mx0, __shfl_xor_sync(0xffffffffu, mx0, 2));
        mx1 = fmaxf(mx1, __shfl_xor_sync(0xffffffffu, mx1, 1));
        mx1 = fmaxf(mx1, __shfl_xor_sync(0xffffffffu, mx1, 2));
        float mn0 = fmaxf(m0, mx0), mn1 = fmaxf(m1, mx1);
        float corr0 = __expf(m0 - mn0), corr1 = __expf(m1 - mn1);
        m0 = mn0; m1 = mn1;
        l0 *= corr0; l1 *= corr1;

        float sum0 = 0.f, sum1 = 0.f;
        #pragma unroll
        for (int nt = 0; nt < 8; nt++) {
            float p00 = __expf(s[nt][0] - mn0);
            float p01 = __expf(s[nt][1] - mn0);
            float p10 = __expf(s[nt][2] - mn1);
            float p11 = __expf(s[nt][3] - mn1);
            sum0 += p00 + p01; sum1 += p10 + p11;
            int col = nt * 8 + tig * 2;
            *(float2*)&Ps[(mrow + gid    ) * AT_STR + col] = make_float2(p00, p01);
            *(float2*)&Ps[(mrow + gid + 8) * AT_STR + col] = make_float2(p10, p11);
        }
        sum0 += __shfl_xor_sync(0xffffffffu, sum0, 1);
        sum0 += __shfl_xor_sync(0xffffffffu, sum0, 2);
        sum1 += __shfl_xor_sync(0xffffffffu, sum1, 1);
        sum1 += __shfl_xor_sync(0xffffffffu, sum1, 2);
        l0 += sum0; l1 += sum1;

        #pragma unroll
        for (int nt = 0; nt < 8; nt++) {
            o[nt][0] *= corr0; o[nt][1] *= corr0;
            o[nt][2] *= corr1; o[nt][3] *= corr1;
        }
        __syncwarp();

        // --- O += P V ---
        const uint32_t* Pu = (const uint32_t*)Ps;
        const uint32_t* Vu = (const uint32_t*)Vs;
        #pragma unroll
        for (int kg = 0; kg < 8; kg++) {
            int kb = kg << 3;
            uint32_t ap[4];
            ap[0] = Pu[(mrow + gid    ) * AT_STR + kb + tig];
            ap[1] = Pu[(mrow + gid + 8) * AT_STR + kb + tig];
            ap[2] = Pu[(mrow + gid    ) * AT_STR + kb + tig + 4];
            ap[3] = Pu[(mrow + gid + 8) * AT_STR + kb + tig + 4];
            #pragma unroll
            for (int nt = 0; nt < 8; nt++) {
                int bc = nt * 8 + gid;
                uint32_t b0 = Vu[(kb + tig    ) * AT_STR + bc];
                uint32_t b1 = Vu[(kb + tig + 4) * AT_STR + bc];
                mma8(o[nt], ap[0], ap[1], ap[2], ap[3], b0, b1);
            }
        }
    }

    float inv0 = 1.f / l0, inv1 = 1.f / l1;
    int row0 = q0 + mrow + gid, row1 = row0 + 8;
    #pragma unroll
    for (int nt = 0; nt < 8; nt++) {
        int col = nt * 8 + tig * 2;
        *(float2*)&O[((size_t)(b * SS + row0)) * DD + h * HD + col] =
            make_float2(o[nt][0] * inv0, o[nt][1] * inv0);
        *(float2*)&O[((size_t)(b * SS + row1)) * DD + h * HD + col] =
            make_float2(o[nt][2] * inv1, o[nt][3] * inv1);
    }
}

// ---------------------------------------------------------------------------
// LayerNorm: one block per row; optional tanh side-output
// ---------------------------------------------------------------------------
__global__ void __launch_bounds__(256) ln_kernel(
    const float* __restrict__ X, const float* __restrict__ g,
    const float* __restrict__ b, float* __restrict__ Y,
    float* __restrict__ YT, int N)
{
    int row = blockIdx.x;
    const float* x = X + (size_t)row * N;
    float s = 0.f, s2 = 0.f;
    for (int i = threadIdx.x; i < N; i += 256) {
        float v = x[i];
        s += v; s2 = fmaf(v, v, s2);
    }
    __shared__ float sh[64];
    for (int o = 16; o > 0; o >>= 1) {
        s  += __shfl_down_sync(0xffffffffu, s,  o);
        s2 += __shfl_down_sync(0xffffffffu, s2, o);
    }
    int wid = threadIdx.x >> 5, lane = threadIdx.x & 31;
    if (lane == 0) { sh[wid] = s; sh[wid + 32] = s2; }
    __syncthreads();
    if (threadIdx.x == 0) {
        float ts = 0.f, ts2 = 0.f;
        for (int w = 0; w < 8; w++) { ts += sh[w]; ts2 += sh[w + 32]; }
        float mu  = ts / N;
        float var = ts2 / N - mu * mu;
        sh[0] = mu; sh[1] = rsqrtf(var + 1e-5f);
    }
    __syncthreads();
    float mu = sh[0], rstd = sh[1];
    for (int i = threadIdx.x; i < N; i += 256) {
        float v = (x[i] - mu) * rstd * g[i] + b[i];
        Y[(size_t)row * N + i] = v;
        if (YT) YT[(size_t)row * N + i] = tanhf(v);
    }
}

// ---------------------------------------------------------------------------
// QBNN combine + LayerNorm + exact GELU (+ optional residual, tanh output)
// ---------------------------------------------------------------------------
__global__ void __launch_bounds__(256) qln_gelu_kernel(
    const float* __restrict__ HT, const float* __restrict__ DLT,
    const float* __restrict__ g,  const float* __restrict__ b,
    const float* __restrict__ Res, float* __restrict__ Y,
    float* __restrict__ YT, int N)
{
    extern __shared__ float rowbuf[];
    __shared__ float sh[64];
    int row = blockIdx.x;
    size_t base = (size_t)row * N;

    float s = 0.f, s2 = 0.f;
    for (int i = threadIdx.x; i < N; i += 256) {
        float ht = HT[base + i];
        float v  = fmaf(LAM_EFF * DLT[base + i], tanhf(ht), ht);
        rowbuf[i] = v;
        s += v; s2 = fmaf(v, v, s2);
    }
    for (int o = 16; o > 0; o >>= 1) {
        s  += __shfl_down_sync(0xffffffffu, s,  o);
        s2 += __shfl_down_sync(0xffffffffu, s2, o);
    }
    int wid = threadIdx.x >> 5, lane = threadIdx.x & 31;
    if (lane == 0) { sh[wid] = s; sh[wid + 32] = s2; }
    __syncthreads();
    if (threadIdx.x == 0) {
        float ts = 0.f, ts2 = 0.f;
        for (int w = 0; w < 8; w++) { ts += sh[w]; ts2 += sh[w + 32]; }
        float mu  = ts / N;
        float var = ts2 / N - mu * mu;
        sh[0] = mu; sh[1] = rsqrtf(var + 1e-5f);
    }
    __syncthreads();
    float mu = sh[0], rstd = sh[1];
    for (int i = threadIdx.x; i < N; i += 256) {
        float v  = (rowbuf[i] - mu) * rstd * g[i] + b[i];
        float ge = v * normcdff(v);
        float o  = Res ? Res[base + i] + ge : ge;
        Y[base + i] = o;
        if (YT) YT[base + i] = tanhf(o);
    }
}

// ---------------------------------------------------------------------------
// tQJ: per (b,h): tanh(Q[b,:,h]) @ J[h]
// ---------------------------------------------------------------------------
__global__ void __launch_bounds__(256) tqj_kernel(
    const float* __restrict__ Q, const float* __restrict__ J,
    float* __restrict__ Out)
{
    __shared__ __align__(16) float As[64][64];
    __shared__ __align__(16) float Js[64][64];
    int tid = threadIdx.x;
    int bh = blockIdx.x; int b = bh >> 4, h = bh & 15;
    int s0 = blockIdx.y << 6;

    #pragma unroll
    for (int i = 0; i < 4; i++) {
        int idx = tid + (i << 8);
        int r = idx >> 4, kq = (idx & 15) << 2;
        float4 v = *(const float4*)&Q[((size_t)(b * SS + s0 + r)) * DD + h * HD + kq];
        As[kq + 0][r] = tanhf(v.x); As[kq + 1][r] = tanhf(v.y);
        As[kq + 2][r] = tanhf(v.z); As[kq + 3][r] = tanhf(v.w);
        ((float4*)Js)[idx] = *(const float4*)&J[(size_t)h * HD * HD + idx * 4];
    }
    __syncthreads();

    int tx = tid & 15, ty = tid >> 4;
    float c[4][4] = {};
    #pragma unroll 8
    for (int kk = 0; kk < 64; kk++) {
        float a[4], bv[4];
        *(float4*)a  = *(const float4*)&As[kk][ty * 4];
        *(float4*)bv = *(const float4*)&Js[kk][tx * 4];
        #pragma unroll
        for (int i = 0; i < 4; i++)
            #pragma unroll
            for (int j = 0; j < 4; j++)
                c[i][j] = fmaf(a[i], bv[j], c[i][j]);
    }
    #pragma unroll
    for (int i = 0; i < 4; i++) {
        float4 v; v.x = c[i][0]; v.y = c[i][1]; v.z = c[i][2]; v.w = c[i][3];
        *(float4*)&Out[((size_t)(b * SS + s0 + ty * 4 + i)) * DD + h * HD + tx * 4] = v;
    }
}

// ---------------------------------------------------------------------------
// Host driver
// ---------------------------------------------------------------------------
static float* symaddr(const void* s)
{
    void* p = nullptr;
    cudaGetSymbolAddress(&p, s);
    return (float*)p;
}

extern "C" void kernel_launch(void* const* d_in, const int* in_sizes, int n_in,
                              void* d_out, int out_size)
{
    (void)in_sizes; (void)n_in; (void)out_size;

    const float* x    = (const float*)d_in[0];
    const float* wq   = (const float*)d_in[1];
    const float* bq   = (const float*)d_in[2];
    const float* wk   = (const float*)d_in[3];
    const float* bk   = (const float*)d_in[4];
    const float* wv   = (const float*)d_in[5];
    const float* bv   = (const float*)d_in[6];
    const float* wo   = (const float*)d_in[7];
    const float* bo   = (const float*)d_in[8];
    const float* Jat  = (const float*)d_in[9];
    const float* lam  = (const float*)d_in[10];
    const float* gat  = (const float*)d_in[11];
    const float* bat  = (const float*)d_in[12];
    const float* W1   = (const float*)d_in[13];
    const float* b1   = (const float*)d_in[14];
    const float* J1   = (const float*)d_in[15];
    const float* g1   = (const float*)d_in[17];
    const float* be1  = (const float*)d_in[18];
    const float* W2   = (const float*)d_in[19];
    const float* b2   = (const float*)d_in[20];
    const float* J2   = (const float*)d_in[21];
    const float* g2   = (const float*)d_in[23];
    const float* be2  = (const float*)d_in[24];
    const float* gf   = (const float*)d_in[25];
    const float* bf   = (const float*)d_in[26];
    float* out = (float*)d_out;

    float* p_xn   = symaddr(buf_xn);
    float* p_Q    = symaddr(buf_Q);
    float* p_K    = symaddr(buf_K);
    float* p_tK   = symaddr(buf_tK);
    float* p_V    = symaddr(buf_V);
    float* p_tQJ  = symaddr(buf_tQJ);
    float* p_ao   = symaddr(buf_ao);
    float* p_x1   = symaddr(buf_x1);
    float* p_th   = symaddr(buf_th);
    float* p_hhat = symaddr(buf_hhat);
    float* p_dlt  = symaddr(buf_dlt);
    float* p_h1   = symaddr(buf_h1);
    float* p_th1  = symaddr(buf_th1);

    cudaFuncSetAttribute(attn_mma_kernel,
                         cudaFuncAttributeMaxDynamicSharedMemorySize, ATT_SMEM);
    cudaFuncSetAttribute(gemm_tf32_kernel<true, false, false>,
                         cudaFuncAttributeMaxDynamicSharedMemorySize, GEMM_SMEM);
    cudaFuncSetAttribute(gemm_tf32_kernel<true, false, true>,
                         cudaFuncAttributeMaxDynamicSharedMemorySize, GEMM_SMEM);
    cudaFuncSetAttribute(gemm_tf32_kernel<true, true, false>,
                         cudaFuncAttributeMaxDynamicSharedMemorySize, GEMM_SMEM);
    cudaFuncSetAttribute(gemm_tf32_kernel<false, false, false>,
                         cudaFuncAttributeMaxDynamicSharedMemorySize, GEMM_SMEM);

    // --- attention branch -------------------------------------------------
    ln_kernel<<<NT, 256>>>(x, gat, bat, p_xn, nullptr, DD);

    dim3 gProj(DD / BN, NT / BM);
    gemm_tf32_kernel<true, false, false><<<gProj, 256, GEMM_SMEM>>>(
        p_xn, wq, bq, nullptr, p_Q, nullptr, NT, DD, DD);
    gemm_tf32_kernel<true, false, true ><<<gProj, 256, GEMM_SMEM>>>(
        p_xn, wk, bk, nullptr, p_K, p_tK, NT, DD, DD);
    gemm_tf32_kernel<true, false, false><<<gProj, 256, GEMM_SMEM>>>(
        p_xn, wv, bv, nullptr, p_V, nullptr, NT, DD, DD);

    tqj_kernel<<<dim3(BB * HH, SS / 64), 256>>>(p_Q, Jat, p_tQJ);

    attn_mma_kernel<<<dim3(SS / 64, BB * HH), 128, ATT_SMEM>>>(
        p_Q, p_K, p_tK, p_V, p_tQJ, p_ao, lam);

    gemm_tf32_kernel<true, true, false><<<gProj, 256, GEMM_SMEM>>>(
        p_ao, wo, bo, x, p_x1, nullptr, NT, DD, DD);

    // --- QBNN FFN layer 1 -------------------------------------------------
    ln_kernel<<<NT, 256>>>(p_x1, gf, bf, p_xn, p_th, DD);

    dim3 gF1(FFD / BN, NT / BM);
    gemm_tf32_kernel<true,  false, false><<<gF1, 256, GEMM_SMEM>>>(
        p_xn, W1, b1, nullptr, p_hhat, nullptr, NT, FFD, DD);
    gemm_tf32_kernel<false, false, false><<<gF1, 256, GEMM_SMEM>>>(
        p_th, J1, nullptr, nullptr, p_dlt, nullptr, NT, FFD, DD);

    qln_gelu_kernel<<<NT, 256, FFD * sizeof(float)>>>(
        p_hhat, p_dlt, g1, be1, nullptr, p_h1, p_th1, FFD);

    // --- QBNN FFN layer 2 -------------------------------------------------
    dim3 gF2(DD / BN, NT / BM);
    gemm_tf32_kernel<true,  false, false><<<gF2, 256, GEMM_SMEM>>>(
        p_h1, W2, b2, nullptr, p_hhat, nullptr, NT, DD, FFD);
    gemm_tf32_kernel<false, false, false><<<gF2, 256, GEMM_SMEM>>>(
        p_th1, J2, nullptr, nullptr, p_dlt, nullptr, NT, DD, FFD);

    qln_gelu_kernel<<<NT, 256, DD * sizeof(float)>>>(
        p_hhat, p_dlt, g2, be2, p_x1, out, nullptr, DD);
}

// round 7
// speedup vs baseline: 1.0017x; 1.0017x over previous
#include <cuda_runtime.h>
#include <cuda_bf16.h>
#include <math.h>
#include <stdint.h>

#define BB   4
#define SS   1024
#define DD   1024
#define HH   16
#define HD   64
#define FFD  4096
#define NT   (BB*SS)
#define INV_SCALE 0.125f
#define LAM_EFF   0.5f

// ---------------- scratch ----------------
__device__ float buf_xn  [NT*DD];
__device__ float buf_Q   [NT*DD];
__device__ float buf_K   [NT*DD];
__device__ float buf_tK  [NT*DD];
__device__ float buf_V   [NT*DD];
__device__ float buf_tQJ [NT*DD];
__device__ float buf_ao  [NT*DD];
__device__ float buf_x1  [NT*DD];
__device__ float buf_th  [NT*DD];
__device__ float buf_hhat[NT*FFD];
__device__ float buf_dlt [NT*FFD];
__device__ float buf_h1  [NT*FFD];
__device__ float buf_th1 [NT*FFD];
__device__ float buf_wqT [DD*DD];
__device__ float buf_wkT [DD*DD];
__device__ float buf_wvT [DD*DD];
__device__ float buf_woT [DD*DD];
__device__ float buf_W1T [FFD*DD];
__device__ float buf_J1T [FFD*DD];
__device__ float buf_W2T [DD*FFD];
__device__ float buf_J2T [DD*FFD];

// ---------------- helpers ----------------
__device__ __forceinline__ void cp16(uint32_t d, const void* g)
{ asm volatile("cp.async.cg.shared.global [%0], [%1], 16;\n" :: "r"(d), "l"(g)); }
__device__ __forceinline__ void cp_commit()
{ asm volatile("cp.async.commit_group;\n"); }
template<int N> __device__ __forceinline__ void cp_wait()
{ asm volatile("cp.async.wait_group %0;\n" :: "n"(N)); }

__device__ __forceinline__ void mma8(float* c,
    uint32_t a0, uint32_t a1, uint32_t a2, uint32_t a3, uint32_t b0, uint32_t b1)
{
    asm volatile(
        "mma.sync.aligned.m16n8k8.row.col.f32.tf32.tf32.f32 "
        "{%0,%1,%2,%3},{%4,%5,%6,%7},{%8,%9},{%0,%1,%2,%3};"
        : "+f"(c[0]), "+f"(c[1]), "+f"(c[2]), "+f"(c[3])
        : "r"(a0), "r"(a1), "r"(a2), "r"(a3), "r"(b0), "r"(b1));
}
__device__ __forceinline__ void ldsm4(uint32_t* r, uint32_t addr)
{
    asm volatile("ldmatrix.sync.aligned.m8n8.x4.shared.b16 {%0,%1,%2,%3}, [%4];"
                 : "=r"(r[0]), "=r"(r[1]), "=r"(r[2]), "=r"(r[3]) : "r"(addr));
}

// ---------------------------------------------------------------------------
// TF32 GEMM v4: C[M,N] = A[M,K] @ BT[N,K]^T (+bias)(+Res), opt tanh out.
// Both operands staged K-major [128 rows][32 k] pad 36. ldmatrix fragments.
// 128x128x32 block, 3-stage cp.async, 8 warps (2M x 4N), warp tile 64x32.
// ---------------------------------------------------------------------------
#define ASTR 36
#define TSZ  (128*ASTR)
#define NSTG 3
#define GEMM_SMEM (NSTG * 2 * TSZ * 4)    // 110592 B

template<bool BIAS, bool RES, bool TOUT>
__global__ void __launch_bounds__(256) gemm_tf32_kernel(
    const float* __restrict__ A, const float* __restrict__ BT,
    const float* __restrict__ bias, const float* __restrict__ Res,
    float* __restrict__ C, float* __restrict__ CT,
    int M, int N, int K)
{
    extern __shared__ float smem[];
    const uint32_t smem_u = (uint32_t)__cvta_generic_to_shared(smem);

    const int tid = threadIdx.x;
    const int bn = blockIdx.x << 7, bm = blockIdx.y << 7;
    const int wid = tid >> 5, lane = tid & 31;
    const int wm = wid & 1, wn = wid >> 1;
    const int gid = lane >> 2, tig = lane & 3;

    float c[4][4][4] = {};

    auto load_stage = [&](int k0, int st) {
        uint32_t ab = smem_u + st * 2 * TSZ * 4;
        uint32_t bb = ab + TSZ * 4;
        #pragma unroll
        for (int i = 0; i < 4; i++) {
            int idx = tid + (i << 8);
            int r = idx >> 3, cq = (idx & 7) << 2;
            cp16(ab + (r * ASTR + cq) * 4, &A [(size_t)(bm + r) * K + k0 + cq]);
            cp16(bb + (r * ASTR + cq) * 4, &BT[(size_t)(bn + r) * K + k0 + cq]);
        }
        cp_commit();
    };

    const int KT = K >> 5;
    load_stage(0, 0);
    load_stage(32, 1);

    // per-thread ldmatrix row addresses
    const int j8 = lane >> 3, r8 = lane & 7;
    const uint32_t aoff = ((wm * 64 + (j8 & 1) * 8 + r8) * ASTR + (j8 >> 1) * 4) * 4;
    const uint32_t boff = TSZ * 4 +
        ((wn * 32 + (j8 >> 1) * 8 + r8) * ASTR + (j8 & 1) * 4) * 4;

    for (int kt = 0; kt < KT; kt++) {
        if (kt + 1 < KT) cp_wait<1>(); else cp_wait<0>();
        __syncthreads();
        if (kt + 2 < KT) load_stage((kt + 2) << 5, (kt + 2) % NSTG);

        uint32_t sb = smem_u + (kt % NSTG) * 2 * TSZ * 4;
        #pragma unroll
        for (int kk = 0; kk < 4; kk++) {
            uint32_t a[4][4], b2[2][4];
            #pragma unroll
            for (int mt = 0; mt < 4; mt++)
                ldsm4(a[mt], sb + aoff + mt * (16 * ASTR * 4) + kk * 32);
            #pragma unroll
            for (int p = 0; p < 2; p++)
                ldsm4(b2[p], sb + boff + p * (16 * ASTR * 4) + kk * 32);
            #pragma unroll
            for (int mt = 0; mt < 4; mt++)
                #pragma unroll
                for (int nt = 0; nt < 4; nt++)
                    mma8(c[mt][nt], a[mt][0], a[mt][1], a[mt][2], a[mt][3],
                         b2[nt >> 1][(nt & 1) * 2], b2[nt >> 1][(nt & 1) * 2 + 1]);
        }
        __syncthreads();
    }

    #pragma unroll
    for (int mt = 0; mt < 4; mt++) {
        #pragma unroll
        for (int nt = 0; nt < 4; nt++) {
            int col = bn + wn * 32 + nt * 8 + tig * 2;
            float2 bi = make_float2(0.f, 0.f);
            if (BIAS) bi = *(const float2*)&bias[col];
            #pragma unroll
            for (int half = 0; half < 2; half++) {
                int row = bm + wm * 64 + mt * 16 + gid + half * 8;
                float2 v;
                v.x = c[mt][nt][half * 2 + 0] + bi.x;
                v.y = c[mt][nt][half * 2 + 1] + bi.y;
                if (RES) {
                    float2 r = *(const float2*)&Res[(size_t)row * N + col];
                    v.x += r.x; v.y += r.y;
                }
                *(float2*)&C[(size_t)row * N + col] = v;
                if (TOUT) {
                    float2 t; t.x = tanhf(v.x); t.y = tanhf(v.y);
                    *(float2*)&CT[(size_t)row * N + col] = t;
                }
            }
        }
    }
}

// ---------------- transpose: out[C][R] = in[R][C] ----------------
__global__ void __launch_bounds__(256) transpose_kernel(
    const float* __restrict__ in, float* __restrict__ out, int R, int C)
{
    __shared__ float t[32][33];
    int bx = blockIdx.x << 5, by = blockIdx.y << 5;
    int x = threadIdx.x, y = threadIdx.y;
    #pragma unroll
    for (int i = 0; i < 32; i += 8)
        t[y + i][x] = in[(size_t)(by + y + i) * C + bx + x];
    __syncthreads();
    #pragma unroll
    for (int i = 0; i < 32; i += 8)
        out[(size_t)(bx + y + i) * R + by + x] = t[x][y + i];
}

// ---------------- tensor-core flash attention (round-4, proven) ----------------
#define AT_STR 68
#define ATT_SMEM (6 * 64 * AT_STR * 4)

__global__ void __launch_bounds__(128) attn_mma_kernel(
    const float* __restrict__ Q,  const float* __restrict__ K,
    const float* __restrict__ TK, const float* __restrict__ V,
    const float* __restrict__ TQJ, float* __restrict__ O,
    const float* __restrict__ lam_p)
{
    extern __shared__ float sm[];
    float* Qs  = sm;
    float* Ts  = Qs + 64 * AT_STR;
    float* Ps  = Ts + 64 * AT_STR;
    float* Ks  = Ps + 64 * AT_STR;
    float* tKs = Ks + 64 * AT_STR;
    float* Vs  = tKs + 64 * AT_STR;
    const uint32_t smem_u = (uint32_t)__cvta_generic_to_shared(sm);
    const uint32_t Qs_u  = smem_u;
    const uint32_t Ts_u  = Qs_u + 64 * AT_STR * 4;
    const uint32_t Ks_u  = Ts_u + 2 * 64 * AT_STR * 4;
    const uint32_t tKs_u = Ks_u + 64 * AT_STR * 4;
    const uint32_t Vs_u  = tKs_u + 64 * AT_STR * 4;

    const int tid = threadIdx.x;
    const int wid = tid >> 5, lane = tid & 31;
    const int gid = lane >> 2, tig = lane & 3;
    const int mrow = wid * 16;
    const int bh = blockIdx.y, b = bh >> 4, h = bh & 15;
    const int q0 = blockIdx.x << 6;
    const float lam = __ldg(lam_p);

    #pragma unroll
    for (int i = tid; i < 1024; i += 128) {
        int r = i >> 4, c = (i & 15) << 2;
        size_t g = ((size_t)(b * SS + q0 + r)) * DD + h * HD + c;
        cp16(Qs_u + (r * AT_STR + c) * 4, &Q[g]);
        cp16(Ts_u + (r * AT_STR + c) * 4, &TQJ[g]);
    }
    cp_commit();

    float m0 = -1e30f, m1 = -1e30f, l0 = 0.f, l1 = 0.f;
    float o[8][4] = {};

    for (int k0 = 0; k0 < SS; k0 += 64) {
        __syncthreads();
        #pragma unroll
        for (int i = tid; i < 1024; i += 128) {
            int r = i >> 4, c = (i & 15) << 2;
            size_t g = ((size_t)(b * SS + k0 + r)) * DD + h * HD + c;
            cp16(Ks_u  + (r * AT_STR + c) * 4, &K[g]);
            cp16(tKs_u + (r * AT_STR + c) * 4, &TK[g]);
            cp16(Vs_u  + (r * AT_STR + c) * 4, &V[g]);
        }
        cp_commit();
        cp_wait<0>();
        __syncthreads();

        float cs[8][4] = {}, cd[8][4] = {};
        const uint32_t* Qu  = (const uint32_t*)Qs;
        const uint32_t* Tu  = (const uint32_t*)Ts;
        const uint32_t* Ku  = (const uint32_t*)Ks;
        const uint32_t* tKu = (const uint32_t*)tKs;
        #pragma unroll
        for (int kg = 0; kg < 8; kg++) {
            int kb = kg << 3;
            uint32_t aq[4], at[4];
            aq[0] = Qu[(mrow + gid    ) * AT_STR + kb + tig];
            aq[1] = Qu[(mrow + gid + 8) * AT_STR + kb + tig];
            aq[2] = Qu[(mrow + gid    ) * AT_STR + kb + tig + 4];
            aq[3] = Qu[(mrow + gid + 8) * AT_STR + kb + tig + 4];
            at[0] = Tu[(mrow + gid    ) * AT_STR + kb + tig];
            at[1] = Tu[(mrow + gid + 8) * AT_STR + kb + tig];
            at[2] = Tu[(mrow + gid    ) * AT_STR + kb + tig + 4];
            at[3] = Tu[(mrow + gid + 8) * AT_STR + kb + tig + 4];
            #pragma unroll
            for (int nt = 0; nt < 8; nt++) {
                int bc = nt * 8 + gid;
                uint32_t b0 = Ku[bc * AT_STR + kb + tig];
                uint32_t b1 = Ku[bc * AT_STR + kb + tig + 4];
                mma8(cs[nt], aq[0], aq[1], aq[2], aq[3], b0, b1);
                uint32_t d0 = tKu[bc * AT_STR + kb + tig];
                uint32_t d1 = tKu[bc * AT_STR + kb + tig + 4];
                mma8(cd[nt], at[0], at[1], at[2], at[3], d0, d1);
            }
        }

        float s[8][4];
        float mx0 = -1e30f, mx1 = -1e30f;
        #pragma unroll
        for (int nt = 0; nt < 8; nt++) {
            #pragma unroll
            for (int e = 0; e < 4; e++)
                s[nt][e] = fmaf(lam, cd[nt][e], cs[nt][e] * INV_SCALE);
            mx0 = fmaxf(mx0, fmaxf(s[nt][0], s[nt][1]));
            mx1 = fmaxf(mx1, fmaxf(s[nt][2], s[nt][3]));
        }
        mx0 = fmaxf(mx0, __shfl_xor_sync(0xffffffffu, mx0, 1));
        mx0 = fmaxf(mx0, __shfl_xor_sync(0xffffffffu, mx0, 2));
        mx1 = fmaxf(mx1, __shfl_xor_sync(0xffffffffu, mx1, 1));
        mx1 = fmaxf(mx1, __shfl_xor_sync(0xffffffffu, mx1, 2));
        float mn0 = fmaxf(m0, mx0), mn1 = fmaxf(m1, mx1);
        float corr0 = __expf(m0 - mn0), corr1 = __expf(m1 - mn1);
        m0 = mn0; m1 = mn1;
        l0 *= corr0; l1 *= corr1;

        float sum0 = 0.f, sum1 = 0.f;
        #pragma unroll
        for (int nt = 0; nt < 8; nt++) {
            float p00 = __expf(s[nt][0] - mn0);
            float p01 = __expf(s[nt][1] - mn0);
            float p10 = __expf(s[nt][2] - mn1);
            float p11 = __expf(s[nt][3] - mn1);
            sum0 += p00 + p01; sum1 += p10 + p11;
            int col = nt * 8 + tig * 2;
            *(float2*)&Ps[(mrow + gid    ) * AT_STR + col] = make_float2(p00, p01);
            *(float2*)&Ps[(mrow + gid + 8) * AT_STR + col] = make_float2(p10, p11);
        }
        sum0 += __shfl_xor_sync(0xffffffffu, sum0, 1);
        sum0 += __shfl_xor_sync(0xffffffffu, sum0, 2);
        sum1 += __shfl_xor_sync(0xffffffffu, sum1, 1);
        sum1 += __shfl_xor_sync(0xffffffffu, sum1, 2);
        l0 += sum0; l1 += sum1;

        #pragma unroll
        for (int nt = 0; nt < 8; nt++) {
            o[nt][0] *= corr0; o[nt][1] *= corr0;
            o[nt][2] *= corr1; o[nt][3] *= corr1;
        }
        __syncwarp();

        const uint32_t* Pu = (const uint32_t*)Ps;
        const uint32_t* Vu = (const uint32_t*)Vs;
        #pragma unroll
        for (int kg = 0; kg < 8; kg++) {
            int kb = kg << 3;
            uint32_t ap[4];
            ap[0] = Pu[(mrow + gid    ) * AT_STR + kb + tig];
            ap[1] = Pu[(mrow + gid + 8) * AT_STR + kb + tig];
            ap[2] = Pu[(mrow + gid    ) * AT_STR + kb + tig + 4];
            ap[3] = Pu[(mrow + gid + 8) * AT_STR + kb + tig + 4];
            #pragma unroll
            for (int nt = 0; nt < 8; nt++) {
                int bc = nt * 8 + gid;
                uint32_t b0 = Vu[(kb + tig    ) * AT_STR + bc];
                uint32_t b1 = Vu[(kb + tig + 4) * AT_STR + bc];
                mma8(o[nt], ap[0], ap[1], ap[2], ap[3], b0, b1);
            }
        }
    }

    float inv0 = 1.f / l0, inv1 = 1.f / l1;
    int row0 = q0 + mrow + gid, row1 = row0 + 8;
    #pragma unroll
    for (int nt = 0; nt < 8; nt++) {
        int col = nt * 8 + tig * 2;
        *(float2*)&O[((size_t)(b * SS + row0)) * DD + h * HD + col] =
            make_float2(o[nt][0] * inv0, o[nt][1] * inv0);
        *(float2*)&O[((size_t)(b * SS + row1)) * DD + h * HD + col] =
            make_float2(o[nt][2] * inv1, o[nt][3] * inv1);
    }
}

// ---------------- LayerNorm (+opt tanh out) ----------------
__global__ void __launch_bounds__(256) ln_kernel(
    const float* __restrict__ X, const float* __restrict__ g,
    const float* __restrict__ b, float* __restrict__ Y,
    float* __restrict__ YT, int N)
{
    int row = blockIdx.x;
    const float* x = X + (size_t)row * N;
    float s = 0.f, s2 = 0.f;
    for (int i = threadIdx.x; i < N; i += 256) {
        float v = x[i];
        s += v; s2 = fmaf(v, v, s2);
    }
    __shared__ float sh[64];
    for (int o = 16; o > 0; o >>= 1) {
        s  += __shfl_down_sync(0xffffffffu, s,  o);
        s2 += __shfl_down_sync(0xffffffffu, s2, o);
    }
    int wid = threadIdx.x >> 5, lane = threadIdx.x & 31;
    if (lane == 0) { sh[wid] = s; sh[wid + 32] = s2; }
    __syncthreads();
    if (threadIdx.x == 0) {
        float ts = 0.f, ts2 = 0.f;
        for (int w = 0; w < 8; w++) { ts += sh[w]; ts2 += sh[w + 32]; }
        float mu = ts / N, var = ts2 / N - mu * mu;
        sh[0] = mu; sh[1] = rsqrtf(var + 1e-5f);
    }
    __syncthreads();
    float mu = sh[0], rstd = sh[1];
    for (int i = threadIdx.x; i < N; i += 256) {
        float v = (x[i] - mu) * rstd * g[i] + b[i];
        Y[(size_t)row * N + i] = v;
        if (YT) YT[(size_t)row * N + i] = tanhf(v);
    }
}

// ---------------- QBNN combine + LN + GELU ----------------
__global__ void __launch_bounds__(256) qln_gelu_kernel(
    const float* __restrict__ HT, const float* __restrict__ DLT,
    const float* __restrict__ g,  const float* __restrict__ b,
    const float* __restrict__ Res, float* __restrict__ Y,
    float* __restrict__ YT, int N)
{
    extern __shared__ float rowbuf[];
    __shared__ float sh[64];
    int row = blockIdx.x;
    size_t base = (size_t)row * N;

    float s = 0.f, s2 = 0.f;
    for (int i = threadIdx.x; i < N; i += 256) {
        float ht = HT[base + i];
        float v  = fmaf(LAM_EFF * DLT[base + i], tanhf(ht), ht);
        rowbuf[i] = v;
        s += v; s2 = fmaf(v, v, s2);
    }
    for (int o = 16; o > 0; o >>= 1) {
        s  += __shfl_down_sync(0xffffffffu, s,  o);
        s2 += __shfl_down_sync(0xffffffffu, s2, o);
    }
    int wid = threadIdx.x >> 5, lane = threadIdx.x & 31;
    if (lane == 0) { sh[wid] = s; sh[wid + 32] = s2; }
    __syncthreads();
    if (threadIdx.x == 0) {
        float ts = 0.f, ts2 = 0.f;
        for (int w = 0; w < 8; w++) { ts += sh[w]; ts2 += sh[w + 32]; }
        float mu = ts / N, var = ts2 / N - mu * mu;
        sh[0] = mu; sh[1] = rsqrtf(var + 1e-5f);
    }
    __syncthreads();
    float mu = sh[0], rstd = sh[1];
    for (int i = threadIdx.x; i < N; i += 256) {
        float v  = (rowbuf[i] - mu) * rstd * g[i] + b[i];
        float ge = v * normcdff(v);
        float o  = Res ? Res[base + i] + ge : ge;
        Y[base + i] = o;
        if (YT) YT[base + i] = tanhf(o);
    }
}

// ---------------- tQJ ----------------
__global__ void __launch_bounds__(256) tqj_kernel(
    const float* __restrict__ Q, const float* __restrict__ J,
    float* __restrict__ Out)
{
    __shared__ __align__(16) float As[64][64];
    __shared__ __align__(16) float Js[64][64];
    int tid = threadIdx.x;
    int bh = blockIdx.x; int b = bh >> 4, h = bh & 15;
    int s0 = blockIdx.y << 6;

    #pragma unroll
    for (int i = 0; i < 4; i++) {
        int idx = tid + (i << 8);
        int r = idx >> 4, kq = (idx & 15) << 2;
        float4 v = *(const float4*)&Q[((size_t)(b * SS + s0 + r)) * DD + h * HD + kq];
        As[kq + 0][r] = tanhf(v.x); As[kq + 1][r] = tanhf(v.y);
        As[kq + 2][r] = tanhf(v.z); As[kq + 3][r] = tanhf(v.w);
        ((float4*)Js)[idx] = *(const float4*)&J[(size_t)h * HD * HD + idx * 4];
    }
    __syncthreads();

    int tx = tid & 15, ty = tid >> 4;
    float c[4][4] = {};
    #pragma unroll 8
    for (int kk = 0; kk < 64; kk++) {
        float a[4], bv[4];
        *(float4*)a  = *(const float4*)&As[kk][ty * 4];
        *(float4*)bv = *(const float4*)&Js[kk][tx * 4];
        #pragma unroll
        for (int i = 0; i < 4; i++)
            #pragma unroll
            for (int j = 0; j < 4; j++)
                c[i][j] = fmaf(a[i], bv[j], c[i][j]);
    }
    #pragma unroll
    for (int i = 0; i < 4; i++) {
        float4 v; v.x = c[i][0]; v.y = c[i][1]; v.z = c[i][2]; v.w = c[i][3];
        *(float4*)&Out[((size_t)(b * SS + s0 + ty * 4 + i)) * DD + h * HD + tx * 4] = v;
    }
}

// ---------------- host ----------------
static float* symaddr(const void* s)
{
    void* p = nullptr;
    cudaGetSymbolAddress(&p, s);
    return (float*)p;
}

extern "C" void kernel_launch(void* const* d_in, const int* in_sizes, int n_in,
                              void* d_out, int out_size)
{
    (void)in_sizes; (void)n_in; (void)out_size;

    const float* x   = (const float*)d_in[0];
    const float* wq  = (const float*)d_in[1];
    const float* bq  = (const float*)d_in[2];
    const float* wk  = (const float*)d_in[3];
    const float* bk  = (const float*)d_in[4];
    const float* wv  = (const float*)d_in[5];
    const float* bv  = (const float*)d_in[6];
    const float* wo  = (const float*)d_in[7];
    const float* bo  = (const float*)d_in[8];
    const float* Jat = (const float*)d_in[9];
    const float* lam = (const float*)d_in[10];
    const float* gat = (const float*)d_in[11];
    const float* bat = (const float*)d_in[12];
    const float* W1  = (const float*)d_in[13];
    const float* b1  = (const float*)d_in[14];
    const float* J1  = (const float*)d_in[15];
    const float* g1  = (const float*)d_in[17];
    const float* be1 = (const float*)d_in[18];
    const float* W2  = (const float*)d_in[19];
    const float* b2  = (const float*)d_in[20];
    const float* J2  = (const float*)d_in[21];
    const float* g2  = (const float*)d_in[23];
    const float* be2 = (const float*)d_in[24];
    const float* gf  = (const float*)d_in[25];
    const float* bf  = (const float*)d_in[26];
    float* out = (float*)d_out;

    float* p_xn   = symaddr(buf_xn);
    float* p_Q    = symaddr(buf_Q);
    float* p_K    = symaddr(buf_K);
    float* p_tK   = symaddr(buf_tK);
    float* p_V    = symaddr(buf_V);
    float* p_tQJ  = symaddr(buf_tQJ);
    float* p_ao   = symaddr(buf_ao);
    float* p_x1   = symaddr(buf_x1);
    float* p_th   = symaddr(buf_th);
    float* p_hhat = symaddr(buf_hhat);
    float* p_dlt  = symaddr(buf_dlt);
    float* p_h1   = symaddr(buf_h1);
    float* p_th1  = symaddr(buf_th1);
    float* p_wqT  = symaddr(buf_wqT);
    float* p_wkT  = symaddr(buf_wkT);
    float* p_wvT  = symaddr(buf_wvT);
    float* p_woT  = symaddr(buf_woT);
    float* p_W1T  = symaddr(buf_W1T);
    float* p_J1T  = symaddr(buf_J1T);
    float* p_W2T  = symaddr(buf_W2T);
    float* p_J2T  = symaddr(buf_J2T);

    cudaFuncSetAttribute(attn_mma_kernel,
                         cudaFuncAttributeMaxDynamicSharedMemorySize, ATT_SMEM);
    cudaFuncSetAttribute(gemm_tf32_kernel<true, false, false>,
                         cudaFuncAttributeMaxDynamicSharedMemorySize, GEMM_SMEM);
    cudaFuncSetAttribute(gemm_tf32_kernel<true, false, true>,
                         cudaFuncAttributeMaxDynamicSharedMemorySize, GEMM_SMEM);
    cudaFuncSetAttribute(gemm_tf32_kernel<true, true, false>,
                         cudaFuncAttributeMaxDynamicSharedMemorySize, GEMM_SMEM);
    cudaFuncSetAttribute(gemm_tf32_kernel<false, false, false>,
                         cudaFuncAttributeMaxDynamicSharedMemorySize, GEMM_SMEM);

    // weight transposes: [K][N] -> [N][K]
    dim3 tb(32, 8);
    transpose_kernel<<<dim3(DD/32,  DD/32 ), tb>>>(wq, p_wqT, DD,  DD);
    transpose_kernel<<<dim3(DD/32,  DD/32 ), tb>>>(wk, p_wkT, DD,  DD);
    transpose_kernel<<<dim3(DD/32,  DD/32 ), tb>>>(wv, p_wvT, DD,  DD);
    transpose_kernel<<<dim3(DD/32,  DD/32 ), tb>>>(wo, p_woT, DD,  DD);
    transpose_kernel<<<dim3(FFD/32, DD/32 ), tb>>>(W1, p_W1T, DD,  FFD);
    transpose_kernel<<<dim3(FFD/32, DD/32 ), tb>>>(J1, p_J1T, DD,  FFD);
    transpose_kernel<<<dim3(DD/32,  FFD/32), tb>>>(W2, p_W2T, FFD, DD);
    transpose_kernel<<<dim3(DD/32,  FFD/32), tb>>>(J2, p_J2T, FFD, DD);

    // --- attention branch ---
    ln_kernel<<<NT, 256>>>(x, gat, bat, p_xn, nullptr, DD);

    dim3 gP(DD / 128, NT / 128);
    gemm_tf32_kernel<true, false, false><<<gP, 256, GEMM_SMEM>>>(
        p_xn, p_wqT, bq, nullptr, p_Q, nullptr, NT, DD, DD);
    gemm_tf32_kernel<true, false, true ><<<gP, 256, GEMM_SMEM>>>(
        p_xn, p_wkT, bk, nullptr, p_K, p_tK, NT, DD, DD);
    gemm_tf32_kernel<true, false, false><<<gP, 256, GEMM_SMEM>>>(
        p_xn, p_wvT, bv, nullptr, p_V, nullptr, NT, DD, DD);

    tqj_kernel<<<dim3(BB * HH, SS / 64), 256>>>(p_Q, Jat, p_tQJ);

    attn_mma_kernel<<<dim3(SS / 64, BB * HH), 128, ATT_SMEM>>>(
        p_Q, p_K, p_tK, p_V, p_tQJ, p_ao, lam);

    gemm_tf32_kernel<true, true, false><<<gP, 256, GEMM_SMEM>>>(
        p_ao, p_woT, bo, x, p_x1, nullptr, NT, DD, DD);

    // --- QBNN FFN layer 1 ---
    ln_kernel<<<NT, 256>>>(p_x1, gf, bf, p_xn, p_th, DD);

    dim3 gF1(FFD / 128, NT / 128);
    gemm_tf32_kernel<true,  false, false><<<gF1, 256, GEMM_SMEM>>>(
        p_xn, p_W1T, b1, nullptr, p_hhat, nullptr, NT, FFD, DD);
    gemm_tf32_kernel<false, false, false><<<gF1, 256, GEMM_SMEM>>>(
        p_th, p_J1T, nullptr, nullptr, p_dlt, nullptr, NT, FFD, DD);

    qln_gelu_kernel<<<NT, 256, FFD * sizeof(float)>>>(
        p_hhat, p_dlt, g1, be1, nullptr, p_h1, p_th1, FFD);

    // --- QBNN FFN layer 2 ---
    dim3 gF2(DD / 128, NT / 128);
    gemm_tf32_kernel<true,  false, false><<<gF2, 256, GEMM_SMEM>>>(
        p_h1, p_W2T, b2, nullptr, p_hhat, nullptr, NT, DD, FFD);
    gemm_tf32_kernel<false, false, false><<<gF2, 256, GEMM_SMEM>>>(
        p_th1, p_J2T, nullptr, nullptr, p_dlt, nullptr, NT, DD, FFD);

    qln_gelu_kernel<<<NT, 256, DD * sizeof(float)>>>(
        p_hhat, p_dlt, g2, be2, p_x1, out, nullptr, DD);
}

// round 9
// speedup vs baseline: 1.6777x; 1.6750x over previous
#include <cuda_runtime.h>
#include <cuda_fp16.h>
#include <math.h>
#include <stdint.h>

#define BB   4
#define SS   1024
#define DD   1024
#define HH   16
#define HD   64
#define FFD  4096
#define NT   (BB*SS)
#define INV_SCALE 0.125f
#define LAM_EFF   0.5f

// ---------------- scratch ----------------
__device__ __half h_xn  [NT*DD];
__device__ __half h_Q   [NT*DD];
__device__ __half h_K   [NT*DD];
__device__ __half h_tK  [NT*DD];
__device__ __half h_V   [NT*DD];
__device__ __half h_tQJ [NT*DD];
__device__ __half h_ao  [NT*DD];
__device__ float  f_x1  [NT*DD];
__device__ __half h_th  [NT*DD];
__device__ float  f_hhat[NT*FFD];
__device__ float  f_dlt [NT*FFD];
__device__ __half h_h1  [NT*FFD];
__device__ __half h_th1 [NT*FFD];
__device__ __half h_wqT [DD*DD];
__device__ __half h_wkT [DD*DD];
__device__ __half h_wvT [DD*DD];
__device__ __half h_woT [DD*DD];
__device__ __half h_W1T [FFD*DD];
__device__ __half h_J1T [FFD*DD];
__device__ __half h_W2T [DD*FFD];
__device__ __half h_J2T [DD*FFD];

// ---------------- helpers ----------------
__device__ __forceinline__ void cp16(uint32_t d, const void* g)
{ asm volatile("cp.async.cg.shared.global [%0], [%1], 16;\n" :: "r"(d), "l"(g)); }
__device__ __forceinline__ void cp_commit()
{ asm volatile("cp.async.commit_group;\n"); }
template<int N> __device__ __forceinline__ void cp_wait()
{ asm volatile("cp.async.wait_group %0;\n" :: "n"(N)); }

__device__ __forceinline__ void mma16(float* c, const uint32_t* a,
                                      uint32_t b0, uint32_t b1)
{
    asm volatile(
        "mma.sync.aligned.m16n8k16.row.col.f32.f16.f16.f32 "
        "{%0,%1,%2,%3},{%4,%5,%6,%7},{%8,%9},{%0,%1,%2,%3};"
        : "+f"(c[0]), "+f"(c[1]), "+f"(c[2]), "+f"(c[3])
        : "r"(a[0]), "r"(a[1]), "r"(a[2]), "r"(a[3]), "r"(b0), "r"(b1));
}
__device__ __forceinline__ void ldsm4(uint32_t* r, uint32_t addr)
{
    asm volatile("ldmatrix.sync.aligned.m8n8.x4.shared.b16 {%0,%1,%2,%3}, [%4];"
                 : "=r"(r[0]), "=r"(r[1]), "=r"(r[2]), "=r"(r[3]) : "r"(addr));
}
__device__ __forceinline__ void ldsm4t(uint32_t* r, uint32_t addr)
{
    asm volatile("ldmatrix.sync.aligned.m8n8.x4.trans.shared.b16 {%0,%1,%2,%3}, [%4];"
                 : "=r"(r[0]), "=r"(r[1]), "=r"(r[2]), "=r"(r[3]) : "r"(addr));
}

// ---------------------------------------------------------------------------
// FP16 GEMM: C[M,N] = A[M,K] @ BT[N,K]^T (+bias)(+Res); fp32 or fp16 out,
// optional fp16 tanh side-output. 128x128x32 block, 4-stage cp.async,
// 8 warps (2M x 4N), warp tile 64x32, m16n8k16 + ldmatrix.
// Rows padded to 40 halves (80B): 8 ldmatrix rows cover all 32 banks.
// ---------------------------------------------------------------------------
#define RSH   40
#define TILEB (128*RSH*2)          // 10240 B per operand tile
#define STG_B (2*TILEB)            // 20480 B per stage
#define NSTG  4
#define GEMM_SMEM (NSTG*STG_B)     // 81920 B

template<bool BIAS, bool RES, bool TOUT, bool HOUT>
__global__ void __launch_bounds__(256, 2) gemm_f16_kernel(
    const __half* __restrict__ A, const __half* __restrict__ BT,
    const float* __restrict__ bias, const float* __restrict__ Res,
    float* __restrict__ C, __half* __restrict__ C16, __half* __restrict__ CT,
    int M, int N, int K)
{
    extern __shared__ __half smh[];
    const uint32_t su = (uint32_t)__cvta_generic_to_shared(smh);

    const int tid = threadIdx.x;
    const int bn = blockIdx.x << 7, bm = blockIdx.y << 7;
    const int wid = tid >> 5, lane = tid & 31;
    const int wm = wid & 1, wn = wid >> 1;
    const int gid = lane >> 2, tig = lane & 3;

    float c[4][4][4] = {};

    auto load_stage = [&](int kt) {
        int s = kt & 3;
        uint32_t ab = su + s * STG_B, bb = ab + TILEB;
        #pragma unroll
        for (int i = 0; i < 2; i++) {
            int idx = tid + (i << 8);
            int r = idx >> 2, c8 = idx & 3;
            cp16(ab + (r * RSH + c8 * 8) * 2,
                 &A[(size_t)(bm + r) * K + kt * 32 + c8 * 8]);
        }
        #pragma unroll
        for (int i = 0; i < 2; i++) {
            int idx = tid + (i << 8);
            int r = idx >> 2, c8 = idx & 3;
            cp16(bb + (r * RSH + c8 * 8) * 2,
                 &BT[(size_t)(bn + r) * K + kt * 32 + c8 * 8]);
        }
        cp_commit();
    };

    const int KT = K >> 5;
    load_stage(0); load_stage(1); load_stage(2);

    const int t7 = lane & 7;
    const uint32_t aro = ((lane >> 3) & 1) * 8 + t7;   // A row-in-tile
    const uint32_t ak8 = ((lane >> 4) & 1) * 8;        // A k offset
    const uint32_t bro = ((lane >> 4) & 1) * 8 + t7;   // B row-in-tile
    const uint32_t bk8 = ((lane >> 3) & 1) * 8;        // B k offset

    for (int kt = 0; kt < KT; kt++) {
        cp_wait<2>();
        __syncthreads();
        if (kt + 3 < KT) load_stage(kt + 3); else cp_commit();

        uint32_t ab = su + (kt & 3) * STG_B, bb = ab + TILEB;
        #pragma unroll
        for (int ks = 0; ks < 2; ks++) {
            uint32_t a[4][4], b[2][4];
            #pragma unroll
            for (int mt = 0; mt < 4; mt++)
                ldsm4(a[mt], ab + ((wm * 64 + mt * 16 + aro) * RSH + ks * 16 + ak8) * 2);
            #pragma unroll
            for (int p = 0; p < 2; p++)
                ldsm4(b[p], bb + ((wn * 32 + p * 16 + bro) * RSH + ks * 16 + bk8) * 2);
            #pragma unroll
            for (int mt = 0; mt < 4; mt++)
                #pragma unroll
                for (int nt = 0; nt < 4; nt++)
                    mma16(c[mt][nt], a[mt],
                          b[nt >> 1][(nt & 1) * 2], b[nt >> 1][(nt & 1) * 2 + 1]);
        }
    }

    #pragma unroll
    for (int mt = 0; mt < 4; mt++) {
        #pragma unroll
        for (int nt = 0; nt < 4; nt++) {
            int col = bn + wn * 32 + nt * 8 + tig * 2;
            float2 bi = make_float2(0.f, 0.f);
            if (BIAS) bi = *(const float2*)&bias[col];
            #pragma unroll
            for (int half_ = 0; half_ < 2; half_++) {
                int row = bm + wm * 64 + mt * 16 + gid + half_ * 8;
                float vx = c[mt][nt][half_ * 2 + 0] + bi.x;
                float vy = c[mt][nt][half_ * 2 + 1] + bi.y;
                if (RES) {
                    float2 r = *(const float2*)&Res[(size_t)row * N + col];
                    vx += r.x; vy += r.y;
                }
                if (HOUT) {
                    *(half2*)&C16[(size_t)row * N + col] = __floats2half2_rn(vx, vy);
                } else {
                    *(float2*)&C[(size_t)row * N + col] = make_float2(vx, vy);
                }
                if (TOUT) {
                    *(half2*)&CT[(size_t)row * N + col] =
                        __floats2half2_rn(tanhf(vx), tanhf(vy));
                }
            }
        }
    }
}

// ---------------- transpose + fp16 convert: out[C][R] = in[R][C] ----------------
__global__ void __launch_bounds__(256) transpose_h_kernel(
    const float* __restrict__ in, __half* __restrict__ out, int R, int C)
{
    __shared__ float t[32][33];
    int bx = blockIdx.x << 5, by = blockIdx.y << 5;
    int x = threadIdx.x, y = threadIdx.y;
    #pragma unroll
    for (int i = 0; i < 32; i += 8)
        t[y + i][x] = in[(size_t)(by + y + i) * C + bx + x];
    __syncthreads();
    #pragma unroll
    for (int i = 0; i < 32; i += 8)
        out[(size_t)(bx + y + i) * R + by + x] = __float2half(t[x][y + i]);
}

// ---------------------------------------------------------------------------
// FP16 tensor-core flash attention with tanh-Hopfield correction.
// 128 thr (4 warps), 64 queries/block, 64-key tiles, m16n8k16.
// Tiles [token][d] fp16, row stride 72 halves (144B: conflict-free ldmatrix).
// ---------------------------------------------------------------------------
#define AST 72
#define ATILE (64*AST)                       // halves per tile
#define ATT_SMEM (6*ATILE*2)                 // Q,T,P,K,tK,V = 55296 B

__global__ void __launch_bounds__(128) attn_f16_kernel(
    const __half* __restrict__ Q,  const __half* __restrict__ K,
    const __half* __restrict__ TK, const __half* __restrict__ V,
    const __half* __restrict__ TQJ, __half* __restrict__ O,
    const float* __restrict__ lam_p)
{
    extern __shared__ __half smh[];
    const uint32_t su = (uint32_t)__cvta_generic_to_shared(smh);
    const uint32_t Qb = su;
    const uint32_t Tb = Qb + ATILE * 2;
    const uint32_t Pb = Tb + ATILE * 2;
    const uint32_t Kb = Pb + ATILE * 2;
    const uint32_t Gb = Kb + ATILE * 2;      // tanh(K)
    const uint32_t Vb = Gb + ATILE * 2;
    __half* Ps = smh + 2 * ATILE;

    const int tid = threadIdx.x;
    const int wid = tid >> 5, lane = tid & 31;
    const int gid = lane >> 2, tig = lane & 3;
    const int mrow = wid * 16;
    const int bh = blockIdx.y, b = bh >> 4, h = bh & 15;
    const int q0 = blockIdx.x << 6;
    const float lam = __ldg(lam_p);

    const int t7 = lane & 7;
    const uint32_t aro = ((lane >> 3) & 1) * 8 + t7, ak8 = ((lane >> 4) & 1) * 8;
    const uint32_t bro = ((lane >> 4) & 1) * 8 + t7, bk8 = ((lane >> 3) & 1) * 8;
    const uint32_t vko = ((lane >> 3) & 1) * 8 + t7, vn8 = ((lane >> 4) & 1) * 8;

    // stage Q and tQJ (once)
    for (int i = tid; i < 512; i += 128) {
        int r = i >> 3, c8 = i & 7;
        size_t g = ((size_t)(b * SS + q0 + r)) * DD + h * HD + c8 * 8;
        cp16(Qb + (r * AST + c8 * 8) * 2, &Q[g]);
        cp16(Tb + (r * AST + c8 * 8) * 2, &TQJ[g]);
    }
    cp_commit();

    float m0 = -1e30f, m1 = -1e30f, l0 = 0.f, l1 = 0.f;
    float o[8][4] = {};

    for (int k0 = 0; k0 < SS; k0 += 64) {
        __syncthreads();
        for (int i = tid; i < 512; i += 128) {
            int r = i >> 3, c8 = i & 7;
            size_t g = ((size_t)(b * SS + k0 + r)) * DD + h * HD + c8 * 8;
            uint32_t off = (r * AST + c8 * 8) * 2;
            cp16(Kb + off, &K[g]);
            cp16(Gb + off, &TK[g]);
            cp16(Vb + off, &V[g]);
        }
        cp_commit();
        cp_wait<0>();
        __syncthreads();

        // S = Q K^T, D = tQJ tanhK^T
        float cs[8][4] = {}, cd[8][4] = {};
        #pragma unroll
        for (int ks = 0; ks < 4; ks++) {
            uint32_t aq[4], at[4], bk[4][4], bt[4][4];
            ldsm4(aq, Qb + ((mrow + aro) * AST + ks * 16 + ak8) * 2);
            ldsm4(at, Tb + ((mrow + aro) * AST + ks * 16 + ak8) * 2);
            #pragma unroll
            for (int p = 0; p < 4; p++) {
                uint32_t off = ((p * 16 + bro) * AST + ks * 16 + bk8) * 2;
                ldsm4(bk[p], Kb + off);
                ldsm4(bt[p], Gb + off);
            }
            #pragma unroll
            for (int nt = 0; nt < 8; nt++) {
                mma16(cs[nt], aq, bk[nt >> 1][(nt & 1) * 2], bk[nt >> 1][(nt & 1) * 2 + 1]);
                mma16(cd[nt], at, bt[nt >> 1][(nt & 1) * 2], bt[nt >> 1][(nt & 1) * 2 + 1]);
            }
        }

        // scores + online softmax
        float s[8][4];
        float mx0 = -1e30f, mx1 = -1e30f;
        #pragma unroll
        for (int nt = 0; nt < 8; nt++) {
            #pragma unroll
            for (int e = 0; e < 4; e++)
                s[nt][e] = fmaf(lam, cd[nt][e], cs[nt][e] * INV_SCALE);
            mx0 = fmaxf(mx0, fmaxf(s[nt][0], s[nt][1]));
            mx1 = fmaxf(mx1, fmaxf(s[nt][2], s[nt][3]));
        }
        mx0 = fmaxf(mx0, __shfl_xor_sync(0xffffffffu, mx0, 1));
        mx0 = fmaxf(mx0, __shfl_xor_sync(0xffffffffu, mx0, 2));
        mx1 = fmaxf(mx1, __shfl_xor_sync(0xffffffffu, mx1, 1));
        mx1 = fmaxf(mx1, __shfl_xor_sync(0xffffffffu, mx1, 2));
        float mn0 = fmaxf(m0, mx0), mn1 = fmaxf(m1, mx1);
        float corr0 = __expf(m0 - mn0), corr1 = __expf(m1 - mn1);
        m0 = mn0; m1 = mn1;
        l0 *= corr0; l1 *= corr1;

        float sum0 = 0.f, sum1 = 0.f;
        #pragma unroll
        for (int nt = 0; nt < 8; nt++) {
            float p00 = __expf(s[nt][0] - mn0);
            float p01 = __expf(s[nt][1] - mn0);
            float p10 = __expf(s[nt][2] - mn1);
            float p11 = __expf(s[nt][3] - mn1);
            sum0 += p00 + p01; sum1 += p10 + p11;
            int col = nt * 8 + tig * 2;
            *(half2*)&Ps[(mrow + gid    ) * AST + col] = __floats2half2_rn(p00, p01);
            *(half2*)&Ps[(mrow + gid + 8) * AST + col] = __floats2half2_rn(p10, p11);
        }
        sum0 += __shfl_xor_sync(0xffffffffu, sum0, 1);
        sum0 += __shfl_xor_sync(0xffffffffu, sum0, 2);
        sum1 += __shfl_xor_sync(0xffffffffu, sum1, 1);
        sum1 += __shfl_xor_sync(0xffffffffu, sum1, 2);
        l0 += sum0; l1 += sum1;

        #pragma unroll
        for (int nt = 0; nt < 8; nt++) {
            o[nt][0] *= corr0; o[nt][1] *= corr0;
            o[nt][2] *= corr1; o[nt][3] *= corr1;
        }
        __syncwarp();

        // O += P V
        #pragma unroll
        for (int ks = 0; ks < 4; ks++) {
            uint32_t ap[4], bv[4][4];
            ldsm4(ap, Pb + ((mrow + aro) * AST + ks * 16 + ak8) * 2);
            #pragma unroll
            for (int p = 0; p < 4; p++)
                ldsm4t(bv[p], Vb + ((ks * 16 + vko) * AST + p * 16 + vn8) * 2);
            #pragma unroll
            for (int nt = 0; nt < 8; nt++)
                mma16(o[nt], ap, bv[nt >> 1][(nt & 1) * 2], bv[nt >> 1][(nt & 1) * 2 + 1]);
        }
        __syncwarp();
    }

    float inv0 = 1.f / l0, inv1 = 1.f / l1;
    int row0 = q0 + mrow + gid, row1 = row0 + 8;
    #pragma unroll
    for (int nt = 0; nt < 8; nt++) {
        int col = nt * 8 + tig * 2;
        *(half2*)&O[((size_t)(b * SS + row0)) * DD + h * HD + col] =
            __floats2half2_rn(o[nt][0] * inv0, o[nt][1] * inv0);
        *(half2*)&O[((size_t)(b * SS + row1)) * DD + h * HD + col] =
            __floats2half2_rn(o[nt][2] * inv1, o[nt][3] * inv1);
    }
}

// ---------------- LayerNorm: fp32 in, fp16 out (+opt fp16 tanh out) ----------------
__global__ void __launch_bounds__(256) ln_kernel(
    const float* __restrict__ X, const float* __restrict__ g,
    const float* __restrict__ b, __half* __restrict__ Y,
    __half* __restrict__ YT, int N)
{
    int row = blockIdx.x;
    const float* x = X + (size_t)row * N;
    float s = 0.f, s2 = 0.f;
    for (int i = threadIdx.x; i < N; i += 256) {
        float v = x[i];
        s += v; s2 = fmaf(v, v, s2);
    }
    __shared__ float sh[64];
    for (int o = 16; o > 0; o >>= 1) {
        s  += __shfl_down_sync(0xffffffffu, s,  o);
        s2 += __shfl_down_sync(0xffffffffu, s2, o);
    }
    int wid = threadIdx.x >> 5, lane = threadIdx.x & 31;
    if (lane == 0) { sh[wid] = s; sh[wid + 32] = s2; }
    __syncthreads();
    if (threadIdx.x == 0) {
        float ts = 0.f, ts2 = 0.f;
        for (int w = 0; w < 8; w++) { ts += sh[w]; ts2 += sh[w + 32]; }
        float mu = ts / N, var = ts2 / N - mu * mu;
        sh[0] = mu; sh[1] = rsqrtf(var + 1e-5f);
    }
    __syncthreads();
    float mu = sh[0], rstd = sh[1];
    for (int i = threadIdx.x; i < N; i += 256) {
        float v = (x[i] - mu) * rstd * g[i] + b[i];
        Y[(size_t)row * N + i] = __float2half(v);
        if (YT) YT[(size_t)row * N + i] = __float2half(tanhf(v));
    }
}

// ---------------- QBNN combine + LN + GELU (fp32 in; fp16 and/or fp32 out) --------
__global__ void __launch_bounds__(256) qln_gelu_kernel(
    const float* __restrict__ HT, const float* __restrict__ DLT,
    const float* __restrict__ g,  const float* __restrict__ b,
    const float* __restrict__ Res, float* __restrict__ Yf,
    __half* __restrict__ Yh, __half* __restrict__ Yth, int N)
{
    extern __shared__ float rowbuf[];
    __shared__ float sh[64];
    int row = blockIdx.x;
    size_t base = (size_t)row * N;

    float s = 0.f, s2 = 0.f;
    for (int i = threadIdx.x; i < N; i += 256) {
        float ht = HT[base + i];
        float v  = fmaf(LAM_EFF * DLT[base + i], tanhf(ht), ht);
        rowbuf[i] = v;
        s += v; s2 = fmaf(v, v, s2);
    }
    for (int o = 16; o > 0; o >>= 1) {
        s  += __shfl_down_sync(0xffffffffu, s,  o);
        s2 += __shfl_down_sync(0xffffffffu, s2, o);
    }
    int wid = threadIdx.x >> 5, lane = threadIdx.x & 31;
    if (lane == 0) { sh[wid] = s; sh[wid + 32] = s2; }
    __syncthreads();
    if (threadIdx.x == 0) {
        float ts = 0.f, ts2 = 0.f;
        for (int w = 0; w < 8; w++) { ts += sh[w]; ts2 += sh[w + 32]; }
        float mu = ts / N, var = ts2 / N - mu * mu;
        sh[0] = mu; sh[1] = rsqrtf(var + 1e-5f);
    }
    __syncthreads();
    float mu = sh[0], rstd = sh[1];
    for (int i = threadIdx.x; i < N; i += 256) {
        float v  = (rowbuf[i] - mu) * rstd * g[i] + b[i];
        float ge = v * normcdff(v);
        float o  = Res ? Res[base + i] + ge : ge;
        if (Yf)  Yf[base + i] = o;
        if (Yh)  Yh[base + i] = __float2half(o);
        if (Yth) Yth[base + i] = __float2half(tanhf(o));
    }
}

// ---------------- tQJ: per (b,h) tanh(Q)@J[h]; fp16 in/out, fp32 math ----------
__global__ void __launch_bounds__(256) tqj_kernel(
    const __half* __restrict__ Q, const float* __restrict__ J,
    __half* __restrict__ Out)
{
    __shared__ __align__(16) float As[64][64];
    __shared__ __align__(16) float Js[64][64];
    int tid = threadIdx.x;
    int bh = blockIdx.x; int b = bh >> 4, h = bh & 15;
    int s0 = blockIdx.y << 6;

    #pragma unroll
    for (int i = 0; i < 4; i++) {
        int idx = tid + (i << 8);
        int r = idx >> 4, kq = (idx & 15) << 2;
        const __half* qp = &Q[((size_t)(b * SS + s0 + r)) * DD + h * HD + kq];
        As[kq + 0][r] = tanhf(__half2float(qp[0]));
        As[kq + 1][r] = tanhf(__half2float(qp[1]));
        As[kq + 2][r] = tanhf(__half2float(qp[2]));
        As[kq + 3][r] = tanhf(__half2float(qp[3]));
        ((float4*)Js)[idx] = *(const float4*)&J[(size_t)h * HD * HD + idx * 4];
    }
    __syncthreads();

    int tx = tid & 15, ty = tid >> 4;
    float c[4][4] = {};
    #pragma unroll 8
    for (int kk = 0; kk < 64; kk++) {
        float a[4], bv[4];
        *(float4*)a  = *(const float4*)&As[kk][ty * 4];
        *(float4*)bv = *(const float4*)&Js[kk][tx * 4];
        #pragma unroll
        for (int i = 0; i < 4; i++)
            #pragma unroll
            for (int j = 0; j < 4; j++)
                c[i][j] = fmaf(a[i], bv[j], c[i][j]);
    }
    #pragma unroll
    for (int i = 0; i < 4; i++) {
        size_t idx = ((size_t)(b * SS + s0 + ty * 4 + i)) * DD + h * HD + tx * 4;
        *(half2*)&Out[idx]     = __floats2half2_rn(c[i][0], c[i][1]);
        *(half2*)&Out[idx + 2] = __floats2half2_rn(c[i][2], c[i][3]);
    }
}

// ---------------- host ----------------
template<typename T> static T* symaddr(const void* s)
{
    void* p = nullptr;
    cudaGetSymbolAddress(&p, s);
    return (T*)p;
}

extern "C" void kernel_launch(void* const* d_in, const int* in_sizes, int n_in,
                              void* d_out, int out_size)
{
    (void)in_sizes; (void)n_in; (void)out_size;

    const float* x   = (const float*)d_in[0];
    const float* wq  = (const float*)d_in[1];
    const float* bq  = (const float*)d_in[2];
    const float* wk  = (const float*)d_in[3];
    const float* bk  = (const float*)d_in[4];
    const float* wv  = (const float*)d_in[5];
    const float* bv  = (const float*)d_in[6];
    const float* wo  = (const float*)d_in[7];
    const float* bo  = (const float*)d_in[8];
    const float* Jat = (const float*)d_in[9];
    const float* lam = (const float*)d_in[10];
    const float* gat = (const float*)d_in[11];
    const float* bat = (const float*)d_in[12];
    const float* W1  = (const float*)d_in[13];
    const float* b1  = (const float*)d_in[14];
    const float* J1  = (const float*)d_in[15];
    const float* g1  = (const float*)d_in[17];
    const float* be1 = (const float*)d_in[18];
    const float* W2  = (const float*)d_in[19];
    const float* b2  = (const float*)d_in[20];
    const float* J2  = (const float*)d_in[21];
    const float* g2  = (const float*)d_in[23];
    const float* be2 = (const float*)d_in[24];
    const float* gf  = (const float*)d_in[25];
    const float* bf  = (const float*)d_in[26];
    float* out = (float*)d_out;

    __half* p_xn  = symaddr<__half>(h_xn);
    __half* p_Q   = symaddr<__half>(h_Q);
    __half* p_K   = symaddr<__half>(h_K);
    __half* p_tK  = symaddr<__half>(h_tK);
    __half* p_V   = symaddr<__half>(h_V);
    __half* p_tQJ = symaddr<__half>(h_tQJ);
    __half* p_ao  = symaddr<__half>(h_ao);
    float*  p_x1  = symaddr<float>(f_x1);
    __half* p_th  = symaddr<__half>(h_th);
    float*  p_hh  = symaddr<float>(f_hhat);
    float*  p_dl  = symaddr<float>(f_dlt);
    __half* p_h1  = symaddr<__half>(h_h1);
    __half* p_th1 = symaddr<__half>(h_th1);
    __half* p_wqT = symaddr<__half>(h_wqT);
    __half* p_wkT = symaddr<__half>(h_wkT);
    __half* p_wvT = symaddr<__half>(h_wvT);
    __half* p_woT = symaddr<__half>(h_woT);
    __half* p_W1T = symaddr<__half>(h_W1T);
    __half* p_J1T = symaddr<__half>(h_J1T);
    __half* p_W2T = symaddr<__half>(h_W2T);
    __half* p_J2T = symaddr<__half>(h_J2T);

    cudaFuncSetAttribute(attn_f16_kernel,
                         cudaFuncAttributeMaxDynamicSharedMemorySize, ATT_SMEM);
    cudaFuncSetAttribute(gemm_f16_kernel<true, false, false, true>,
                         cudaFuncAttributeMaxDynamicSharedMemorySize, GEMM_SMEM);
    cudaFuncSetAttribute(gemm_f16_kernel<true, false, true, true>,
                         cudaFuncAttributeMaxDynamicSharedMemorySize, GEMM_SMEM);
    cudaFuncSetAttribute(gemm_f16_kernel<true, true, false, false>,
                         cudaFuncAttributeMaxDynamicSharedMemorySize, GEMM_SMEM);
    cudaFuncSetAttribute(gemm_f16_kernel<true, false, false, false>,
                         cudaFuncAttributeMaxDynamicSharedMemorySize, GEMM_SMEM);
    cudaFuncSetAttribute(gemm_f16_kernel<false, false, false, false>,
                         cudaFuncAttributeMaxDynamicSharedMemorySize, GEMM_SMEM);

    // weight transposes + fp16 convert: [K][N] -> [N][K]
    dim3 tb(32, 8);
    transpose_h_kernel<<<dim3(DD/32,  DD/32 ), tb>>>(wq, p_wqT, DD,  DD);
    transpose_h_kernel<<<dim3(DD/32,  DD/32 ), tb>>>(wk, p_wkT, DD,  DD);
    transpose_h_kernel<<<dim3(DD/32,  DD/32 ), tb>>>(wv, p_wvT, DD,  DD);
    transpose_h_kernel<<<dim3(DD/32,  DD/32 ), tb>>>(wo, p_woT, DD,  DD);
    transpose_h_kernel<<<dim3(FFD/32, DD/32 ), tb>>>(W1, p_W1T, DD,  FFD);
    transpose_h_kernel<<<dim3(FFD/32, DD/32 ), tb>>>(J1, p_J1T, DD,  FFD);
    transpose_h_kernel<<<dim3(DD/32,  FFD/32), tb>>>(W2, p_W2T, FFD, DD);
    transpose_h_kernel<<<dim3(DD/32,  FFD/32), tb>>>(J2, p_J2T, FFD, DD);

    // --- attention branch ---
    ln_kernel<<<NT, 256>>>(x, gat, bat, p_xn, nullptr, DD);

    dim3 gP(DD / 128, NT / 128);
    gemm_f16_kernel<true, false, false, true><<<gP, 256, GEMM_SMEM>>>(
        p_xn, p_wqT, bq, nullptr, nullptr, p_Q, nullptr, NT, DD, DD);
    gemm_f16_kernel<true, false, true, true><<<gP, 256, GEMM_SMEM>>>(
        p_xn, p_wkT, bk, nullptr, nullptr, p_K, p_tK, NT, DD, DD);
    gemm_f16_kernel<true, false, false, true><<<gP, 256, GEMM_SMEM>>>(
        p_xn, p_wvT, bv, nullptr, nullptr, p_V, nullptr, NT, DD, DD);

    tqj_kernel<<<dim3(BB * HH, SS / 64), 256>>>(p_Q, Jat, p_tQJ);

    attn_f16_kernel<<<dim3(SS / 64, BB * HH), 128, ATT_SMEM>>>(
        p_Q, p_K, p_tK, p_V, p_tQJ, p_ao, lam);

    gemm_f16_kernel<true, true, false, false><<<gP, 256, GEMM_SMEM>>>(
        p_ao, p_woT, bo, x, p_x1, nullptr, nullptr, NT, DD, DD);

    // --- QBNN FFN layer 1 ---
    ln_kernel<<<NT, 256>>>(p_x1, gf, bf, p_xn, p_th, DD);

    dim3 gF1(FFD / 128, NT / 128);
    gemm_f16_kernel<true, false, false, false><<<gF1, 256, GEMM_SMEM>>>(
        p_xn, p_W1T, b1, nullptr, p_hh, nullptr, nullptr, NT, FFD, DD);
    gemm_f16_kernel<false, false, false, false><<<gF1, 256, GEMM_SMEM>>>(
        p_th, p_J1T, nullptr, nullptr, p_dl, nullptr, nullptr, NT, FFD, DD);

    qln_gelu_kernel<<<NT, 256, FFD * sizeof(float)>>>(
        p_hh, p_dl, g1, be1, nullptr, nullptr, p_h1, p_th1, FFD);

    // --- QBNN FFN layer 2 ---
    dim3 gF2(DD / 128, NT / 128);
    gemm_f16_kernel<true, false, false, false><<<gF2, 256, GEMM_SMEM>>>(
        p_h1, p_W2T, b2, nullptr, p_hh, nullptr, nullptr, NT, DD, FFD);
    gemm_f16_kernel<false, false, false, false><<<gF2, 256, GEMM_SMEM>>>(
        p_th1, p_J2T, nullptr, nullptr, p_dl, nullptr, nullptr, NT, DD, FFD);

    qln_gelu_kernel<<<NT, 256, DD * sizeof(float)>>>(
        p_hh, p_dl, g2, be2, p_x1, out, nullptr, nullptr, DD);
}

// round 14
// speedup vs baseline: 1.7758x; 1.0584x over previous
#include <cuda_runtime.h>
#include <cuda_fp16.h>
#include <math.h>
#include <stdint.h>

#define BB   4
#define SS   1024
#define DD   1024
#define HH   16
#define HD   64
#define FFD  4096
#define NT   (BB*SS)
#define INV_SCALE 0.125f
#define LAM_EFF   0.5f

// ---------------- scratch ----------------
__device__ __half h_xn  [NT*DD];
__device__ __half h_Q   [NT*DD];
__device__ __half h_K   [NT*DD];
__device__ __half h_tK  [NT*DD];
__device__ __half h_V   [NT*DD];
__device__ __half h_tQJ [NT*DD];
__device__ __half h_ao  [NT*DD];
__device__ float  f_x1  [NT*DD];
__device__ __half h_th  [NT*DD];
__device__ __half h_hh  [NT*FFD];
__device__ __half h_dl  [NT*FFD];
__device__ __half h_h1  [NT*FFD];
__device__ __half h_th1 [NT*FFD];
// fp16 weights, natural [K][N] layout
__device__ __half h_wq  [DD*DD];
__device__ __half h_wk  [DD*DD];
__device__ __half h_wv  [DD*DD];
__device__ __half h_wo  [DD*DD];
__device__ __half h_W1  [DD*FFD];
__device__ __half h_J1  [DD*FFD];
__device__ __half h_W2  [FFD*DD];
__device__ __half h_J2  [FFD*DD];

// ---------------- helpers ----------------
__device__ __forceinline__ void cp16(uint32_t d, const void* g)
{ asm volatile("cp.async.cg.shared.global [%0], [%1], 16;\n" :: "r"(d), "l"(g)); }
__device__ __forceinline__ void cp_commit()
{ asm volatile("cp.async.commit_group;\n"); }
template<int N> __device__ __forceinline__ void cp_wait()
{ asm volatile("cp.async.wait_group %0;\n" :: "n"(N)); }

__device__ __forceinline__ void mma16(float* c, const uint32_t* a,
                                      uint32_t b0, uint32_t b1)
{
    asm volatile(
        "mma.sync.aligned.m16n8k16.row.col.f32.f16.f16.f32 "
        "{%0,%1,%2,%3},{%4,%5,%6,%7},{%8,%9},{%0,%1,%2,%3};"
        : "+f"(c[0]), "+f"(c[1]), "+f"(c[2]), "+f"(c[3])
        : "r"(a[0]), "r"(a[1]), "r"(a[2]), "r"(a[3]), "r"(b0), "r"(b1));
}
__device__ __forceinline__ void ldsm4(uint32_t* r, uint32_t addr)
{
    asm volatile("ldmatrix.sync.aligned.m8n8.x4.shared.b16 {%0,%1,%2,%3}, [%4];"
                 : "=r"(r[0]), "=r"(r[1]), "=r"(r[2]), "=r"(r[3]) : "r"(addr));
}
__device__ __forceinline__ void ldsm4t(uint32_t* r, uint32_t addr)
{
    asm volatile("ldmatrix.sync.aligned.m8n8.x4.trans.shared.b16 {%0,%1,%2,%3}, [%4];"
                 : "=r"(r[0]), "=r"(r[1]), "=r"(r[2]), "=r"(r[3]) : "r"(addr));
}

// ---------------------------------------------------------------------------
// FP16 GEMM v5: C[M,N] = A[M,K] @ W[K,N] (+bias)(+Res); fp32 or fp16 out.
// A staged [128 m][40 k]; W staged natural [32 k][136 n] + ldmatrix.trans.
// 128x128x32 block, 4-stage cp.async, 8 warps (2M x 4N), m16n8k16.
// ---------------------------------------------------------------------------
#define RSH   40
#define BSTR  136
#define ATILEB (128*RSH*2)          // 10240 B
#define BTILEB (32*BSTR*2)          //  8704 B
#define STG_B  (ATILEB + BTILEB)    // 18944 B
#define NSTG   4
#define GEMM_SMEM (NSTG*STG_B)      // 75776 B

template<bool BIAS, bool RES, bool HOUT>
__global__ void __launch_bounds__(256, 2) gemm_f16_kernel(
    const __half* __restrict__ A, const __half* __restrict__ W,
    const float* __restrict__ bias, const float* __restrict__ Res,
    float* __restrict__ C, __half* __restrict__ C16,
    int M, int N, int K)
{
    extern __shared__ __half smh[];
    const uint32_t su = (uint32_t)__cvta_generic_to_shared(smh);

    const int tid = threadIdx.x;
    const int bn = blockIdx.x << 7, bm = blockIdx.y << 7;
    const int wid = tid >> 5, lane = tid & 31;
    const int wm = wid & 1, wn = wid >> 1;
    const int gid = lane >> 2, tig = lane & 3;

    float c[4][4][4] = {};

    auto load_stage = [&](int kt) {
        uint32_t ab = su + (kt & 3) * STG_B, bb = ab + ATILEB;
        #pragma unroll
        for (int i = 0; i < 2; i++) {
            int idx = tid + (i << 8);
            int r = idx >> 2, c8 = idx & 3;
            cp16(ab + (r * RSH + c8 * 8) * 2,
                 &A[(size_t)(bm + r) * K + kt * 32 + c8 * 8]);
        }
        #pragma unroll
        for (int i = 0; i < 2; i++) {
            int idx = tid + (i << 8);
            int r = idx >> 4, c8 = idx & 15;
            cp16(bb + (r * BSTR + c8 * 8) * 2,
                 &W[(size_t)(kt * 32 + r) * N + bn + c8 * 8]);
        }
        cp_commit();
    };

    const int KT = K >> 5;
    load_stage(0); load_stage(1); load_stage(2);

    const int t7 = lane & 7;
    const uint32_t aro = ((lane >> 3) & 1) * 8 + t7;
    const uint32_t ak8 = ((lane >> 4) & 1) * 8;
    const uint32_t bko = ((lane >> 3) & 1) * 8 + t7;   // k row for B.trans
    const uint32_t bn8 = ((lane >> 4) & 1) * 8;        // n offset

    for (int kt = 0; kt < KT; kt++) {
        cp_wait<2>();
        __syncthreads();
        if (kt + 3 < KT) load_stage(kt + 3); else cp_commit();

        uint32_t ab = su + (kt & 3) * STG_B, bb = ab + ATILEB;
        #pragma unroll
        for (int ks = 0; ks < 2; ks++) {
            uint32_t a[4][4], b[2][4];
            #pragma unroll
            for (int mt = 0; mt < 4; mt++)
                ldsm4(a[mt], ab + ((wm * 64 + mt * 16 + aro) * RSH + ks * 16 + ak8) * 2);
            #pragma unroll
            for (int p = 0; p < 2; p++)
                ldsm4t(b[p], bb + ((ks * 16 + bko) * BSTR + wn * 32 + p * 16 + bn8) * 2);
            #pragma unroll
            for (int mt = 0; mt < 4; mt++)
                #pragma unroll
                for (int nt = 0; nt < 4; nt++)
                    mma16(c[mt][nt], a[mt],
                          b[nt >> 1][(nt & 1) * 2], b[nt >> 1][(nt & 1) * 2 + 1]);
        }
    }

    #pragma unroll
    for (int mt = 0; mt < 4; mt++) {
        #pragma unroll
        for (int nt = 0; nt < 4; nt++) {
            int col = bn + wn * 32 + nt * 8 + tig * 2;
            float2 bi = make_float2(0.f, 0.f);
            if (BIAS) bi = *(const float2*)&bias[col];
            #pragma unroll
            for (int hf = 0; hf < 2; hf++) {
                int row = bm + wm * 64 + mt * 16 + gid + hf * 8;
                float vx = c[mt][nt][hf * 2 + 0] + bi.x;
                float vy = c[mt][nt][hf * 2 + 1] + bi.y;
                if (RES) {
                    float2 r = *(const float2*)&Res[(size_t)row * N + col];
                    vx += r.x; vy += r.y;
                }
                if (HOUT)
                    *(half2*)&C16[(size_t)row * N + col] = __floats2half2_rn(vx, vy);
                else
                    *(float2*)&C[(size_t)row * N + col] = make_float2(vx, vy);
            }
        }
    }
}

// ---------------------------------------------------------------------------
// Merged QKV GEMM: one launch, weight/bias/output selected by blockIdx.x>>3.
// K segment (w==1) also writes tanh side output.
// ---------------------------------------------------------------------------
__global__ void __launch_bounds__(256, 2) gemm_qkv_kernel(
    const __half* __restrict__ A,
    const __half* __restrict__ Wq, const __half* __restrict__ Wk,
    const __half* __restrict__ Wv,
    const float* __restrict__ bq, const float* __restrict__ bk,
    const float* __restrict__ bv,
    __half* __restrict__ Qo, __half* __restrict__ Ko,
    __half* __restrict__ Vo, __half* __restrict__ tKo)
{
    extern __shared__ __half smh[];
    const uint32_t su = (uint32_t)__cvta_generic_to_shared(smh);

    const int w = blockIdx.x >> 3;
    const __half* W = (w == 0) ? Wq : (w == 1) ? Wk : Wv;
    const float* bias = (w == 0) ? bq : (w == 1) ? bk : bv;
    __half* Out = (w == 0) ? Qo : (w == 1) ? Ko : Vo;

    const int tid = threadIdx.x;
    const int bn = (blockIdx.x & 7) << 7, bm = blockIdx.y << 7;
    const int wid = tid >> 5, lane = tid & 31;
    const int wm = wid & 1, wn = wid >> 1;
    const int gid = lane >> 2, tig = lane & 3;

    float c[4][4][4] = {};

    auto load_stage = [&](int kt) {
        uint32_t ab = su + (kt & 3) * STG_B, bb = ab + ATILEB;
        #pragma unroll
        for (int i = 0; i < 2; i++) {
            int idx = tid + (i << 8);
            int r = idx >> 2, c8 = idx & 3;
            cp16(ab + (r * RSH + c8 * 8) * 2,
                 &A[(size_t)(bm + r) * DD + kt * 32 + c8 * 8]);
        }
        #pragma unroll
        for (int i = 0; i < 2; i++) {
            int idx = tid + (i << 8);
            int r = idx >> 4, c8 = idx & 15;
            cp16(bb + (r * BSTR + c8 * 8) * 2,
                 &W[(size_t)(kt * 32 + r) * DD + bn + c8 * 8]);
        }
        cp_commit();
    };

    load_stage(0); load_stage(1); load_stage(2);

    const int t7 = lane & 7;
    const uint32_t aro = ((lane >> 3) & 1) * 8 + t7;
    const uint32_t ak8 = ((lane >> 4) & 1) * 8;
    const uint32_t bko = ((lane >> 3) & 1) * 8 + t7;
    const uint32_t bn8 = ((lane >> 4) & 1) * 8;

    for (int kt = 0; kt < 32; kt++) {
        cp_wait<2>();
        __syncthreads();
        if (kt + 3 < 32) load_stage(kt + 3); else cp_commit();

        uint32_t ab = su + (kt & 3) * STG_B, bb = ab + ATILEB;
        #pragma unroll
        for (int ks = 0; ks < 2; ks++) {
            uint32_t a[4][4], b[2][4];
            #pragma unroll
            for (int mt = 0; mt < 4; mt++)
                ldsm4(a[mt], ab + ((wm * 64 + mt * 16 + aro) * RSH + ks * 16 + ak8) * 2);
            #pragma unroll
            for (int p = 0; p < 2; p++)
                ldsm4t(b[p], bb + ((ks * 16 + bko) * BSTR + wn * 32 + p * 16 + bn8) * 2);
            #pragma unroll
            for (int mt = 0; mt < 4; mt++)
                #pragma unroll
                for (int nt = 0; nt < 4; nt++)
                    mma16(c[mt][nt], a[mt],
                          b[nt >> 1][(nt & 1) * 2], b[nt >> 1][(nt & 1) * 2 + 1]);
        }
    }

    #pragma unroll
    for (int mt = 0; mt < 4; mt++) {
        #pragma unroll
        for (int nt = 0; nt < 4; nt++) {
            int col = bn + wn * 32 + nt * 8 + tig * 2;
            float2 bi = *(const float2*)&bias[col];
            #pragma unroll
            for (int hf = 0; hf < 2; hf++) {
                int row = bm + wm * 64 + mt * 16 + gid + hf * 8;
                float vx = c[mt][nt][hf * 2 + 0] + bi.x;
                float vy = c[mt][nt][hf * 2 + 1] + bi.y;
                *(half2*)&Out[(size_t)row * DD + col] = __floats2half2_rn(vx, vy);
                if (w == 1)
                    *(half2*)&tKo[(size_t)row * DD + col] =
                        __floats2half2_rn(tanhf(vx), tanhf(vy));
            }
        }
    }
}

// ---------------- fp32 -> fp16 convert (elementwise) ----------------
__global__ void __launch_bounds__(256) convert_h_kernel(
    const float* __restrict__ in, __half* __restrict__ out, int n4)
{
    int i = blockIdx.x * 256 + threadIdx.x;
    if (i < n4) {
        float4 v = *(const float4*)&in[i * 4];
        *(half2*)&out[i * 4]     = __floats2half2_rn(v.x, v.y);
        *(half2*)&out[i * 4 + 2] = __floats2half2_rn(v.z, v.w);
    }
}

// ---------------------------------------------------------------------------
// FP16 tensor-core flash attention (round-9, proven)
// ---------------------------------------------------------------------------
#define AST 72
#define ATILE (64*AST)
#define ATT_SMEM (6*ATILE*2)

__global__ void __launch_bounds__(128) attn_f16_kernel(
    const __half* __restrict__ Q,  const __half* __restrict__ K,
    const __half* __restrict__ TK, const __half* __restrict__ V,
    const __half* __restrict__ TQJ, __half* __restrict__ O,
    const float* __restrict__ lam_p)
{
    extern __shared__ __half smh[];
    const uint32_t su = (uint32_t)__cvta_generic_to_shared(smh);
    const uint32_t Qb = su;
    const uint32_t Tb = Qb + ATILE * 2;
    const uint32_t Pb = Tb + ATILE * 2;
    const uint32_t Kb = Pb + ATILE * 2;
    const uint32_t Gb = Kb + ATILE * 2;
    const uint32_t Vb = Gb + ATILE * 2;
    __half* Ps = smh + 2 * ATILE;

    const int tid = threadIdx.x;
    const int wid = tid >> 5, lane = tid & 31;
    const int gid = lane >> 2, tig = lane & 3;
    const int mrow = wid * 16;
    const int bh = blockIdx.y, b = bh >> 4, h = bh & 15;
    const int q0 = blockIdx.x << 6;
    const float lam = __ldg(lam_p);

    const int t7 = lane & 7;
    const uint32_t aro = ((lane >> 3) & 1) * 8 + t7, ak8 = ((lane >> 4) & 1) * 8;
    const uint32_t bro = ((lane >> 4) & 1) * 8 + t7, bk8 = ((lane >> 3) & 1) * 8;
    const uint32_t vko = ((lane >> 3) & 1) * 8 + t7, vn8 = ((lane >> 4) & 1) * 8;

    for (int i = tid; i < 512; i += 128) {
        int r = i >> 3, c8 = i & 7;
        size_t g = ((size_t)(b * SS + q0 + r)) * DD + h * HD + c8 * 8;
        cp16(Qb + (r * AST + c8 * 8) * 2, &Q[g]);
        cp16(Tb + (r * AST + c8 * 8) * 2, &TQJ[g]);
    }
    cp_commit();

    float m0 = -1e30f, m1 = -1e30f, l0 = 0.f, l1 = 0.f;
    float o[8][4] = {};

    for (int k0 = 0; k0 < SS; k0 += 64) {
        __syncthreads();
        for (int i = tid; i < 512; i += 128) {
            int r = i >> 3, c8 = i & 7;
            size_t g = ((size_t)(b * SS + k0 + r)) * DD + h * HD + c8 * 8;
            uint32_t off = (r * AST + c8 * 8) * 2;
            cp16(Kb + off, &K[g]);
            cp16(Gb + off, &TK[g]);
            cp16(Vb + off, &V[g]);
        }
        cp_commit();
        cp_wait<0>();
        __syncthreads();

        float cs[8][4] = {}, cd[8][4] = {};
        #pragma unroll
        for (int ks = 0; ks < 4; ks++) {
            uint32_t aq[4], at[4], bk[4][4], bt[4][4];
            ldsm4(aq, Qb + ((mrow + aro) * AST + ks * 16 + ak8) * 2);
            ldsm4(at, Tb + ((mrow + aro) * AST + ks * 16 + ak8) * 2);
            #pragma unroll
            for (int p = 0; p < 4; p++) {
                uint32_t off = ((p * 16 + bro) * AST + ks * 16 + bk8) * 2;
                ldsm4(bk[p], Kb + off);
                ldsm4(bt[p], Gb + off);
            }
            #pragma unroll
            for (int nt = 0; nt < 8; nt++) {
                mma16(cs[nt], aq, bk[nt >> 1][(nt & 1) * 2], bk[nt >> 1][(nt & 1) * 2 + 1]);
                mma16(cd[nt], at, bt[nt >> 1][(nt & 1) * 2], bt[nt >> 1][(nt & 1) * 2 + 1]);
            }
        }

        float s[8][4];
        float mx0 = -1e30f, mx1 = -1e30f;
        #pragma unroll
        for (int nt = 0; nt < 8; nt++) {
            #pragma unroll
            for (int e = 0; e < 4; e++)
                s[nt][e] = fmaf(lam, cd[nt][e], cs[nt][e] * INV_SCALE);
            mx0 = fmaxf(mx0, fmaxf(s[nt][0], s[nt][1]));
            mx1 = fmaxf(mx1, fmaxf(s[nt][2], s[nt][3]));
        }
        mx0 = fmaxf(mx0, __shfl_xor_sync(0xffffffffu, mx0, 1));
        mx0 = fmaxf(mx0, __shfl_xor_sync(0xffffffffu, mx0, 2));
        mx1 = fmaxf(mx1, __shfl_xor_sync(0xffffffffu, mx1, 1));
        mx1 = fmaxf(mx1, __shfl_xor_sync(0xffffffffu, mx1, 2));
        float mn0 = fmaxf(m0, mx0), mn1 = fmaxf(m1, mx1);
        float corr0 = __expf(m0 - mn0), corr1 = __expf(m1 - mn1);
        m0 = mn0; m1 = mn1;
        l0 *= corr0; l1 *= corr1;

        float sum0 = 0.f, sum1 = 0.f;
        #pragma unroll
        for (int nt = 0; nt < 8; nt++) {
            float p00 = __expf(s[nt][0] - mn0);
            float p01 = __expf(s[nt][1] - mn0);
            float p10 = __expf(s[nt][2] - mn1);
            float p11 = __expf(s[nt][3] - mn1);
            sum0 += p00 + p01; sum1 += p10 + p11;
            int col = nt * 8 + tig * 2;
            *(half2*)&Ps[(mrow + gid    ) * AST + col] = __floats2half2_rn(p00, p01);
            *(half2*)&Ps[(mrow + gid + 8) * AST + col] = __floats2half2_rn(p10, p11);
        }
        sum0 += __shfl_xor_sync(0xffffffffu, sum0, 1);
        sum0 += __shfl_xor_sync(0xffffffffu, sum0, 2);
        sum1 += __shfl_xor_sync(0xffffffffu, sum1, 1);
        sum1 += __shfl_xor_sync(0xffffffffu, sum1, 2);
        l0 += sum0; l1 += sum1;

        #pragma unroll
        for (int nt = 0; nt < 8; nt++) {
            o[nt][0] *= corr0; o[nt][1] *= corr0;
            o[nt][2] *= corr1; o[nt][3] *= corr1;
        }
        __syncwarp();

        #pragma unroll
        for (int ks = 0; ks < 4; ks++) {
            uint32_t ap[4], bv[4][4];
            ldsm4(ap, Pb + ((mrow + aro) * AST + ks * 16 + ak8) * 2);
            #pragma unroll
            for (int p = 0; p < 4; p++)
                ldsm4t(bv[p], Vb + ((ks * 16 + vko) * AST + p * 16 + vn8) * 2);
            #pragma unroll
            for (int nt = 0; nt < 8; nt++)
                mma16(o[nt], ap, bv[nt >> 1][(nt & 1) * 2], bv[nt >> 1][(nt & 1) * 2 + 1]);
        }
        __syncwarp();
    }

    float inv0 = 1.f / l0, inv1 = 1.f / l1;
    int row0 = q0 + mrow + gid, row1 = row0 + 8;
    #pragma unroll
    for (int nt = 0; nt < 8; nt++) {
        int col = nt * 8 + tig * 2;
        *(half2*)&O[((size_t)(b * SS + row0)) * DD + h * HD + col] =
            __floats2half2_rn(o[nt][0] * inv0, o[nt][1] * inv0);
        *(half2*)&O[((size_t)(b * SS + row1)) * DD + h * HD + col] =
            __floats2half2_rn(o[nt][2] * inv1, o[nt][3] * inv1);
    }
}

// ---------------- LayerNorm: fp32 in, fp16 out (+opt fp16 tanh out) ----------------
__global__ void __launch_bounds__(256) ln_kernel(
    const float* __restrict__ X, const float* __restrict__ g,
    const float* __restrict__ b, __half* __restrict__ Y,
    __half* __restrict__ YT, int N)
{
    int row = blockIdx.x;
    const float* x = X + (size_t)row * N;
    float s = 0.f, s2 = 0.f;
    for (int i = threadIdx.x; i < N; i += 256) {
        float v = x[i];
        s += v; s2 = fmaf(v, v, s2);
    }
    __shared__ float sh[64];
    for (int o = 16; o > 0; o >>= 1) {
        s  += __shfl_down_sync(0xffffffffu, s,  o);
        s2 += __shfl_down_sync(0xffffffffu, s2, o);
    }
    int wid = threadIdx.x >> 5, lane = threadIdx.x & 31;
    if (lane == 0) { sh[wid] = s; sh[wid + 32] = s2; }
    __syncthreads();
    if (threadIdx.x == 0) {
        float ts = 0.f, ts2 = 0.f;
        for (int w = 0; w < 8; w++) { ts += sh[w]; ts2 += sh[w + 32]; }
        float mu = ts / N, var = ts2 / N - mu * mu;
        sh[0] = mu; sh[1] = rsqrtf(var + 1e-5f);
    }
    __syncthreads();
    float mu = sh[0], rstd = sh[1];
    for (int i = threadIdx.x; i < N; i += 256) {
        float v = (x[i] - mu) * rstd * g[i] + b[i];
        Y[(size_t)row * N + i] = __float2half(v);
        if (YT) YT[(size_t)row * N + i] = __float2half(tanhf(v));
    }
}

// ---------------- QBNN combine + LN + GELU (fp16 ht/dlt in) ----------------
__global__ void __launch_bounds__(256) qln_gelu_kernel(
    const __half* __restrict__ HT, const __half* __restrict__ DLT,
    const float* __restrict__ g,  const float* __restrict__ b,
    const float* __restrict__ Res, float* __restrict__ Yf,
    __half* __restrict__ Yh, __half* __restrict__ Yth, int N)
{
    extern __shared__ float rowbuf[];
    __shared__ float sh[64];
    int row = blockIdx.x;
    size_t base = (size_t)row * N;

    float s = 0.f, s2 = 0.f;
    for (int i = threadIdx.x; i < N; i += 256) {
        float ht = __half2float(HT[base + i]);
        float dl = __half2float(DLT[base + i]);
        float v  = fmaf(LAM_EFF * dl, tanhf(ht), ht);
        rowbuf[i] = v;
        s += v; s2 = fmaf(v, v, s2);
    }
    for (int o = 16; o > 0; o >>= 1) {
        s  += __shfl_down_sync(0xffffffffu, s,  o);
        s2 += __shfl_down_sync(0xffffffffu, s2, o);
    }
    int wid = threadIdx.x >> 5, lane = threadIdx.x & 31;
    if (lane == 0) { sh[wid] = s; sh[wid + 32] = s2; }
    __syncthreads();
    if (threadIdx.x == 0) {
        float ts = 0.f, ts2 = 0.f;
        for (int w = 0; w < 8; w++) { ts += sh[w]; ts2 += sh[w + 32]; }
        float mu = ts / N, var = ts2 / N - mu * mu;
        sh[0] = mu; sh[1] = rsqrtf(var + 1e-5f);
    }
    __syncthreads();
    float mu = sh[0], rstd = sh[1];
    for (int i = threadIdx.x; i < N; i += 256) {
        float v  = (rowbuf[i] - mu) * rstd * g[i] + b[i];
        float ge = v * normcdff(v);
        float o  = Res ? Res[base + i] + ge : ge;
        if (Yf)  Yf[base + i] = o;
        if (Yh)  Yh[base + i] = __float2half(o);
        if (Yth) Yth[base + i] = __float2half(tanhf(o));
    }
}

// ---------------- tQJ: per (b,h) tanh(Q)@J[h]; fp16 in/out, fp32 math ----------
__global__ void __launch_bounds__(256) tqj_kernel(
    const __half* __restrict__ Q, const float* __restrict__ J,
    __half* __restrict__ Out)
{
    __shared__ __align__(16) float As[64][64];
    __shared__ __align__(16) float Js[64][64];
    int tid = threadIdx.x;
    int bh = blockIdx.x; int b = bh >> 4, h = bh & 15;
    int s0 = blockIdx.y << 6;

    #pragma unroll
    for (int i = 0; i < 4; i++) {
        int idx = tid + (i << 8);
        int r = idx >> 4, kq = (idx & 15) << 2;
        const __half* qp = &Q[((size_t)(b * SS + s0 + r)) * DD + h * HD + kq];
        As[kq + 0][r] = tanhf(__half2float(qp[0]));
        As[kq + 1][r] = tanhf(__half2float(qp[1]));
        As[kq + 2][r] = tanhf(__half2float(qp[2]));
        As[kq + 3][r] = tanhf(__half2float(qp[3]));
        ((float4*)Js)[idx] = *(const float4*)&J[(size_t)h * HD * HD + idx * 4];
    }
    __syncthreads();

    int tx = tid & 15, ty = tid >> 4;
    float c[4][4] = {};
    #pragma unroll 8
    for (int kk = 0; kk < 64; kk++) {
        float a[4], bv[4];
        *(float4*)a  = *(const float4*)&As[kk][ty * 4];
        *(float4*)bv = *(const float4*)&Js[kk][tx * 4];
        #pragma unroll
        for (int i = 0; i < 4; i++)
            #pragma unroll
            for (int j = 0; j < 4; j++)
                c[i][j] = fmaf(a[i], bv[j], c[i][j]);
    }
    #pragma unroll
    for (int i = 0; i < 4; i++) {
        size_t idx = ((size_t)(b * SS + s0 + ty * 4 + i)) * DD + h * HD + tx * 4;
        *(half2*)&Out[idx]     = __floats2half2_rn(c[i][0], c[i][1]);
        *(half2*)&Out[idx + 2] = __floats2half2_rn(c[i][2], c[i][3]);
    }
}

// ---------------- host ----------------
template<typename T> static T* symaddr(const void* s)
{
    void* p = nullptr;
    cudaGetSymbolAddress(&p, s);
    return (T*)p;
}

extern "C" void kernel_launch(void* const* d_in, const int* in_sizes, int n_in,
                              void* d_out, int out_size)
{
    (void)in_sizes; (void)n_in; (void)out_size;

    const float* x   = (const float*)d_in[0];
    const float* wq  = (const float*)d_in[1];
    const float* bq  = (const float*)d_in[2];
    const float* wk  = (const float*)d_in[3];
    const float* bk  = (const float*)d_in[4];
    const float* wv  = (const float*)d_in[5];
    const float* bv  = (const float*)d_in[6];
    const float* wo  = (const float*)d_in[7];
    const float* bo  = (const float*)d_in[8];
    const float* Jat = (const float*)d_in[9];
    const float* lam = (const float*)d_in[10];
    const float* gat = (const float*)d_in[11];
    const float* bat = (const float*)d_in[12];
    const float* W1  = (const float*)d_in[13];
    const float* b1  = (const float*)d_in[14];
    const float* J1  = (const float*)d_in[15];
    const float* g1  = (const float*)d_in[17];
    const float* be1 = (const float*)d_in[18];
    const float* W2  = (const float*)d_in[19];
    const float* b2  = (const float*)d_in[20];
    const float* J2  = (const float*)d_in[21];
    const float* g2  = (const float*)d_in[23];
    const float* be2 = (const float*)d_in[24];
    const float* gf  = (const float*)d_in[25];
    const float* bf  = (const float*)d_in[26];
    float* out = (float*)d_out;

    __half* p_xn  = symaddr<__half>(h_xn);
    __half* p_Q   = symaddr<__half>(h_Q);
    __half* p_K   = symaddr<__half>(h_K);
    __half* p_tK  = symaddr<__half>(h_tK);
    __half* p_V   = symaddr<__half>(h_V);
    __half* p_tQJ = symaddr<__half>(h_tQJ);
    __half* p_ao  = symaddr<__half>(h_ao);
    float*  p_x1  = symaddr<float>(f_x1);
    __half* p_th  = symaddr<__half>(h_th);
    __half* p_hh  = symaddr<__half>(h_hh);
    __half* p_dl  = symaddr<__half>(h_dl);
    __half* p_h1  = symaddr<__half>(h_h1);
    __half* p_th1 = symaddr<__half>(h_th1);
    __half* p_wq  = symaddr<__half>(h_wq);
    __half* p_wk  = symaddr<__half>(h_wk);
    __half* p_wv  = symaddr<__half>(h_wv);
    __half* p_wo  = symaddr<__half>(h_wo);
    __half* p_W1  = symaddr<__half>(h_W1);
    __half* p_J1  = symaddr<__half>(h_J1);
    __half* p_W2  = symaddr<__half>(h_W2);
    __half* p_J2  = symaddr<__half>(h_J2);

    cudaFuncSetAttribute(attn_f16_kernel,
                         cudaFuncAttributeMaxDynamicSharedMemorySize, ATT_SMEM);
    cudaFuncSetAttribute(gemm_qkv_kernel,
                         cudaFuncAttributeMaxDynamicSharedMemorySize, GEMM_SMEM);
    cudaFuncSetAttribute(gemm_f16_kernel<true, true, false>,
                         cudaFuncAttributeMaxDynamicSharedMemorySize, GEMM_SMEM);
    cudaFuncSetAttribute(gemm_f16_kernel<true, false, true>,
                         cudaFuncAttributeMaxDynamicSharedMemorySize, GEMM_SMEM);
    cudaFuncSetAttribute(gemm_f16_kernel<false, false, true>,
                         cudaFuncAttributeMaxDynamicSharedMemorySize, GEMM_SMEM);

    // weight fp32 -> fp16 converts (layout preserved)
    convert_h_kernel<<<(DD*DD/4 + 255)/256, 256>>>(wq, p_wq, DD*DD/4);
    convert_h_kernel<<<(DD*DD/4 + 255)/256, 256>>>(wk, p_wk, DD*DD/4);
    convert_h_kernel<<<(DD*DD/4 + 255)/256, 256>>>(wv, p_wv, DD*DD/4);
    convert_h_kernel<<<(DD*DD/4 + 255)/256, 256>>>(wo, p_wo, DD*DD/4);
    convert_h_kernel<<<(DD*FFD/4 + 255)/256, 256>>>(W1, p_W1, DD*FFD/4);
    convert_h_kernel<<<(DD*FFD/4 + 255)/256, 256>>>(J1, p_J1, DD*FFD/4);
    convert_h_kernel<<<(FFD*DD/4 + 255)/256, 256>>>(W2, p_W2, FFD*DD/4);
    convert_h_kernel<<<(FFD*DD/4 + 255)/256, 256>>>(J2, p_J2, FFD*DD/4);

    // --- attention branch ---
    ln_kernel<<<NT, 256>>>(x, gat, bat, p_xn, nullptr, DD);

    gemm_qkv_kernel<<<dim3(24, NT / 128), 256, GEMM_SMEM>>>(
        p_xn, p_wq, p_wk, p_wv, bq, bk, bv, p_Q, p_K, p_V, p_tK);

    tqj_kernel<<<dim3(BB * HH, SS / 64), 256>>>(p_Q, Jat, p_tQJ);

    attn_f16_kernel<<<dim3(SS / 64, BB * HH), 128, ATT_SMEM>>>(
        p_Q, p_K, p_tK, p_V, p_tQJ, p_ao, lam);

    gemm_f16_kernel<true, true, false><<<dim3(8, NT / 128), 256, GEMM_SMEM>>>(
        p_ao, p_wo, bo, x, p_x1, nullptr, NT, DD, DD);

    // --- QBNN FFN layer 1 ---
    ln_kernel<<<NT, 256>>>(p_x1, gf, bf, p_xn, p_th, DD);

    dim3 gF1(FFD / 128, NT / 128);
    gemm_f16_kernel<true, false, true><<<gF1, 256, GEMM_SMEM>>>(
        p_xn, p_W1, b1, nullptr, nullptr, p_hh, NT, FFD, DD);
    gemm_f16_kernel<false, false, true><<<gF1, 256, GEMM_SMEM>>>(
        p_th, p_J1, nullptr, nullptr, nullptr, p_dl, NT, FFD, DD);

    qln_gelu_kernel<<<NT, 256, FFD * sizeof(float)>>>(
        p_hh, p_dl, g1, be1, nullptr, nullptr, p_h1, p_th1, FFD);

    // --- QBNN FFN layer 2 ---
    dim3 gF2(DD / 128, NT / 128);
    gemm_f16_kernel<true, false, true><<<gF2, 256, GEMM_SMEM>>>(
        p_h1, p_W2, b2, nullptr, nullptr, p_hh, NT, DD, FFD);
    gemm_f16_kernel<false, false, true><<<gF2, 256, GEMM_SMEM>>>(
        p_th1, p_J2, nullptr, nullptr, nullptr, p_dl, NT, DD, FFD);

    qln_gelu_kernel<<<NT, 256, DD * sizeof(float)>>>(
        p_hh, p_dl, g2, be2, p_x1, out, nullptr, nullptr, DD);
}

// round 15
// speedup vs baseline: 1.8314x; 1.0313x over previous
#include <cuda_runtime.h>
#include <cuda_fp16.h>
#include <math.h>
#include <stdint.h>

#define BB   4
#define SS   1024
#define DD   1024
#define HH   16
#define HD   64
#define FFD  4096
#define NT   (BB*SS)
#define INV_SCALE 0.125f
#define LAM_EFF   0.5f

// ---------------- scratch ----------------
__device__ __half h_xn  [NT*DD];
__device__ __half h_Q   [NT*DD];
__device__ __half h_K   [NT*DD];
__device__ __half h_tK  [NT*DD];
__device__ __half h_V   [NT*DD];
__device__ __half h_tQJ [NT*DD];
__device__ __half h_ao  [NT*DD];
__device__ float  f_x1  [NT*DD];
__device__ __half h_th  [NT*DD];
__device__ __half h_hh  [NT*FFD];
__device__ __half h_dl  [NT*FFD];
__device__ __half h_h1  [NT*FFD];
__device__ __half h_th1 [NT*FFD];
// fp16 weights, natural [K][N] layout
__device__ __half h_wq  [DD*DD];
__device__ __half h_wk  [DD*DD];
__device__ __half h_wv  [DD*DD];
__device__ __half h_wo  [DD*DD];
__device__ __half h_W1  [DD*FFD];
__device__ __half h_J1  [DD*FFD];
__device__ __half h_W2  [FFD*DD];
__device__ __half h_J2  [FFD*DD];

// ---------------- helpers ----------------
__device__ __forceinline__ void cp16(uint32_t d, const void* g)
{ asm volatile("cp.async.cg.shared.global [%0], [%1], 16;\n" :: "r"(d), "l"(g)); }
__device__ __forceinline__ void cp_commit()
{ asm volatile("cp.async.commit_group;\n"); }
template<int N> __device__ __forceinline__ void cp_wait()
{ asm volatile("cp.async.wait_group %0;\n" :: "n"(N)); }

__device__ __forceinline__ void mma16(float* c, const uint32_t* a,
                                      uint32_t b0, uint32_t b1)
{
    asm volatile(
        "mma.sync.aligned.m16n8k16.row.col.f32.f16.f16.f32 "
        "{%0,%1,%2,%3},{%4,%5,%6,%7},{%8,%9},{%0,%1,%2,%3};"
        : "+f"(c[0]), "+f"(c[1]), "+f"(c[2]), "+f"(c[3])
        : "r"(a[0]), "r"(a[1]), "r"(a[2]), "r"(a[3]), "r"(b0), "r"(b1));
}
__device__ __forceinline__ void ldsm4(uint32_t* r, uint32_t addr)
{
    asm volatile("ldmatrix.sync.aligned.m8n8.x4.shared.b16 {%0,%1,%2,%3}, [%4];"
                 : "=r"(r[0]), "=r"(r[1]), "=r"(r[2]), "=r"(r[3]) : "r"(addr));
}
__device__ __forceinline__ void ldsm4t(uint32_t* r, uint32_t addr)
{
    asm volatile("ldmatrix.sync.aligned.m8n8.x4.trans.shared.b16 {%0,%1,%2,%3}, [%4];"
                 : "=r"(r[0]), "=r"(r[1]), "=r"(r[2]), "=r"(r[3]) : "r"(addr));
}

// ---------------------------------------------------------------------------
// FP16 GEMM tiling constants (shared by all GEMM kernels)
// A staged [128 m][40 k]; W staged natural [32 k][136 n] + ldmatrix.trans.
// 128x128x32 block, 4-stage cp.async, 8 warps (2M x 4N), m16n8k16.
// ---------------------------------------------------------------------------
#define RSH   40
#define BSTR  136
#define ATILEB (128*RSH*2)
#define BTILEB (32*BSTR*2)
#define STG_B  (ATILEB + BTILEB)
#define NSTG   4
#define GEMM_SMEM (NSTG*STG_B)      // 75776 B

// ---------------------------------------------------------------------------
// Generic GEMM: C = A@W (+bias)(+Res); fp32 or fp16 out. (used for out-proj)
// ---------------------------------------------------------------------------
template<bool BIAS, bool RES, bool HOUT>
__global__ void __launch_bounds__(256, 2) gemm_f16_kernel(
    const __half* __restrict__ A, const __half* __restrict__ W,
    const float* __restrict__ bias, const float* __restrict__ Res,
    float* __restrict__ C, __half* __restrict__ C16,
    int M, int N, int K)
{
    extern __shared__ __half smh[];
    const uint32_t su = (uint32_t)__cvta_generic_to_shared(smh);

    const int tid = threadIdx.x;
    const int bn = blockIdx.x << 7, bm = blockIdx.y << 7;
    const int wid = tid >> 5, lane = tid & 31;
    const int wm = wid & 1, wn = wid >> 1;
    const int gid = lane >> 2, tig = lane & 3;

    float c[4][4][4] = {};

    auto load_stage = [&](int kt) {
        uint32_t ab = su + (kt & 3) * STG_B, bb = ab + ATILEB;
        #pragma unroll
        for (int i = 0; i < 2; i++) {
            int idx = tid + (i << 8);
            int r = idx >> 2, c8 = idx & 3;
            cp16(ab + (r * RSH + c8 * 8) * 2,
                 &A[(size_t)(bm + r) * K + kt * 32 + c8 * 8]);
        }
        #pragma unroll
        for (int i = 0; i < 2; i++) {
            int idx = tid + (i << 8);
            int r = idx >> 4, c8 = idx & 15;
            cp16(bb + (r * BSTR + c8 * 8) * 2,
                 &W[(size_t)(kt * 32 + r) * N + bn + c8 * 8]);
        }
        cp_commit();
    };

    const int KT = K >> 5;
    load_stage(0); load_stage(1); load_stage(2);

    const int t7 = lane & 7;
    const uint32_t aro = ((lane >> 3) & 1) * 8 + t7;
    const uint32_t ak8 = ((lane >> 4) & 1) * 8;
    const uint32_t bko = ((lane >> 3) & 1) * 8 + t7;
    const uint32_t bn8 = ((lane >> 4) & 1) * 8;

    for (int kt = 0; kt < KT; kt++) {
        cp_wait<2>();
        __syncthreads();
        if (kt + 3 < KT) load_stage(kt + 3); else cp_commit();

        uint32_t ab = su + (kt & 3) * STG_B, bb = ab + ATILEB;
        #pragma unroll
        for (int ks = 0; ks < 2; ks++) {
            uint32_t a[4][4], b[2][4];
            #pragma unroll
            for (int mt = 0; mt < 4; mt++)
                ldsm4(a[mt], ab + ((wm * 64 + mt * 16 + aro) * RSH + ks * 16 + ak8) * 2);
            #pragma unroll
            for (int p = 0; p < 2; p++)
                ldsm4t(b[p], bb + ((ks * 16 + bko) * BSTR + wn * 32 + p * 16 + bn8) * 2);
            #pragma unroll
            for (int mt = 0; mt < 4; mt++)
                #pragma unroll
                for (int nt = 0; nt < 4; nt++)
                    mma16(c[mt][nt], a[mt],
                          b[nt >> 1][(nt & 1) * 2], b[nt >> 1][(nt & 1) * 2 + 1]);
        }
    }

    #pragma unroll
    for (int mt = 0; mt < 4; mt++) {
        #pragma unroll
        for (int nt = 0; nt < 4; nt++) {
            int col = bn + wn * 32 + nt * 8 + tig * 2;
            float2 bi = make_float2(0.f, 0.f);
            if (BIAS) bi = *(const float2*)&bias[col];
            #pragma unroll
            for (int hf = 0; hf < 2; hf++) {
                int row = bm + wm * 64 + mt * 16 + gid + hf * 8;
                float vx = c[mt][nt][hf * 2 + 0] + bi.x;
                float vy = c[mt][nt][hf * 2 + 1] + bi.y;
                if (RES) {
                    float2 r = *(const float2*)&Res[(size_t)row * N + col];
                    vx += r.x; vy += r.y;
                }
                if (HOUT)
                    *(half2*)&C16[(size_t)row * N + col] = __floats2half2_rn(vx, vy);
                else
                    *(float2*)&C[(size_t)row * N + col] = make_float2(vx, vy);
            }
        }
    }
}

// ---------------------------------------------------------------------------
// Merged QKV GEMM: one launch, weight/bias/output selected by blockIdx.x>>3.
// ---------------------------------------------------------------------------
__global__ void __launch_bounds__(256, 2) gemm_qkv_kernel(
    const __half* __restrict__ A,
    const __half* __restrict__ Wq, const __half* __restrict__ Wk,
    const __half* __restrict__ Wv,
    const float* __restrict__ bq, const float* __restrict__ bk,
    const float* __restrict__ bv,
    __half* __restrict__ Qo, __half* __restrict__ Ko,
    __half* __restrict__ Vo, __half* __restrict__ tKo)
{
    extern __shared__ __half smh[];
    const uint32_t su = (uint32_t)__cvta_generic_to_shared(smh);

    const int w = blockIdx.x >> 3;
    const __half* W = (w == 0) ? Wq : (w == 1) ? Wk : Wv;
    const float* bias = (w == 0) ? bq : (w == 1) ? bk : bv;
    __half* Out = (w == 0) ? Qo : (w == 1) ? Ko : Vo;

    const int tid = threadIdx.x;
    const int bn = (blockIdx.x & 7) << 7, bm = blockIdx.y << 7;
    const int wid = tid >> 5, lane = tid & 31;
    const int wm = wid & 1, wn = wid >> 1;
    const int gid = lane >> 2, tig = lane & 3;

    float c[4][4][4] = {};

    auto load_stage = [&](int kt) {
        uint32_t ab = su + (kt & 3) * STG_B, bb = ab + ATILEB;
        #pragma unroll
        for (int i = 0; i < 2; i++) {
            int idx = tid + (i << 8);
            int r = idx >> 2, c8 = idx & 3;
            cp16(ab + (r * RSH + c8 * 8) * 2,
                 &A[(size_t)(bm + r) * DD + kt * 32 + c8 * 8]);
        }
        #pragma unroll
        for (int i = 0; i < 2; i++) {
            int idx = tid + (i << 8);
            int r = idx >> 4, c8 = idx & 15;
            cp16(bb + (r * BSTR + c8 * 8) * 2,
                 &W[(size_t)(kt * 32 + r) * DD + bn + c8 * 8]);
        }
        cp_commit();
    };

    load_stage(0); load_stage(1); load_stage(2);

    const int t7 = lane & 7;
    const uint32_t aro = ((lane >> 3) & 1) * 8 + t7;
    const uint32_t ak8 = ((lane >> 4) & 1) * 8;
    const uint32_t bko = ((lane >> 3) & 1) * 8 + t7;
    const uint32_t bn8 = ((lane >> 4) & 1) * 8;

    for (int kt = 0; kt < 32; kt++) {
        cp_wait<2>();
        __syncthreads();
        if (kt + 3 < 32) load_stage(kt + 3); else cp_commit();

        uint32_t ab = su + (kt & 3) * STG_B, bb = ab + ATILEB;
        #pragma unroll
        for (int ks = 0; ks < 2; ks++) {
            uint32_t a[4][4], b[2][4];
            #pragma unroll
            for (int mt = 0; mt < 4; mt++)
                ldsm4(a[mt], ab + ((wm * 64 + mt * 16 + aro) * RSH + ks * 16 + ak8) * 2);
            #pragma unroll
            for (int p = 0; p < 2; p++)
                ldsm4t(b[p], bb + ((ks * 16 + bko) * BSTR + wn * 32 + p * 16 + bn8) * 2);
            #pragma unroll
            for (int mt = 0; mt < 4; mt++)
                #pragma unroll
                for (int nt = 0; nt < 4; nt++)
                    mma16(c[mt][nt], a[mt],
                          b[nt >> 1][(nt & 1) * 2], b[nt >> 1][(nt & 1) * 2 + 1]);
        }
    }

    #pragma unroll
    for (int mt = 0; mt < 4; mt++) {
        #pragma unroll
        for (int nt = 0; nt < 4; nt++) {
            int col = bn + wn * 32 + nt * 8 + tig * 2;
            float2 bi = *(const float2*)&bias[col];
            #pragma unroll
            for (int hf = 0; hf < 2; hf++) {
                int row = bm + wm * 64 + mt * 16 + gid + hf * 8;
                float vx = c[mt][nt][hf * 2 + 0] + bi.x;
                float vy = c[mt][nt][hf * 2 + 1] + bi.y;
                *(half2*)&Out[(size_t)row * DD + col] = __floats2half2_rn(vx, vy);
                if (w == 1)
                    *(half2*)&tKo[(size_t)row * DD + col] =
                        __floats2half2_rn(tanhf(vx), tanhf(vy));
            }
        }
    }
}

// ---------------------------------------------------------------------------
// Merged FF dual GEMM: even blocks compute A1@W+bias -> O1 (h_tilde),
// odd blocks compute A2@J -> O2 (delta). One launch per QBNN layer.
// ---------------------------------------------------------------------------
__global__ void __launch_bounds__(256, 2) gemm_ffdual_kernel(
    const __half* __restrict__ A1, const __half* __restrict__ A2,
    const __half* __restrict__ W,  const __half* __restrict__ J,
    const float* __restrict__ bias,
    __half* __restrict__ O1, __half* __restrict__ O2,
    int N, int K)
{
    extern __shared__ __half smh[];
    const uint32_t su = (uint32_t)__cvta_generic_to_shared(smh);

    const int sel = blockIdx.x & 1;
    const __half* A  = sel ? A2 : A1;
    const __half* Wm = sel ? J : W;
    __half* Out = sel ? O2 : O1;

    const int tid = threadIdx.x;
    const int bn = (blockIdx.x >> 1) << 7, bm = blockIdx.y << 7;
    const int wid = tid >> 5, lane = tid & 31;
    const int wm = wid & 1, wn = wid >> 1;
    const int gid = lane >> 2, tig = lane & 3;

    float c[4][4][4] = {};

    auto load_stage = [&](int kt) {
        uint32_t ab = su + (kt & 3) * STG_B, bb = ab + ATILEB;
        #pragma unroll
        for (int i = 0; i < 2; i++) {
            int idx = tid + (i << 8);
            int r = idx >> 2, c8 = idx & 3;
            cp16(ab + (r * RSH + c8 * 8) * 2,
                 &A[(size_t)(bm + r) * K + kt * 32 + c8 * 8]);
        }
        #pragma unroll
        for (int i = 0; i < 2; i++) {
            int idx = tid + (i << 8);
            int r = idx >> 4, c8 = idx & 15;
            cp16(bb + (r * BSTR + c8 * 8) * 2,
                 &Wm[(size_t)(kt * 32 + r) * N + bn + c8 * 8]);
        }
        cp_commit();
    };

    const int KT = K >> 5;
    load_stage(0); load_stage(1); load_stage(2);

    const int t7 = lane & 7;
    const uint32_t aro = ((lane >> 3) & 1) * 8 + t7;
    const uint32_t ak8 = ((lane >> 4) & 1) * 8;
    const uint32_t bko = ((lane >> 3) & 1) * 8 + t7;
    const uint32_t bn8 = ((lane >> 4) & 1) * 8;

    for (int kt = 0; kt < KT; kt++) {
        cp_wait<2>();
        __syncthreads();
        if (kt + 3 < KT) load_stage(kt + 3); else cp_commit();

        uint32_t ab = su + (kt & 3) * STG_B, bb = ab + ATILEB;
        #pragma unroll
        for (int ks = 0; ks < 2; ks++) {
            uint32_t a[4][4], b[2][4];
            #pragma unroll
            for (int mt = 0; mt < 4; mt++)
                ldsm4(a[mt], ab + ((wm * 64 + mt * 16 + aro) * RSH + ks * 16 + ak8) * 2);
            #pragma unroll
            for (int p = 0; p < 2; p++)
                ldsm4t(b[p], bb + ((ks * 16 + bko) * BSTR + wn * 32 + p * 16 + bn8) * 2);
            #pragma unroll
            for (int mt = 0; mt < 4; mt++)
                #pragma unroll
                for (int nt = 0; nt < 4; nt++)
                    mma16(c[mt][nt], a[mt],
                          b[nt >> 1][(nt & 1) * 2], b[nt >> 1][(nt & 1) * 2 + 1]);
        }
    }

    #pragma unroll
    for (int mt = 0; mt < 4; mt++) {
        #pragma unroll
        for (int nt = 0; nt < 4; nt++) {
            int col = bn + wn * 32 + nt * 8 + tig * 2;
            float2 bi = make_float2(0.f, 0.f);
            if (sel == 0) bi = *(const float2*)&bias[col];
            #pragma unroll
            for (int hf = 0; hf < 2; hf++) {
                int row = bm + wm * 64 + mt * 16 + gid + hf * 8;
                float vx = c[mt][nt][hf * 2 + 0] + bi.x;
                float vy = c[mt][nt][hf * 2 + 1] + bi.y;
                *(half2*)&Out[(size_t)row * N + col] = __floats2half2_rn(vx, vy);
            }
        }
    }
}

// ---------------- fused fp32 -> fp16 convert of ALL weights (one launch) ----------
#define CVT_S1 (DD*DD/4)     // 262144 = 2^18 float4 per small weight
#define CVT_S2 (DD*FFD/4)    // 1048576 = 2^20 float4 per big weight
#define CVT_TOTAL4 (4*CVT_S1 + 4*CVT_S2)

__global__ void __launch_bounds__(256) convert_all_kernel(
    const float* __restrict__ wq, const float* __restrict__ wk,
    const float* __restrict__ wv, const float* __restrict__ wo,
    const float* __restrict__ W1, const float* __restrict__ J1,
    const float* __restrict__ W2, const float* __restrict__ J2,
    __half* dwq, __half* dwk, __half* dwv, __half* dwo,
    __half* dW1, __half* dJ1, __half* dW2, __half* dJ2)
{
    int i = blockIdx.x * 256 + threadIdx.x;
    if (i >= CVT_TOTAL4) return;
    const float* src; __half* dst; int off;
    if (i < 4 * CVT_S1) {
        int w = i >> 18; off = i & (CVT_S1 - 1);
        src = (w == 0) ? wq : (w == 1) ? wk : (w == 2) ? wv : wo;
        dst = (w == 0) ? dwq : (w == 1) ? dwk : (w == 2) ? dwv : dwo;
    } else {
        int j = i - 4 * CVT_S1;
        int w = j >> 20; off = j & (CVT_S2 - 1);
        src = (w == 0) ? W1 : (w == 1) ? J1 : (w == 2) ? W2 : J2;
        dst = (w == 0) ? dW1 : (w == 1) ? dJ1 : (w == 2) ? dW2 : dJ2;
    }
    float4 v = *(const float4*)&src[(size_t)off * 4];
    *(half2*)&dst[(size_t)off * 4]     = __floats2half2_rn(v.x, v.y);
    *(half2*)&dst[(size_t)off * 4 + 2] = __floats2half2_rn(v.z, v.w);
}

// ---------------------------------------------------------------------------
// FP16 tensor-core flash attention (proven)
// ---------------------------------------------------------------------------
#define AST 72
#define ATILE (64*AST)
#define ATT_SMEM (6*ATILE*2)

__global__ void __launch_bounds__(128) attn_f16_kernel(
    const __half* __restrict__ Q,  const __half* __restrict__ K,
    const __half* __restrict__ TK, const __half* __restrict__ V,
    const __half* __restrict__ TQJ, __half* __restrict__ O,
    const float* __restrict__ lam_p)
{
    extern __shared__ __half smh[];
    const uint32_t su = (uint32_t)__cvta_generic_to_shared(smh);
    const uint32_t Qb = su;
    const uint32_t Tb = Qb + ATILE * 2;
    const uint32_t Pb = Tb + ATILE * 2;
    const uint32_t Kb = Pb + ATILE * 2;
    const uint32_t Gb = Kb + ATILE * 2;
    const uint32_t Vb = Gb + ATILE * 2;
    __half* Ps = smh + 2 * ATILE;

    const int tid = threadIdx.x;
    const int wid = tid >> 5, lane = tid & 31;
    const int gid = lane >> 2, tig = lane & 3;
    const int mrow = wid * 16;
    const int bh = blockIdx.y, b = bh >> 4, h = bh & 15;
    const int q0 = blockIdx.x << 6;
    const float lam = __ldg(lam_p);

    const int t7 = lane & 7;
    const uint32_t aro = ((lane >> 3) & 1) * 8 + t7, ak8 = ((lane >> 4) & 1) * 8;
    const uint32_t bro = ((lane >> 4) & 1) * 8 + t7, bk8 = ((lane >> 3) & 1) * 8;
    const uint32_t vko = ((lane >> 3) & 1) * 8 + t7, vn8 = ((lane >> 4) & 1) * 8;

    for (int i = tid; i < 512; i += 128) {
        int r = i >> 3, c8 = i & 7;
        size_t g = ((size_t)(b * SS + q0 + r)) * DD + h * HD + c8 * 8;
        cp16(Qb + (r * AST + c8 * 8) * 2, &Q[g]);
        cp16(Tb + (r * AST + c8 * 8) * 2, &TQJ[g]);
    }
    cp_commit();

    float m0 = -1e30f, m1 = -1e30f, l0 = 0.f, l1 = 0.f;
    float o[8][4] = {};

    for (int k0 = 0; k0 < SS; k0 += 64) {
        __syncthreads();
        for (int i = tid; i < 512; i += 128) {
            int r = i >> 3, c8 = i & 7;
            size_t g = ((size_t)(b * SS + k0 + r)) * DD + h * HD + c8 * 8;
            uint32_t off = (r * AST + c8 * 8) * 2;
            cp16(Kb + off, &K[g]);
            cp16(Gb + off, &TK[g]);
            cp16(Vb + off, &V[g]);
        }
        cp_commit();
        cp_wait<0>();
        __syncthreads();

        float cs[8][4] = {}, cd[8][4] = {};
        #pragma unroll
        for (int ks = 0; ks < 4; ks++) {
            uint32_t aq[4], at[4], bk[4][4], bt[4][4];
            ldsm4(aq, Qb + ((mrow + aro) * AST + ks * 16 + ak8) * 2);
            ldsm4(at, Tb + ((mrow + aro) * AST + ks * 16 + ak8) * 2);
            #pragma unroll
            for (int p = 0; p < 4; p++) {
                uint32_t off = ((p * 16 + bro) * AST + ks * 16 + bk8) * 2;
                ldsm4(bk[p], Kb + off);
                ldsm4(bt[p], Gb + off);
            }
            #pragma unroll
            for (int nt = 0; nt < 8; nt++) {
                mma16(cs[nt], aq, bk[nt >> 1][(nt & 1) * 2], bk[nt >> 1][(nt & 1) * 2 + 1]);
                mma16(cd[nt], at, bt[nt >> 1][(nt & 1) * 2], bt[nt >> 1][(nt & 1) * 2 + 1]);
            }
        }

        float s[8][4];
        float mx0 = -1e30f, mx1 = -1e30f;
        #pragma unroll
        for (int nt = 0; nt < 8; nt++) {
            #pragma unroll
            for (int e = 0; e < 4; e++)
                s[nt][e] = fmaf(lam, cd[nt][e], cs[nt][e] * INV_SCALE);
            mx0 = fmaxf(mx0, fmaxf(s[nt][0], s[nt][1]));
            mx1 = fmaxf(mx1, fmaxf(s[nt][2], s[nt][3]));
        }
        mx0 = fmaxf(mx0, __shfl_xor_sync(0xffffffffu, mx0, 1));
        mx0 = fmaxf(mx0, __shfl_xor_sync(0xffffffffu, mx0, 2));
        mx1 = fmaxf(mx1, __shfl_xor_sync(0xffffffffu, mx1, 1));
        mx1 = fmaxf(mx1, __shfl_xor_sync(0xffffffffu, mx1, 2));
        float mn0 = fmaxf(m0, mx0), mn1 = fmaxf(m1, mx1);
        float corr0 = __expf(m0 - mn0), corr1 = __expf(m1 - mn1);
        m0 = mn0; m1 = mn1;
        l0 *= corr0; l1 *= corr1;

        float sum0 = 0.f, sum1 = 0.f;
        #pragma unroll
        for (int nt = 0; nt < 8; nt++) {
            float p00 = __expf(s[nt][0] - mn0);
            float p01 = __expf(s[nt][1] - mn0);
            float p10 = __expf(s[nt][2] - mn1);
            float p11 = __expf(s[nt][3] - mn1);
            sum0 += p00 + p01; sum1 += p10 + p11;
            int col = nt * 8 + tig * 2;
            *(half2*)&Ps[(mrow + gid    ) * AST + col] = __floats2half2_rn(p00, p01);
            *(half2*)&Ps[(mrow + gid + 8) * AST + col] = __floats2half2_rn(p10, p11);
        }
        sum0 += __shfl_xor_sync(0xffffffffu, sum0, 1);
        sum0 += __shfl_xor_sync(0xffffffffu, sum0, 2);
        sum1 += __shfl_xor_sync(0xffffffffu, sum1, 1);
        sum1 += __shfl_xor_sync(0xffffffffu, sum1, 2);
        l0 += sum0; l1 += sum1;

        #pragma unroll
        for (int nt = 0; nt < 8; nt++) {
            o[nt][0] *= corr0; o[nt][1] *= corr0;
            o[nt][2] *= corr1; o[nt][3] *= corr1;
        }
        __syncwarp();

        #pragma unroll
        for (int ks = 0; ks < 4; ks++) {
            uint32_t ap[4], bv[4][4];
            ldsm4(ap, Pb + ((mrow + aro) * AST + ks * 16 + ak8) * 2);
            #pragma unroll
            for (int p = 0; p < 4; p++)
                ldsm4t(bv[p], Vb + ((ks * 16 + vko) * AST + p * 16 + vn8) * 2);
            #pragma unroll
            for (int nt = 0; nt < 8; nt++)
                mma16(o[nt], ap, bv[nt >> 1][(nt & 1) * 2], bv[nt >> 1][(nt & 1) * 2 + 1]);
        }
        __syncwarp();
    }

    float inv0 = 1.f / l0, inv1 = 1.f / l1;
    int row0 = q0 + mrow + gid, row1 = row0 + 8;
    #pragma unroll
    for (int nt = 0; nt < 8; nt++) {
        int col = nt * 8 + tig * 2;
        *(half2*)&O[((size_t)(b * SS + row0)) * DD + h * HD + col] =
            __floats2half2_rn(o[nt][0] * inv0, o[nt][1] * inv0);
        *(half2*)&O[((size_t)(b * SS + row1)) * DD + h * HD + col] =
            __floats2half2_rn(o[nt][2] * inv1, o[nt][3] * inv1);
    }
}

// ---------------- LayerNorm: fp32 in, fp16 out (+opt fp16 tanh out) ----------------
__global__ void __launch_bounds__(256) ln_kernel(
    const float* __restrict__ X, const float* __restrict__ g,
    const float* __restrict__ b, __half* __restrict__ Y,
    __half* __restrict__ YT, int N)
{
    int row = blockIdx.x;
    const float* x = X + (size_t)row * N;
    float s = 0.f, s2 = 0.f;
    for (int i = threadIdx.x; i < N; i += 256) {
        float v = x[i];
        s += v; s2 = fmaf(v, v, s2);
    }
    __shared__ float sh[64];
    for (int o = 16; o > 0; o >>= 1) {
        s  += __shfl_down_sync(0xffffffffu, s,  o);
        s2 += __shfl_down_sync(0xffffffffu, s2, o);
    }
    int wid = threadIdx.x >> 5, lane = threadIdx.x & 31;
    if (lane == 0) { sh[wid] = s; sh[wid + 32] = s2; }
    __syncthreads();
    if (threadIdx.x == 0) {
        float ts = 0.f, ts2 = 0.f;
        for (int w = 0; w < 8; w++) { ts += sh[w]; ts2 += sh[w + 32]; }
        float mu = ts / N, var = ts2 / N - mu * mu;
        sh[0] = mu; sh[1] = rsqrtf(var + 1e-5f);
    }
    __syncthreads();
    float mu = sh[0], rstd = sh[1];
    for (int i = threadIdx.x; i < N; i += 256) {
        float v = (x[i] - mu) * rstd * g[i] + b[i];
        Y[(size_t)row * N + i] = __float2half(v);
        if (YT) YT[(size_t)row * N + i] = __float2half(tanhf(v));
    }
}

// ---------------- QBNN combine + LN + GELU (fp16 ht/dlt in) ----------------
__global__ void __launch_bounds__(256) qln_gelu_kernel(
    const __half* __restrict__ HT, const __half* __restrict__ DLT,
    const float* __restrict__ g,  const float* __restrict__ b,
    const float* __restrict__ Res, float* __restrict__ Yf,
    __half* __restrict__ Yh, __half* __restrict__ Yth, int N)
{
    extern __shared__ float rowbuf[];
    __shared__ float sh[64];
    int row = blockIdx.x;
    size_t base = (size_t)row * N;

    float s = 0.f, s2 = 0.f;
    for (int i = threadIdx.x; i < N; i += 256) {
        float ht = __half2float(HT[base + i]);
        float dl = __half2float(DLT[base + i]);
        float v  = fmaf(LAM_EFF * dl, tanhf(ht), ht);
        rowbuf[i] = v;
        s += v; s2 = fmaf(v, v, s2);
    }
    for (int o = 16; o > 0; o >>= 1) {
        s  += __shfl_down_sync(0xffffffffu, s,  o);
        s2 += __shfl_down_sync(0xffffffffu, s2, o);
    }
    int wid = threadIdx.x >> 5, lane = threadIdx.x & 31;
    if (lane == 0) { sh[wid] = s; sh[wid + 32] = s2; }
    __syncthreads();
    if (threadIdx.x == 0) {
        float ts = 0.f, ts2 = 0.f;
        for (int w = 0; w < 8; w++) { ts += sh[w]; ts2 += sh[w + 32]; }
        float mu = ts / N, var = ts2 / N - mu * mu;
        sh[0] = mu; sh[1] = rsqrtf(var + 1e-5f);
    }
    __syncthreads();
    float mu = sh[0], rstd = sh[1];
    for (int i = threadIdx.x; i < N; i += 256) {
        float v  = (rowbuf[i] - mu) * rstd * g[i] + b[i];
        float ge = v * normcdff(v);
        float o  = Res ? Res[base + i] + ge : ge;
        if (Yf)  Yf[base + i] = o;
        if (Yh)  Yh[base + i] = __float2half(o);
        if (Yth) Yth[base + i] = __float2half(tanhf(o));
    }
}

// ---------------- tQJ: per (b,h) tanh(Q)@J[h]; fp16 in/out, fp32 math ----------
__global__ void __launch_bounds__(256) tqj_kernel(
    const __half* __restrict__ Q, const float* __restrict__ J,
    __half* __restrict__ Out)
{
    __shared__ __align__(16) float As[64][64];
    __shared__ __align__(16) float Js[64][64];
    int tid = threadIdx.x;
    int bh = blockIdx.x; int b = bh >> 4, h = bh & 15;
    int s0 = blockIdx.y << 6;

    #pragma unroll
    for (int i = 0; i < 4; i++) {
        int idx = tid + (i << 8);
        int r = idx >> 4, kq = (idx & 15) << 2;
        const __half* qp = &Q[((size_t)(b * SS + s0 + r)) * DD + h * HD + kq];
        As[kq + 0][r] = tanhf(__half2float(qp[0]));
        As[kq + 1][r] = tanhf(__half2float(qp[1]));
        As[kq + 2][r] = tanhf(__half2float(qp[2]));
        As[kq + 3][r] = tanhf(__half2float(qp[3]));
        ((float4*)Js)[idx] = *(const float4*)&J[(size_t)h * HD * HD + idx * 4];
    }
    __syncthreads();

    int tx = tid & 15, ty = tid >> 4;
    float c[4][4] = {};
    #pragma unroll 8
    for (int kk = 0; kk < 64; kk++) {
        float a[4], bv[4];
        *(float4*)a  = *(const float4*)&As[kk][ty * 4];
        *(float4*)bv = *(const float4*)&Js[kk][tx * 4];
        #pragma unroll
        for (int i = 0; i < 4; i++)
            #pragma unroll
            for (int j = 0; j < 4; j++)
                c[i][j] = fmaf(a[i], bv[j], c[i][j]);
    }
    #pragma unroll
    for (int i = 0; i < 4; i++) {
        size_t idx = ((size_t)(b * SS + s0 + ty * 4 + i)) * DD + h * HD + tx * 4;
        *(half2*)&Out[idx]     = __floats2half2_rn(c[i][0], c[i][1]);
        *(half2*)&Out[idx + 2] = __floats2half2_rn(c[i][2], c[i][3]);
    }
}

// ---------------- host ----------------
template<typename T> static T* symaddr(const void* s)
{
    void* p = nullptr;
    cudaGetSymbolAddress(&p, s);
    return (T*)p;
}

extern "C" void kernel_launch(void* const* d_in, const int* in_sizes, int n_in,
                              void* d_out, int out_size)
{
    (void)in_sizes; (void)n_in; (void)out_size;

    const float* x   = (const float*)d_in[0];
    const float* wq  = (const float*)d_in[1];
    const float* bq  = (const float*)d_in[2];
    const float* wk  = (const float*)d_in[3];
    const float* bk  = (const float*)d_in[4];
    const float* wv  = (const float*)d_in[5];
    const float* bv  = (const float*)d_in[6];
    const float* wo  = (const float*)d_in[7];
    const float* bo  = (const float*)d_in[8];
    const float* Jat = (const float*)d_in[9];
    const float* lam = (const float*)d_in[10];
    const float* gat = (const float*)d_in[11];
    const float* bat = (const float*)d_in[12];
    const float* W1  = (const float*)d_in[13];
    const float* b1  = (const float*)d_in[14];
    const float* J1  = (const float*)d_in[15];
    const float* g1  = (const float*)d_in[17];
    const float* be1 = (const float*)d_in[18];
    const float* W2  = (const float*)d_in[19];
    const float* b2  = (const float*)d_in[20];
    const float* J2  = (const float*)d_in[21];
    const float* g2  = (const float*)d_in[23];
    const float* be2 = (const float*)d_in[24];
    const float* gf  = (const float*)d_in[25];
    const float* bf  = (const float*)d_in[26];
    float* out = (float*)d_out;

    __half* p_xn  = symaddr<__half>(h_xn);
    __half* p_Q   = symaddr<__half>(h_Q);
    __half* p_K   = symaddr<__half>(h_K);
    __half* p_tK  = symaddr<__half>(h_tK);
    __half* p_V   = symaddr<__half>(h_V);
    __half* p_tQJ = symaddr<__half>(h_tQJ);
    __half* p_ao  = symaddr<__half>(h_ao);
    float*  p_x1  = symaddr<float>(f_x1);
    __half* p_th  = symaddr<__half>(h_th);
    __half* p_hh  = symaddr<__half>(h_hh);
    __half* p_dl  = symaddr<__half>(h_dl);
    __half* p_h1  = symaddr<__half>(h_h1);
    __half* p_th1 = symaddr<__half>(h_th1);
    __half* p_wq  = symaddr<__half>(h_wq);
    __half* p_wk  = symaddr<__half>(h_wk);
    __half* p_wv  = symaddr<__half>(h_wv);
    __half* p_wo  = symaddr<__half>(h_wo);
    __half* p_W1  = symaddr<__half>(h_W1);
    __half* p_J1  = symaddr<__half>(h_J1);
    __half* p_W2  = symaddr<__half>(h_W2);
    __half* p_J2  = symaddr<__half>(h_J2);

    cudaFuncSetAttribute(attn_f16_kernel,
                         cudaFuncAttributeMaxDynamicSharedMemorySize, ATT_SMEM);
    cudaFuncSetAttribute(gemm_qkv_kernel,
                         cudaFuncAttributeMaxDynamicSharedMemorySize, GEMM_SMEM);
    cudaFuncSetAttribute(gemm_ffdual_kernel,
                         cudaFuncAttributeMaxDynamicSharedMemorySize, GEMM_SMEM);
    cudaFuncSetAttribute(gemm_f16_kernel<true, true, false>,
                         cudaFuncAttributeMaxDynamicSharedMemorySize, GEMM_SMEM);

    // fused weight fp32 -> fp16 convert (one launch)
    convert_all_kernel<<<CVT_TOTAL4 / 256, 256>>>(
        wq, wk, wv, wo, W1, J1, W2, J2,
        p_wq, p_wk, p_wv, p_wo, p_W1, p_J1, p_W2, p_J2);

    // --- attention branch ---
    ln_kernel<<<NT, 256>>>(x, gat, bat, p_xn, nullptr, DD);

    gemm_qkv_kernel<<<dim3(24, NT / 128), 256, GEMM_SMEM>>>(
        p_xn, p_wq, p_wk, p_wv, bq, bk, bv, p_Q, p_K, p_V, p_tK);

    tqj_kernel<<<dim3(BB * HH, SS / 64), 256>>>(p_Q, Jat, p_tQJ);

    attn_f16_kernel<<<dim3(SS / 64, BB * HH), 128, ATT_SMEM>>>(
        p_Q, p_K, p_tK, p_V, p_tQJ, p_ao, lam);

    gemm_f16_kernel<true, true, false><<<dim3(8, NT / 128), 256, GEMM_SMEM>>>(
        p_ao, p_wo, bo, x, p_x1, nullptr, NT, DD, DD);

    // --- QBNN FFN layer 1 (merged dual GEMM) ---
    ln_kernel<<<NT, 256>>>(p_x1, gf, bf, p_xn, p_th, DD);

    gemm_ffdual_kernel<<<dim3(2 * FFD / 128, NT / 128), 256, GEMM_SMEM>>>(
        p_xn, p_th, p_W1, p_J1, b1, p_hh, p_dl, FFD, DD);

    qln_gelu_kernel<<<NT, 256, FFD * sizeof(float)>>>(
        p_hh, p_dl, g1, be1, nullptr, nullptr, p_h1, p_th1, FFD);

    // --- QBNN FFN layer 2 (merged dual GEMM) ---
    gemm_ffdual_kernel<<<dim3(2 * DD / 128, NT / 128), 256, GEMM_SMEM>>>(
        p_h1, p_th1, p_W2, p_J2, b2, p_hh, p_dl, DD, FFD);

    qln_gelu_kernel<<<NT, 256, DD * sizeof(float)>>>(
        p_hh, p_dl, g2, be2, p_x1, out, nullptr, nullptr, DD);
}

// round 16
// speedup vs baseline: 1.8976x; 1.0361x over previous
#include <cuda_runtime.h>
#include <cuda_fp16.h>
#include <math.h>
#include <stdint.h>

#define BB   4
#define SS   1024
#define DD   1024
#define HH   16
#define HD   64
#define FFD  4096
#define NT   (BB*SS)
#define INV_SCALE 0.125f
#define LAM_EFF   0.5f

// ---------------- scratch ----------------
__device__ __half h_xn  [NT*DD];
__device__ __half h_Q   [NT*DD];
__device__ __half h_K   [NT*DD];
__device__ __half h_tK  [NT*DD];
__device__ __half h_V   [NT*DD];
__device__ __half h_ao  [NT*DD];
__device__ float  f_x1  [NT*DD];
__device__ __half h_th  [NT*DD];
__device__ __half h_hh  [NT*FFD];
__device__ __half h_dl  [NT*FFD];
__device__ __half h_h1  [NT*FFD];
__device__ __half h_th1 [NT*FFD];
// fp16 weights, natural [K][N] layout
__device__ __half h_wq  [DD*DD];
__device__ __half h_wk  [DD*DD];
__device__ __half h_wv  [DD*DD];
__device__ __half h_wo  [DD*DD];
__device__ __half h_W1  [DD*FFD];
__device__ __half h_J1  [DD*FFD];
__device__ __half h_W2  [FFD*DD];
__device__ __half h_J2  [FFD*DD];

// ---------------- helpers ----------------
__device__ __forceinline__ void cp16(uint32_t d, const void* g)
{ asm volatile("cp.async.cg.shared.global [%0], [%1], 16;\n" :: "r"(d), "l"(g)); }
__device__ __forceinline__ void cp_commit()
{ asm volatile("cp.async.commit_group;\n"); }
template<int N> __device__ __forceinline__ void cp_wait()
{ asm volatile("cp.async.wait_group %0;\n" :: "n"(N)); }

__device__ __forceinline__ void mma16(float* c, const uint32_t* a,
                                      uint32_t b0, uint32_t b1)
{
    asm volatile(
        "mma.sync.aligned.m16n8k16.row.col.f32.f16.f16.f32 "
        "{%0,%1,%2,%3},{%4,%5,%6,%7},{%8,%9},{%0,%1,%2,%3};"
        : "+f"(c[0]), "+f"(c[1]), "+f"(c[2]), "+f"(c[3])
        : "r"(a[0]), "r"(a[1]), "r"(a[2]), "r"(a[3]), "r"(b0), "r"(b1));
}
__device__ __forceinline__ void ldsm4(uint32_t* r, uint32_t addr)
{
    asm volatile("ldmatrix.sync.aligned.m8n8.x4.shared.b16 {%0,%1,%2,%3}, [%4];"
                 : "=r"(r[0]), "=r"(r[1]), "=r"(r[2]), "=r"(r[3]) : "r"(addr));
}
__device__ __forceinline__ void ldsm4t(uint32_t* r, uint32_t addr)
{
    asm volatile("ldmatrix.sync.aligned.m8n8.x4.trans.shared.b16 {%0,%1,%2,%3}, [%4];"
                 : "=r"(r[0]), "=r"(r[1]), "=r"(r[2]), "=r"(r[3]) : "r"(addr));
}

// ---------------------------------------------------------------------------
// FP16 GEMM tiling constants
// ---------------------------------------------------------------------------
#define RSH   40
#define BSTR  136
#define ATILEB (128*RSH*2)
#define BTILEB (32*BSTR*2)
#define STG_B  (ATILEB + BTILEB)
#define NSTG   4
#define GEMM_SMEM (NSTG*STG_B)      // 75776 B

// ---------------------------------------------------------------------------
// Generic GEMM: C = A@W (+bias)(+Res); fp32 or fp16 out. (used for out-proj)
// ---------------------------------------------------------------------------
template<bool BIAS, bool RES, bool HOUT>
__global__ void __launch_bounds__(256, 2) gemm_f16_kernel(
    const __half* __restrict__ A, const __half* __restrict__ W,
    const float* __restrict__ bias, const float* __restrict__ Res,
    float* __restrict__ C, __half* __restrict__ C16,
    int M, int N, int K)
{
    extern __shared__ __half smh[];
    const uint32_t su = (uint32_t)__cvta_generic_to_shared(smh);

    const int tid = threadIdx.x;
    const int bn = blockIdx.x << 7, bm = blockIdx.y << 7;
    const int wid = tid >> 5, lane = tid & 31;
    const int wm = wid & 1, wn = wid >> 1;
    const int gid = lane >> 2, tig = lane & 3;

    float c[4][4][4] = {};

    auto load_stage = [&](int kt) {
        uint32_t ab = su + (kt & 3) * STG_B, bb = ab + ATILEB;
        #pragma unroll
        for (int i = 0; i < 2; i++) {
            int idx = tid + (i << 8);
            int r = idx >> 2, c8 = idx & 3;
            cp16(ab + (r * RSH + c8 * 8) * 2,
                 &A[(size_t)(bm + r) * K + kt * 32 + c8 * 8]);
        }
        #pragma unroll
        for (int i = 0; i < 2; i++) {
            int idx = tid + (i << 8);
            int r = idx >> 4, c8 = idx & 15;
            cp16(bb + (r * BSTR + c8 * 8) * 2,
                 &W[(size_t)(kt * 32 + r) * N + bn + c8 * 8]);
        }
        cp_commit();
    };

    const int KT = K >> 5;
    load_stage(0); load_stage(1); load_stage(2);

    const int t7 = lane & 7;
    const uint32_t aro = ((lane >> 3) & 1) * 8 + t7;
    const uint32_t ak8 = ((lane >> 4) & 1) * 8;
    const uint32_t bko = ((lane >> 3) & 1) * 8 + t7;
    const uint32_t bn8 = ((lane >> 4) & 1) * 8;

    for (int kt = 0; kt < KT; kt++) {
        cp_wait<2>();
        __syncthreads();
        if (kt + 3 < KT) load_stage(kt + 3); else cp_commit();

        uint32_t ab = su + (kt & 3) * STG_B, bb = ab + ATILEB;
        #pragma unroll
        for (int ks = 0; ks < 2; ks++) {
            uint32_t a[4][4], b[2][4];
            #pragma unroll
            for (int mt = 0; mt < 4; mt++)
                ldsm4(a[mt], ab + ((wm * 64 + mt * 16 + aro) * RSH + ks * 16 + ak8) * 2);
            #pragma unroll
            for (int p = 0; p < 2; p++)
                ldsm4t(b[p], bb + ((ks * 16 + bko) * BSTR + wn * 32 + p * 16 + bn8) * 2);
            #pragma unroll
            for (int mt = 0; mt < 4; mt++)
                #pragma unroll
                for (int nt = 0; nt < 4; nt++)
                    mma16(c[mt][nt], a[mt],
                          b[nt >> 1][(nt & 1) * 2], b[nt >> 1][(nt & 1) * 2 + 1]);
        }
    }

    #pragma unroll
    for (int mt = 0; mt < 4; mt++) {
        #pragma unroll
        for (int nt = 0; nt < 4; nt++) {
            int col = bn + wn * 32 + nt * 8 + tig * 2;
            float2 bi = make_float2(0.f, 0.f);
            if (BIAS) bi = *(const float2*)&bias[col];
            #pragma unroll
            for (int hf = 0; hf < 2; hf++) {
                int row = bm + wm * 64 + mt * 16 + gid + hf * 8;
                float vx = c[mt][nt][hf * 2 + 0] + bi.x;
                float vy = c[mt][nt][hf * 2 + 1] + bi.y;
                if (RES) {
                    float2 r = *(const float2*)&Res[(size_t)row * N + col];
                    vx += r.x; vy += r.y;
                }
                if (HOUT)
                    *(half2*)&C16[(size_t)row * N + col] = __floats2half2_rn(vx, vy);
                else
                    *(float2*)&C[(size_t)row * N + col] = make_float2(vx, vy);
            }
        }
    }
}

// ---------------------------------------------------------------------------
// Merged QKV GEMM
// ---------------------------------------------------------------------------
__global__ void __launch_bounds__(256, 2) gemm_qkv_kernel(
    const __half* __restrict__ A,
    const __half* __restrict__ Wq, const __half* __restrict__ Wk,
    const __half* __restrict__ Wv,
    const float* __restrict__ bq, const float* __restrict__ bk,
    const float* __restrict__ bv,
    __half* __restrict__ Qo, __half* __restrict__ Ko,
    __half* __restrict__ Vo, __half* __restrict__ tKo)
{
    extern __shared__ __half smh[];
    const uint32_t su = (uint32_t)__cvta_generic_to_shared(smh);

    const int w = blockIdx.x >> 3;
    const __half* W = (w == 0) ? Wq : (w == 1) ? Wk : Wv;
    const float* bias = (w == 0) ? bq : (w == 1) ? bk : bv;
    __half* Out = (w == 0) ? Qo : (w == 1) ? Ko : Vo;

    const int tid = threadIdx.x;
    const int bn = (blockIdx.x & 7) << 7, bm = blockIdx.y << 7;
    const int wid = tid >> 5, lane = tid & 31;
    const int wm = wid & 1, wn = wid >> 1;
    const int gid = lane >> 2, tig = lane & 3;

    float c[4][4][4] = {};

    auto load_stage = [&](int kt) {
        uint32_t ab = su + (kt & 3) * STG_B, bb = ab + ATILEB;
        #pragma unroll
        for (int i = 0; i < 2; i++) {
            int idx = tid + (i << 8);
            int r = idx >> 2, c8 = idx & 3;
            cp16(ab + (r * RSH + c8 * 8) * 2,
                 &A[(size_t)(bm + r) * DD + kt * 32 + c8 * 8]);
        }
        #pragma unroll
        for (int i = 0; i < 2; i++) {
            int idx = tid + (i << 8);
            int r = idx >> 4, c8 = idx & 15;
            cp16(bb + (r * BSTR + c8 * 8) * 2,
                 &W[(size_t)(kt * 32 + r) * DD + bn + c8 * 8]);
        }
        cp_commit();
    };

    load_stage(0); load_stage(1); load_stage(2);

    const int t7 = lane & 7;
    const uint32_t aro = ((lane >> 3) & 1) * 8 + t7;
    const uint32_t ak8 = ((lane >> 4) & 1) * 8;
    const uint32_t bko = ((lane >> 3) & 1) * 8 + t7;
    const uint32_t bn8 = ((lane >> 4) & 1) * 8;

    for (int kt = 0; kt < 32; kt++) {
        cp_wait<2>();
        __syncthreads();
        if (kt + 3 < 32) load_stage(kt + 3); else cp_commit();

        uint32_t ab = su + (kt & 3) * STG_B, bb = ab + ATILEB;
        #pragma unroll
        for (int ks = 0; ks < 2; ks++) {
            uint32_t a[4][4], b[2][4];
            #pragma unroll
            for (int mt = 0; mt < 4; mt++)
                ldsm4(a[mt], ab + ((wm * 64 + mt * 16 + aro) * RSH + ks * 16 + ak8) * 2);
            #pragma unroll
            for (int p = 0; p < 2; p++)
                ldsm4t(b[p], bb + ((ks * 16 + bko) * BSTR + wn * 32 + p * 16 + bn8) * 2);
            #pragma unroll
            for (int mt = 0; mt < 4; mt++)
                #pragma unroll
                for (int nt = 0; nt < 4; nt++)
                    mma16(c[mt][nt], a[mt],
                          b[nt >> 1][(nt & 1) * 2], b[nt >> 1][(nt & 1) * 2 + 1]);
        }
    }

    #pragma unroll
    for (int mt = 0; mt < 4; mt++) {
        #pragma unroll
        for (int nt = 0; nt < 4; nt++) {
            int col = bn + wn * 32 + nt * 8 + tig * 2;
            float2 bi = *(const float2*)&bias[col];
            #pragma unroll
            for (int hf = 0; hf < 2; hf++) {
                int row = bm + wm * 64 + mt * 16 + gid + hf * 8;
                float vx = c[mt][nt][hf * 2 + 0] + bi.x;
                float vy = c[mt][nt][hf * 2 + 1] + bi.y;
                *(half2*)&Out[(size_t)row * DD + col] = __floats2half2_rn(vx, vy);
                if (w == 1)
                    *(half2*)&tKo[(size_t)row * DD + col] =
                        __floats2half2_rn(tanhf(vx), tanhf(vy));
            }
        }
    }
}

// ---------------------------------------------------------------------------
// Merged FF dual GEMM
// ---------------------------------------------------------------------------
__global__ void __launch_bounds__(256, 2) gemm_ffdual_kernel(
    const __half* __restrict__ A1, const __half* __restrict__ A2,
    const __half* __restrict__ W,  const __half* __restrict__ J,
    const float* __restrict__ bias,
    __half* __restrict__ O1, __half* __restrict__ O2,
    int N, int K)
{
    extern __shared__ __half smh[];
    const uint32_t su = (uint32_t)__cvta_generic_to_shared(smh);

    const int sel = blockIdx.x & 1;
    const __half* A  = sel ? A2 : A1;
    const __half* Wm = sel ? J : W;
    __half* Out = sel ? O2 : O1;

    const int tid = threadIdx.x;
    const int bn = (blockIdx.x >> 1) << 7, bm = blockIdx.y << 7;
    const int wid = tid >> 5, lane = tid & 31;
    const int wm = wid & 1, wn = wid >> 1;
    const int gid = lane >> 2, tig = lane & 3;

    float c[4][4][4] = {};

    auto load_stage = [&](int kt) {
        uint32_t ab = su + (kt & 3) * STG_B, bb = ab + ATILEB;
        #pragma unroll
        for (int i = 0; i < 2; i++) {
            int idx = tid + (i << 8);
            int r = idx >> 2, c8 = idx & 3;
            cp16(ab + (r * RSH + c8 * 8) * 2,
                 &A[(size_t)(bm + r) * K + kt * 32 + c8 * 8]);
        }
        #pragma unroll
        for (int i = 0; i < 2; i++) {
            int idx = tid + (i << 8);
            int r = idx >> 4, c8 = idx & 15;
            cp16(bb + (r * BSTR + c8 * 8) * 2,
                 &Wm[(size_t)(kt * 32 + r) * N + bn + c8 * 8]);
        }
        cp_commit();
    };

    const int KT = K >> 5;
    load_stage(0); load_stage(1); load_stage(2);

    const int t7 = lane & 7;
    const uint32_t aro = ((lane >> 3) & 1) * 8 + t7;
    const uint32_t ak8 = ((lane >> 4) & 1) * 8;
    const uint32_t bko = ((lane >> 3) & 1) * 8 + t7;
    const uint32_t bn8 = ((lane >> 4) & 1) * 8;

    for (int kt = 0; kt < KT; kt++) {
        cp_wait<2>();
        __syncthreads();
        if (kt + 3 < KT) load_stage(kt + 3); else cp_commit();

        uint32_t ab = su + (kt & 3) * STG_B, bb = ab + ATILEB;
        #pragma unroll
        for (int ks = 0; ks < 2; ks++) {
            uint32_t a[4][4], b[2][4];
            #pragma unroll
            for (int mt = 0; mt < 4; mt++)
                ldsm4(a[mt], ab + ((wm * 64 + mt * 16 + aro) * RSH + ks * 16 + ak8) * 2);
            #pragma unroll
            for (int p = 0; p < 2; p++)
                ldsm4t(b[p], bb + ((ks * 16 + bko) * BSTR + wn * 32 + p * 16 + bn8) * 2);
            #pragma unroll
            for (int mt = 0; mt < 4; mt++)
                #pragma unroll
                for (int nt = 0; nt < 4; nt++)
                    mma16(c[mt][nt], a[mt],
                          b[nt >> 1][(nt & 1) * 2], b[nt >> 1][(nt & 1) * 2 + 1]);
        }
    }

    #pragma unroll
    for (int mt = 0; mt < 4; mt++) {
        #pragma unroll
        for (int nt = 0; nt < 4; nt++) {
            int col = bn + wn * 32 + nt * 8 + tig * 2;
            float2 bi = make_float2(0.f, 0.f);
            if (sel == 0) bi = *(const float2*)&bias[col];
            #pragma unroll
            for (int hf = 0; hf < 2; hf++) {
                int row = bm + wm * 64 + mt * 16 + gid + hf * 8;
                float vx = c[mt][nt][hf * 2 + 0] + bi.x;
                float vy = c[mt][nt][hf * 2 + 1] + bi.y;
                *(half2*)&Out[(size_t)row * N + col] = __floats2half2_rn(vx, vy);
            }
        }
    }
}

// ---------------- fused fp32 -> fp16 convert of ALL weights ----------------
#define CVT_S1 (DD*DD/4)
#define CVT_S2 (DD*FFD/4)
#define CVT_TOTAL4 (4*CVT_S1 + 4*CVT_S2)

__global__ void __launch_bounds__(256) convert_all_kernel(
    const float* __restrict__ wq, const float* __restrict__ wk,
    const float* __restrict__ wv, const float* __restrict__ wo,
    const float* __restrict__ W1, const float* __restrict__ J1,
    const float* __restrict__ W2, const float* __restrict__ J2,
    __half* dwq, __half* dwk, __half* dwv, __half* dwo,
    __half* dW1, __half* dJ1, __half* dW2, __half* dJ2)
{
    int i = blockIdx.x * 256 + threadIdx.x;
    if (i >= CVT_TOTAL4) return;
    const float* src; __half* dst; int off;
    if (i < 4 * CVT_S1) {
        int w = i >> 18; off = i & (CVT_S1 - 1);
        src = (w == 0) ? wq : (w == 1) ? wk : (w == 2) ? wv : wo;
        dst = (w == 0) ? dwq : (w == 1) ? dwk : (w == 2) ? dwv : dwo;
    } else {
        int j = i - 4 * CVT_S1;
        int w = j >> 20; off = j & (CVT_S2 - 1);
        src = (w == 0) ? W1 : (w == 1) ? J1 : (w == 2) ? W2 : J2;
        dst = (w == 0) ? dW1 : (w == 1) ? dJ1 : (w == 2) ? dW2 : dJ2;
    }
    float4 v = *(const float4*)&src[(size_t)off * 4];
    *(half2*)&dst[(size_t)off * 4]     = __floats2half2_rn(v.x, v.y);
    *(half2*)&dst[(size_t)off * 4 + 2] = __floats2half2_rn(v.z, v.w);
}

// ---------------------------------------------------------------------------
// FP16 flash attention with FUSED tQJ = tanh(Q) @ J[h] prologue.
// ---------------------------------------------------------------------------
#define AST 72
#define ATILE (64*AST)
#define ATT_SMEM (6*ATILE*2)

__global__ void __launch_bounds__(128) attn_f16_kernel(
    const __half* __restrict__ Q,  const __half* __restrict__ K,
    const __half* __restrict__ TK, const __half* __restrict__ V,
    const float* __restrict__ Jat, __half* __restrict__ O,
    const float* __restrict__ lam_p)
{
    extern __shared__ __half smh[];
    const uint32_t su = (uint32_t)__cvta_generic_to_shared(smh);
    const uint32_t Qb = su;
    const uint32_t Tb = Qb + ATILE * 2;
    const uint32_t Pb = Tb + ATILE * 2;   // prologue: tanh(Q) scratch
    const uint32_t Kb = Pb + ATILE * 2;   // prologue: J[h] fp16
    const uint32_t Gb = Kb + ATILE * 2;
    const uint32_t Vb = Gb + ATILE * 2;
    __half* sm = smh;

    const int tid = threadIdx.x;
    const int wid = tid >> 5, lane = tid & 31;
    const int gid = lane >> 2, tig = lane & 3;
    const int mrow = wid * 16;
    const int bh = blockIdx.y, b = bh >> 4, h = bh & 15;
    const int q0 = blockIdx.x << 6;
    const float lam = __ldg(lam_p);

    const int t7 = lane & 7;
    const uint32_t aro = ((lane >> 3) & 1) * 8 + t7, ak8 = ((lane >> 4) & 1) * 8;
    const uint32_t bro = ((lane >> 4) & 1) * 8 + t7, bk8 = ((lane >> 3) & 1) * 8;
    const uint32_t vko = ((lane >> 3) & 1) * 8 + t7, vn8 = ((lane >> 4) & 1) * 8;

    // ---- prologue: stage Q, stage J[h] fp16, compute T = tanh(Q) @ J ----
    for (int i = tid; i < 512; i += 128) {
        int r = i >> 3, c8 = i & 7;
        cp16(Qb + (r * AST + c8 * 8) * 2,
             &Q[((size_t)(b * SS + q0 + r)) * DD + h * HD + c8 * 8]);
    }
    cp_commit();

    // J[h]: [d][e] fp32 -> fp16 into Kb region (natural [K][N] layout)
    for (int i = tid; i < 1024; i += 128) {
        int d = i >> 4, e4 = (i & 15) << 2;
        float4 v = *(const float4*)&Jat[(size_t)h * HD * HD + d * HD + e4];
        *(half2*)&sm[(Kb - su) / 2 + d * AST + e4]     = __floats2half2_rn(v.x, v.y);
        *(half2*)&sm[(Kb - su) / 2 + d * AST + e4 + 2] = __floats2half2_rn(v.z, v.w);
    }
    cp_wait<0>();
    __syncthreads();

    // tanh(Q) -> Pb region (fp16)
    for (int i = tid; i < 2048; i += 128) {
        int r = i >> 5, c2 = (i & 31) << 1;
        half2 q = *(half2*)&sm[(Qb - su) / 2 + r * AST + c2];
        *(half2*)&sm[(Pb - su) / 2 + r * AST + c2] =
            __floats2half2_rn(tanhf(__half2float(q.x)), tanhf(__half2float(q.y)));
    }
    __syncthreads();

    // T = tanhQ @ J : A from Pb (ldsm4), B from Kb [k][n] (ldsm4t)
    {
        float ct[8][4] = {};
        #pragma unroll
        for (int ks = 0; ks < 4; ks++) {
            uint32_t ap[4], bj[4][4];
            ldsm4(ap, Pb + ((mrow + aro) * AST + ks * 16 + ak8) * 2);
            #pragma unroll
            for (int p = 0; p < 4; p++)
                ldsm4t(bj[p], Kb + ((ks * 16 + vko) * AST + p * 16 + vn8) * 2);
            #pragma unroll
            for (int nt = 0; nt < 8; nt++)
                mma16(ct[nt], ap, bj[nt >> 1][(nt & 1) * 2], bj[nt >> 1][(nt & 1) * 2 + 1]);
        }
        __half* Ts = sm + (Tb - su) / 2;
        #pragma unroll
        for (int nt = 0; nt < 8; nt++) {
            int col = nt * 8 + tig * 2;
            *(half2*)&Ts[(mrow + gid    ) * AST + col] =
                __floats2half2_rn(ct[nt][0], ct[nt][1]);
            *(half2*)&Ts[(mrow + gid + 8) * AST + col] =
                __floats2half2_rn(ct[nt][2], ct[nt][3]);
        }
        __syncwarp();
    }

    __half* Ps = sm + (Pb - su) / 2;

    float m0 = -1e30f, m1 = -1e30f, l0 = 0.f, l1 = 0.f;
    float o[8][4] = {};

    for (int k0 = 0; k0 < SS; k0 += 64) {
        __syncthreads();
        for (int i = tid; i < 512; i += 128) {
            int r = i >> 3, c8 = i & 7;
            size_t g = ((size_t)(b * SS + k0 + r)) * DD + h * HD + c8 * 8;
            uint32_t off = (r * AST + c8 * 8) * 2;
            cp16(Kb + off, &K[g]);
            cp16(Gb + off, &TK[g]);
            cp16(Vb + off, &V[g]);
        }
        cp_commit();
        cp_wait<0>();
        __syncthreads();

        float cs[8][4] = {}, cd[8][4] = {};
        #pragma unroll
        for (int ks = 0; ks < 4; ks++) {
            uint32_t aq[4], at[4], bk[4][4], bt[4][4];
            ldsm4(aq, Qb + ((mrow + aro) * AST + ks * 16 + ak8) * 2);
            ldsm4(at, Tb + ((mrow + aro) * AST + ks * 16 + ak8) * 2);
            #pragma unroll
            for (int p = 0; p < 4; p++) {
                uint32_t off = ((p * 16 + bro) * AST + ks * 16 + bk8) * 2;
                ldsm4(bk[p], Kb + off);
                ldsm4(bt[p], Gb + off);
            }
            #pragma unroll
            for (int nt = 0; nt < 8; nt++) {
                mma16(cs[nt], aq, bk[nt >> 1][(nt & 1) * 2], bk[nt >> 1][(nt & 1) * 2 + 1]);
                mma16(cd[nt], at, bt[nt >> 1][(nt & 1) * 2], bt[nt >> 1][(nt & 1) * 2 + 1]);
            }
        }

        float s[8][4];
        float mx0 = -1e30f, mx1 = -1e30f;
        #pragma unroll
        for (int nt = 0; nt < 8; nt++) {
            #pragma unroll
            for (int e = 0; e < 4; e++)
                s[nt][e] = fmaf(lam, cd[nt][e], cs[nt][e] * INV_SCALE);
            mx0 = fmaxf(mx0, fmaxf(s[nt][0], s[nt][1]));
            mx1 = fmaxf(mx1, fmaxf(s[nt][2], s[nt][3]));
        }
        mx0 = fmaxf(mx0, __shfl_xor_sync(0xffffffffu, mx0, 1));
        mx0 = fmaxf(mx0, __shfl_xor_sync(0xffffffffu, mx0, 2));
        mx1 = fmaxf(mx1, __shfl_xor_sync(0xffffffffu, mx1, 1));
        mx1 = fmaxf(mx1, __shfl_xor_sync(0xffffffffu, mx1, 2));
        float mn0 = fmaxf(m0, mx0), mn1 = fmaxf(m1, mx1);
        float corr0 = __expf(m0 - mn0), corr1 = __expf(m1 - mn1);
        m0 = mn0; m1 = mn1;
        l0 *= corr0; l1 *= corr1;

        float sum0 = 0.f, sum1 = 0.f;
        #pragma unroll
        for (int nt = 0; nt < 8; nt++) {
            float p00 = __expf(s[nt][0] - mn0);
            float p01 = __expf(s[nt][1] - mn0);
            float p10 = __expf(s[nt][2] - mn1);
            float p11 = __expf(s[nt][3] - mn1);
            sum0 += p00 + p01; sum1 += p10 + p11;
            int col = nt * 8 + tig * 2;
            *(half2*)&Ps[(mrow + gid    ) * AST + col] = __floats2half2_rn(p00, p01);
            *(half2*)&Ps[(mrow + gid + 8) * AST + col] = __floats2half2_rn(p10, p11);
        }
        sum0 += __shfl_xor_sync(0xffffffffu, sum0, 1);
        sum0 += __shfl_xor_sync(0xffffffffu, sum0, 2);
        sum1 += __shfl_xor_sync(0xffffffffu, sum1, 1);
        sum1 += __shfl_xor_sync(0xffffffffu, sum1, 2);
        l0 += sum0; l1 += sum1;

        #pragma unroll
        for (int nt = 0; nt < 8; nt++) {
            o[nt][0] *= corr0; o[nt][1] *= corr0;
            o[nt][2] *= corr1; o[nt][3] *= corr1;
        }
        __syncwarp();

        #pragma unroll
        for (int ks = 0; ks < 4; ks++) {
            uint32_t ap[4], bv[4][4];
            ldsm4(ap, Pb + ((mrow + aro) * AST + ks * 16 + ak8) * 2);
            #pragma unroll
            for (int p = 0; p < 4; p++)
                ldsm4t(bv[p], Vb + ((ks * 16 + vko) * AST + p * 16 + vn8) * 2);
            #pragma unroll
            for (int nt = 0; nt < 8; nt++)
                mma16(o[nt], ap, bv[nt >> 1][(nt & 1) * 2], bv[nt >> 1][(nt & 1) * 2 + 1]);
        }
        __syncwarp();
    }

    float inv0 = 1.f / l0, inv1 = 1.f / l1;
    int row0 = q0 + mrow + gid, row1 = row0 + 8;
    #pragma unroll
    for (int nt = 0; nt < 8; nt++) {
        int col = nt * 8 + tig * 2;
        *(half2*)&O[((size_t)(b * SS + row0)) * DD + h * HD + col] =
            __floats2half2_rn(o[nt][0] * inv0, o[nt][1] * inv0);
        *(half2*)&O[((size_t)(b * SS + row1)) * DD + h * HD + col] =
            __floats2half2_rn(o[nt][2] * inv1, o[nt][3] * inv1);
    }
}

// ---------------- LayerNorm: fp32 in, fp16 out (+opt fp16 tanh out) ----------------
__global__ void __launch_bounds__(256) ln_kernel(
    const float* __restrict__ X, const float* __restrict__ g,
    const float* __restrict__ b, __half* __restrict__ Y,
    __half* __restrict__ YT, int N)
{
    int row = blockIdx.x;
    const float* x = X + (size_t)row * N;
    float s = 0.f, s2 = 0.f;
    for (int i = threadIdx.x; i < N; i += 256) {
        float v = x[i];
        s += v; s2 = fmaf(v, v, s2);
    }
    __shared__ float sh[64];
    for (int o = 16; o > 0; o >>= 1) {
        s  += __shfl_down_sync(0xffffffffu, s,  o);
        s2 += __shfl_down_sync(0xffffffffu, s2, o);
    }
    int wid = threadIdx.x >> 5, lane = threadIdx.x & 31;
    if (lane == 0) { sh[wid] = s; sh[wid + 32] = s2; }
    __syncthreads();
    if (threadIdx.x == 0) {
        float ts = 0.f, ts2 = 0.f;
        for (int w = 0; w < 8; w++) { ts += sh[w]; ts2 += sh[w + 32]; }
        float mu = ts / N, var = ts2 / N - mu * mu;
        sh[0] = mu; sh[1] = rsqrtf(var + 1e-5f);
    }
    __syncthreads();
    float mu = sh[0], rstd = sh[1];
    for (int i = threadIdx.x; i < N; i += 256) {
        float v = (x[i] - mu) * rstd * g[i] + b[i];
        Y[(size_t)row * N + i] = __float2half(v);
        if (YT) YT[(size_t)row * N + i] = __float2half(tanhf(v));
    }
}

// ---------------- QBNN combine + LN + GELU (fp16 ht/dlt in, half2 vec) ------------
__global__ void __launch_bounds__(256) qln_gelu_kernel(
    const __half* __restrict__ HT, const __half* __restrict__ DLT,
    const float* __restrict__ g,  const float* __restrict__ b,
    const float* __restrict__ Res, float* __restrict__ Yf,
    __half* __restrict__ Yh, __half* __restrict__ Yth, int N)
{
    extern __shared__ float rowbuf[];
    __shared__ float sh[64];
    int row = blockIdx.x;
    size_t base = (size_t)row * N;
    int N2 = N >> 1;

    float s = 0.f, s2 = 0.f;
    for (int i = threadIdx.x; i < N2; i += 256) {
        half2 ht2 = *(const half2*)&HT[base + i * 2];
        half2 dl2 = *(const half2*)&DLT[base + i * 2];
        float hx = __half2float(ht2.x), hy = __half2float(ht2.y);
        float vx = fmaf(LAM_EFF * __half2float(dl2.x), tanhf(hx), hx);
        float vy = fmaf(LAM_EFF * __half2float(dl2.y), tanhf(hy), hy);
        rowbuf[i * 2] = vx; rowbuf[i * 2 + 1] = vy;
        s += vx + vy; s2 = fmaf(vx, vx, fmaf(vy, vy, s2));
    }
    for (int o = 16; o > 0; o >>= 1) {
        s  += __shfl_down_sync(0xffffffffu, s,  o);
        s2 += __shfl_down_sync(0xffffffffu, s2, o);
    }
    int wid = threadIdx.x >> 5, lane = threadIdx.x & 31;
    if (lane == 0) { sh[wid] = s; sh[wid + 32] = s2; }
    __syncthreads();
    if (threadIdx.x == 0) {
        float ts = 0.f, ts2 = 0.f;
        for (int w = 0; w < 8; w++) { ts += sh[w]; ts2 += sh[w + 32]; }
        float mu = ts / N, var = ts2 / N - mu * mu;
        sh[0] = mu; sh[1] = rsqrtf(var + 1e-5f);
    }
    __syncthreads();
    float mu = sh[0], rstd = sh[1];
    for (int i = threadIdx.x; i < N2; i += 256) {
        float2 gg = *(const float2*)&g[i * 2];
        float2 bb = *(const float2*)&b[i * 2];
        float vx = (rowbuf[i * 2]     - mu) * rstd * gg.x + bb.x;
        float vy = (rowbuf[i * 2 + 1] - mu) * rstd * gg.y + bb.y;
        float gex = vx * normcdff(vx), gey = vy * normcdff(vy);
        float ox = gex, oy = gey;
        if (Res) {
            float2 rr = *(const float2*)&Res[base + i * 2];
            ox += rr.x; oy += rr.y;
        }
        if (Yf)  *(float2*)&Yf[base + i * 2] = make_float2(ox, oy);
        if (Yh)  *(half2*)&Yh[base + i * 2] = __floats2half2_rn(ox, oy);
        if (Yth) *(half2*)&Yth[base + i * 2] =
                     __floats2half2_rn(tanhf(ox), tanhf(oy));
    }
}

// ---------------- host ----------------
template<typename T> static T* symaddr(const void* s)
{
    void* p = nullptr;
    cudaGetSymbolAddress(&p, s);
    return (T*)p;
}

extern "C" void kernel_launch(void* const* d_in, const int* in_sizes, int n_in,
                              void* d_out, int out_size)
{
    (void)in_sizes; (void)n_in; (void)out_size;

    const float* x   = (const float*)d_in[0];
    const float* wq  = (const float*)d_in[1];
    const float* bq  = (const float*)d_in[2];
    const float* wk  = (const float*)d_in[3];
    const float* bk  = (const float*)d_in[4];
    const float* wv  = (const float*)d_in[5];
    const float* bv  = (const float*)d_in[6];
    const float* wo  = (const float*)d_in[7];
    const float* bo  = (const float*)d_in[8];
    const float* Jat = (const float*)d_in[9];
    const float* lam = (const float*)d_in[10];
    const float* gat = (const float*)d_in[11];
    const float* bat = (const float*)d_in[12];
    const float* W1  = (const float*)d_in[13];
    const float* b1  = (const float*)d_in[14];
    const float* J1  = (const float*)d_in[15];
    const float* g1  = (const float*)d_in[17];
    const float* be1 = (const float*)d_in[18];
    const float* W2  = (const float*)d_in[19];
    const float* b2  = (const float*)d_in[20];
    const float* J2  = (const float*)d_in[21];
    const float* g2  = (const float*)d_in[23];
    const float* be2 = (const float*)d_in[24];
    const float* gf  = (const float*)d_in[25];
    const float* bf  = (const float*)d_in[26];
    float* out = (float*)d_out;

    __half* p_xn  = symaddr<__half>(h_xn);
    __half* p_Q   = symaddr<__half>(h_Q);
    __half* p_K   = symaddr<__half>(h_K);
    __half* p_tK  = symaddr<__half>(h_tK);
    __half* p_V   = symaddr<__half>(h_V);
    __half* p_ao  = symaddr<__half>(h_ao);
    float*  p_x1  = symaddr<float>(f_x1);
    __half* p_th  = symaddr<__half>(h_th);
    __half* p_hh  = symaddr<__half>(h_hh);
    __half* p_dl  = symaddr<__half>(h_dl);
    __half* p_h1  = symaddr<__half>(h_h1);
    __half* p_th1 = symaddr<__half>(h_th1);
    __half* p_wq  = symaddr<__half>(h_wq);
    __half* p_wk  = symaddr<__half>(h_wk);
    __half* p_wv  = symaddr<__half>(h_wv);
    __half* p_wo  = symaddr<__half>(h_wo);
    __half* p_W1  = symaddr<__half>(h_W1);
    __half* p_J1  = symaddr<__half>(h_J1);
    __half* p_W2  = symaddr<__half>(h_W2);
    __half* p_J2  = symaddr<__half>(h_J2);

    cudaFuncSetAttribute(attn_f16_kernel,
                         cudaFuncAttributeMaxDynamicSharedMemorySize, ATT_SMEM);
    cudaFuncSetAttribute(gemm_qkv_kernel,
                         cudaFuncAttributeMaxDynamicSharedMemorySize, GEMM_SMEM);
    cudaFuncSetAttribute(gemm_ffdual_kernel,
                         cudaFuncAttributeMaxDynamicSharedMemorySize, GEMM_SMEM);
    cudaFuncSetAttribute(gemm_f16_kernel<true, true, false>,
                         cudaFuncAttributeMaxDynamicSharedMemorySize, GEMM_SMEM);

    convert_all_kernel<<<CVT_TOTAL4 / 256, 256>>>(
        wq, wk, wv, wo, W1, J1, W2, J2,
        p_wq, p_wk, p_wv, p_wo, p_W1, p_J1, p_W2, p_J2);

    // --- attention branch ---
    ln_kernel<<<NT, 256>>>(x, gat, bat, p_xn, nullptr, DD);

    gemm_qkv_kernel<<<dim3(24, NT / 128), 256, GEMM_SMEM>>>(
        p_xn, p_wq, p_wk, p_wv, bq, bk, bv, p_Q, p_K, p_V, p_tK);

    attn_f16_kernel<<<dim3(SS / 64, BB * HH), 128, ATT_SMEM>>>(
        p_Q, p_K, p_tK, p_V, Jat, p_ao, lam);

    gemm_f16_kernel<true, true, false><<<dim3(8, NT / 128), 256, GEMM_SMEM>>>(
        p_ao, p_wo, bo, x, p_x1, nullptr, NT, DD, DD);

    // --- QBNN FFN layer 1 (merged dual GEMM) ---
    ln_kernel<<<NT, 256>>>(p_x1, gf, bf, p_xn, p_th, DD);

    gemm_ffdual_kernel<<<dim3(2 * FFD / 128, NT / 128), 256, GEMM_SMEM>>>(
        p_xn, p_th, p_W1, p_J1, b1, p_hh, p_dl, FFD, DD);

    qln_gelu_kernel<<<NT, 256, FFD * sizeof(float)>>>(
        p_hh, p_dl, g1, be1, nullptr, nullptr, p_h1, p_th1, FFD);

    // --- QBNN FFN layer 2 (merged dual GEMM) ---
    gemm_ffdual_kernel<<<dim3(2 * DD / 128, NT / 128), 256, GEMM_SMEM>>>(
        p_h1, p_th1, p_W2, p_J2, b2, p_hh, p_dl, DD, FFD);

    qln_gelu_kernel<<<NT, 256, DD * sizeof(float)>>>(
        p_hh, p_dl, g2, be2, p_x1, out, nullptr, nullptr, DD);
}

// round 17
// speedup vs baseline: 1.9006x; 1.0016x over previous
#include <cuda_runtime.h>
#include <cuda_fp16.h>
#include <math.h>
#include <stdint.h>

#define BB   4
#define SS   1024
#define DD   1024
#define HH   16
#define HD   64
#define FFD  4096
#define NT   (BB*SS)
#define INV_SCALE 0.125f
#define LAM_EFF   0.5f

// ---------------- scratch ----------------
__device__ __half h_xn  [NT*DD];
__device__ __half h_Q   [NT*DD];
__device__ __half h_K   [NT*DD];
__device__ __half h_tK  [NT*DD];
__device__ __half h_V   [NT*DD];
__device__ __half h_ao  [NT*DD];
__device__ float  f_x1  [NT*DD];
__device__ __half h_th  [NT*DD];
__device__ __half h_hh  [NT*FFD];
__device__ __half h_dl  [NT*FFD];
__device__ __half h_h1  [NT*FFD];
__device__ __half h_th1 [NT*FFD];
// fp16 weights, natural [K][N] layout
__device__ __half h_wq  [DD*DD];
__device__ __half h_wk  [DD*DD];
__device__ __half h_wv  [DD*DD];
__device__ __half h_wo  [DD*DD];
__device__ __half h_W1  [DD*FFD];
__device__ __half h_J1  [DD*FFD];
__device__ __half h_W2  [FFD*DD];
__device__ __half h_J2  [FFD*DD];

// ---------------- helpers ----------------
__device__ __forceinline__ void cp16(uint32_t d, const void* g)
{ asm volatile("cp.async.cg.shared.global [%0], [%1], 16;\n" :: "r"(d), "l"(g)); }
__device__ __forceinline__ void cp_commit()
{ asm volatile("cp.async.commit_group;\n"); }
template<int N> __device__ __forceinline__ void cp_wait()
{ asm volatile("cp.async.wait_group %0;\n" :: "n"(N)); }

__device__ __forceinline__ void mma16(float* c, const uint32_t* a,
                                      uint32_t b0, uint32_t b1)
{
    asm volatile(
        "mma.sync.aligned.m16n8k16.row.col.f32.f16.f16.f32 "
        "{%0,%1,%2,%3},{%4,%5,%6,%7},{%8,%9},{%0,%1,%2,%3};"
        : "+f"(c[0]), "+f"(c[1]), "+f"(c[2]), "+f"(c[3])
        : "r"(a[0]), "r"(a[1]), "r"(a[2]), "r"(a[3]), "r"(b0), "r"(b1));
}
__device__ __forceinline__ void ldsm4(uint32_t* r, uint32_t addr)
{
    asm volatile("ldmatrix.sync.aligned.m8n8.x4.shared.b16 {%0,%1,%2,%3}, [%4];"
                 : "=r"(r[0]), "=r"(r[1]), "=r"(r[2]), "=r"(r[3]) : "r"(addr));
}
__device__ __forceinline__ void ldsm4t(uint32_t* r, uint32_t addr)
{
    asm volatile("ldmatrix.sync.aligned.m8n8.x4.trans.shared.b16 {%0,%1,%2,%3}, [%4];"
                 : "=r"(r[0]), "=r"(r[1]), "=r"(r[2]), "=r"(r[3]) : "r"(addr));
}

// ---------------------------------------------------------------------------
// FP16 GEMM tiling constants
// ---------------------------------------------------------------------------
#define RSH   40
#define BSTR  136
#define ATILEB (128*RSH*2)
#define BTILEB (32*BSTR*2)
#define STG_B  (ATILEB + BTILEB)
#define NSTG   4
#define GEMM_SMEM (NSTG*STG_B)      // 75776 B

// ---------------------------------------------------------------------------
// Generic GEMM: C = A@W (+bias)(+Res); fp32 or fp16 out. (used for out-proj)
// ---------------------------------------------------------------------------
template<bool BIAS, bool RES, bool HOUT>
__global__ void __launch_bounds__(256, 2) gemm_f16_kernel(
    const __half* __restrict__ A, const __half* __restrict__ W,
    const float* __restrict__ bias, const float* __restrict__ Res,
    float* __restrict__ C, __half* __restrict__ C16,
    int M, int N, int K)
{
    extern __shared__ __half smh[];
    const uint32_t su = (uint32_t)__cvta_generic_to_shared(smh);

    const int tid = threadIdx.x;
    const int bn = blockIdx.x << 7, bm = blockIdx.y << 7;
    const int wid = tid >> 5, lane = tid & 31;
    const int wm = wid & 1, wn = wid >> 1;
    const int gid = lane >> 2, tig = lane & 3;

    float c[4][4][4] = {};

    auto load_stage = [&](int kt) {
        uint32_t ab = su + (kt & 3) * STG_B, bb = ab + ATILEB;
        #pragma unroll
        for (int i = 0; i < 2; i++) {
            int idx = tid + (i << 8);
            int r = idx >> 2, c8 = idx & 3;
            cp16(ab + (r * RSH + c8 * 8) * 2,
                 &A[(size_t)(bm + r) * K + kt * 32 + c8 * 8]);
        }
        #pragma unroll
        for (int i = 0; i < 2; i++) {
            int idx = tid + (i << 8);
            int r = idx >> 4, c8 = idx & 15;
            cp16(bb + (r * BSTR + c8 * 8) * 2,
                 &W[(size_t)(kt * 32 + r) * N + bn + c8 * 8]);
        }
        cp_commit();
    };

    const int KT = K >> 5;
    load_stage(0); load_stage(1); load_stage(2);

    const int t7 = lane & 7;
    const uint32_t aro = ((lane >> 3) & 1) * 8 + t7;
    const uint32_t ak8 = ((lane >> 4) & 1) * 8;
    const uint32_t bko = ((lane >> 3) & 1) * 8 + t7;
    const uint32_t bn8 = ((lane >> 4) & 1) * 8;

    for (int kt = 0; kt < KT; kt++) {
        cp_wait<2>();
        __syncthreads();
        if (kt + 3 < KT) load_stage(kt + 3); else cp_commit();

        uint32_t ab = su + (kt & 3) * STG_B, bb = ab + ATILEB;
        #pragma unroll
        for (int ks = 0; ks < 2; ks++) {
            uint32_t a[4][4], b[2][4];
            #pragma unroll
            for (int mt = 0; mt < 4; mt++)
                ldsm4(a[mt], ab + ((wm * 64 + mt * 16 + aro) * RSH + ks * 16 + ak8) * 2);
            #pragma unroll
            for (int p = 0; p < 2; p++)
                ldsm4t(b[p], bb + ((ks * 16 + bko) * BSTR + wn * 32 + p * 16 + bn8) * 2);
            #pragma unroll
            for (int mt = 0; mt < 4; mt++)
                #pragma unroll
                for (int nt = 0; nt < 4; nt++)
                    mma16(c[mt][nt], a[mt],
                          b[nt >> 1][(nt & 1) * 2], b[nt >> 1][(nt & 1) * 2 + 1]);
        }
    }

    #pragma unroll
    for (int mt = 0; mt < 4; mt++) {
        #pragma unroll
        for (int nt = 0; nt < 4; nt++) {
            int col = bn + wn * 32 + nt * 8 + tig * 2;
            float2 bi = make_float2(0.f, 0.f);
            if (BIAS) bi = *(const float2*)&bias[col];
            #pragma unroll
            for (int hf = 0; hf < 2; hf++) {
                int row = bm + wm * 64 + mt * 16 + gid + hf * 8;
                float vx = c[mt][nt][hf * 2 + 0] + bi.x;
                float vy = c[mt][nt][hf * 2 + 1] + bi.y;
                if (RES) {
                    float2 r = *(const float2*)&Res[(size_t)row * N + col];
                    vx += r.x; vy += r.y;
                }
                if (HOUT)
                    *(half2*)&C16[(size_t)row * N + col] = __floats2half2_rn(vx, vy);
                else
                    *(float2*)&C[(size_t)row * N + col] = make_float2(vx, vy);
            }
        }
    }
}

// ---------------------------------------------------------------------------
// Merged QKV GEMM
// ---------------------------------------------------------------------------
__global__ void __launch_bounds__(256, 2) gemm_qkv_kernel(
    const __half* __restrict__ A,
    const __half* __restrict__ Wq, const __half* __restrict__ Wk,
    const __half* __restrict__ Wv,
    const float* __restrict__ bq, const float* __restrict__ bk,
    const float* __restrict__ bv,
    __half* __restrict__ Qo, __half* __restrict__ Ko,
    __half* __restrict__ Vo, __half* __restrict__ tKo)
{
    extern __shared__ __half smh[];
    const uint32_t su = (uint32_t)__cvta_generic_to_shared(smh);

    const int w = blockIdx.x >> 3;
    const __half* W = (w == 0) ? Wq : (w == 1) ? Wk : Wv;
    const float* bias = (w == 0) ? bq : (w == 1) ? bk : bv;
    __half* Out = (w == 0) ? Qo : (w == 1) ? Ko : Vo;

    const int tid = threadIdx.x;
    const int bn = (blockIdx.x & 7) << 7, bm = blockIdx.y << 7;
    const int wid = tid >> 5, lane = tid & 31;
    const int wm = wid & 1, wn = wid >> 1;
    const int gid = lane >> 2, tig = lane & 3;

    float c[4][4][4] = {};

    auto load_stage = [&](int kt) {
        uint32_t ab = su + (kt & 3) * STG_B, bb = ab + ATILEB;
        #pragma unroll
        for (int i = 0; i < 2; i++) {
            int idx = tid + (i << 8);
            int r = idx >> 2, c8 = idx & 3;
            cp16(ab + (r * RSH + c8 * 8) * 2,
                 &A[(size_t)(bm + r) * DD + kt * 32 + c8 * 8]);
        }
        #pragma unroll
        for (int i = 0; i < 2; i++) {
            int idx = tid + (i << 8);
            int r = idx >> 4, c8 = idx & 15;
            cp16(bb + (r * BSTR + c8 * 8) * 2,
                 &W[(size_t)(kt * 32 + r) * DD + bn + c8 * 8]);
        }
        cp_commit();
    };

    load_stage(0); load_stage(1); load_stage(2);

    const int t7 = lane & 7;
    const uint32_t aro = ((lane >> 3) & 1) * 8 + t7;
    const uint32_t ak8 = ((lane >> 4) & 1) * 8;
    const uint32_t bko = ((lane >> 3) & 1) * 8 + t7;
    const uint32_t bn8 = ((lane >> 4) & 1) * 8;

    for (int kt = 0; kt < 32; kt++) {
        cp_wait<2>();
        __syncthreads();
        if (kt + 3 < 32) load_stage(kt + 3); else cp_commit();

        uint32_t ab = su + (kt & 3) * STG_B, bb = ab + ATILEB;
        #pragma unroll
        for (int ks = 0; ks < 2; ks++) {
            uint32_t a[4][4], b[2][4];
            #pragma unroll
            for (int mt = 0; mt < 4; mt++)
                ldsm4(a[mt], ab + ((wm * 64 + mt * 16 + aro) * RSH + ks * 16 + ak8) * 2);
            #pragma unroll
            for (int p = 0; p < 2; p++)
                ldsm4t(b[p], bb + ((ks * 16 + bko) * BSTR + wn * 32 + p * 16 + bn8) * 2);
            #pragma unroll
            for (int mt = 0; mt < 4; mt++)
                #pragma unroll
                for (int nt = 0; nt < 4; nt++)
                    mma16(c[mt][nt], a[mt],
                          b[nt >> 1][(nt & 1) * 2], b[nt >> 1][(nt & 1) * 2 + 1]);
        }
    }

    #pragma unroll
    for (int mt = 0; mt < 4; mt++) {
        #pragma unroll
        for (int nt = 0; nt < 4; nt++) {
            int col = bn + wn * 32 + nt * 8 + tig * 2;
            float2 bi = *(const float2*)&bias[col];
            #pragma unroll
            for (int hf = 0; hf < 2; hf++) {
                int row = bm + wm * 64 + mt * 16 + gid + hf * 8;
                float vx = c[mt][nt][hf * 2 + 0] + bi.x;
                float vy = c[mt][nt][hf * 2 + 1] + bi.y;
                *(half2*)&Out[(size_t)row * DD + col] = __floats2half2_rn(vx, vy);
                if (w == 1)
                    *(half2*)&tKo[(size_t)row * DD + col] =
                        __floats2half2_rn(tanhf(vx), tanhf(vy));
            }
        }
    }
}

// ---------------------------------------------------------------------------
// Merged FF dual GEMM
// ---------------------------------------------------------------------------
__global__ void __launch_bounds__(256, 2) gemm_ffdual_kernel(
    const __half* __restrict__ A1, const __half* __restrict__ A2,
    const __half* __restrict__ W,  const __half* __restrict__ J,
    const float* __restrict__ bias,
    __half* __restrict__ O1, __half* __restrict__ O2,
    int N, int K)
{
    extern __shared__ __half smh[];
    const uint32_t su = (uint32_t)__cvta_generic_to_shared(smh);

    const int sel = blockIdx.x & 1;
    const __half* A  = sel ? A2 : A1;
    const __half* Wm = sel ? J : W;
    __half* Out = sel ? O2 : O1;

    const int tid = threadIdx.x;
    const int bn = (blockIdx.x >> 1) << 7, bm = blockIdx.y << 7;
    const int wid = tid >> 5, lane = tid & 31;
    const int wm = wid & 1, wn = wid >> 1;
    const int gid = lane >> 2, tig = lane & 3;

    float c[4][4][4] = {};

    auto load_stage = [&](int kt) {
        uint32_t ab = su + (kt & 3) * STG_B, bb = ab + ATILEB;
        #pragma unroll
        for (int i = 0; i < 2; i++) {
            int idx = tid + (i << 8);
            int r = idx >> 2, c8 = idx & 3;
            cp16(ab + (r * RSH + c8 * 8) * 2,
                 &A[(size_t)(bm + r) * K + kt * 32 + c8 * 8]);
        }
        #pragma unroll
        for (int i = 0; i < 2; i++) {
            int idx = tid + (i << 8);
            int r = idx >> 4, c8 = idx & 15;
            cp16(bb + (r * BSTR + c8 * 8) * 2,
                 &Wm[(size_t)(kt * 32 + r) * N + bn + c8 * 8]);
        }
        cp_commit();
    };

    const int KT = K >> 5;
    load_stage(0); load_stage(1); load_stage(2);

    const int t7 = lane & 7;
    const uint32_t aro = ((lane >> 3) & 1) * 8 + t7;
    const uint32_t ak8 = ((lane >> 4) & 1) * 8;
    const uint32_t bko = ((lane >> 3) & 1) * 8 + t7;
    const uint32_t bn8 = ((lane >> 4) & 1) * 8;

    for (int kt = 0; kt < KT; kt++) {
        cp_wait<2>();
        __syncthreads();
        if (kt + 3 < KT) load_stage(kt + 3); else cp_commit();

        uint32_t ab = su + (kt & 3) * STG_B, bb = ab + ATILEB;
        #pragma unroll
        for (int ks = 0; ks < 2; ks++) {
            uint32_t a[4][4], b[2][4];
            #pragma unroll
            for (int mt = 0; mt < 4; mt++)
                ldsm4(a[mt], ab + ((wm * 64 + mt * 16 + aro) * RSH + ks * 16 + ak8) * 2);
            #pragma unroll
            for (int p = 0; p < 2; p++)
                ldsm4t(b[p], bb + ((ks * 16 + bko) * BSTR + wn * 32 + p * 16 + bn8) * 2);
            #pragma unroll
            for (int mt = 0; mt < 4; mt++)
                #pragma unroll
                for (int nt = 0; nt < 4; nt++)
                    mma16(c[mt][nt], a[mt],
                          b[nt >> 1][(nt & 1) * 2], b[nt >> 1][(nt & 1) * 2 + 1]);
        }
    }

    #pragma unroll
    for (int mt = 0; mt < 4; mt++) {
        #pragma unroll
        for (int nt = 0; nt < 4; nt++) {
            int col = bn + wn * 32 + nt * 8 + tig * 2;
            float2 bi = make_float2(0.f, 0.f);
            if (sel == 0) bi = *(const float2*)&bias[col];
            #pragma unroll
            for (int hf = 0; hf < 2; hf++) {
                int row = bm + wm * 64 + mt * 16 + gid + hf * 8;
                float vx = c[mt][nt][hf * 2 + 0] + bi.x;
                float vy = c[mt][nt][hf * 2 + 1] + bi.y;
                *(half2*)&Out[(size_t)row * N + col] = __floats2half2_rn(vx, vy);
            }
        }
    }
}

// ---------------- fused fp32 -> fp16 convert of ALL weights ----------------
#define CVT_S1 (DD*DD/4)
#define CVT_S2 (DD*FFD/4)
#define CVT_TOTAL4 (4*CVT_S1 + 4*CVT_S2)

__global__ void __launch_bounds__(256) convert_all_kernel(
    const float* __restrict__ wq, const float* __restrict__ wk,
    const float* __restrict__ wv, const float* __restrict__ wo,
    const float* __restrict__ W1, const float* __restrict__ J1,
    const float* __restrict__ W2, const float* __restrict__ J2,
    __half* dwq, __half* dwk, __half* dwv, __half* dwo,
    __half* dW1, __half* dJ1, __half* dW2, __half* dJ2)
{
    int i = blockIdx.x * 256 + threadIdx.x;
    if (i >= CVT_TOTAL4) return;
    const float* src; __half* dst; int off;
    if (i < 4 * CVT_S1) {
        int w = i >> 18; off = i & (CVT_S1 - 1);
        src = (w == 0) ? wq : (w == 1) ? wk : (w == 2) ? wv : wo;
        dst = (w == 0) ? dwq : (w == 1) ? dwk : (w == 2) ? dwv : dwo;
    } else {
        int j = i - 4 * CVT_S1;
        int w = j >> 20; off = j & (CVT_S2 - 1);
        src = (w == 0) ? W1 : (w == 1) ? J1 : (w == 2) ? W2 : J2;
        dst = (w == 0) ? dW1 : (w == 1) ? dJ1 : (w == 2) ? dW2 : dJ2;
    }
    float4 v = *(const float4*)&src[(size_t)off * 4];
    *(half2*)&dst[(size_t)off * 4]     = __floats2half2_rn(v.x, v.y);
    *(half2*)&dst[(size_t)off * 4 + 2] = __floats2half2_rn(v.z, v.w);
}

// ---------------------------------------------------------------------------
// FP16 flash attention with fused tQJ prologue + pipelined mainloop.
// smem tiles: Q, T, P, K0, G0, K1, G1, V  (8 x 64x72 fp16 = 73728 B)
// KG double-buffered (prefetch next tile during compute); V in its own
// cp.async group, waited only before PV (overlaps S/D mma + softmax).
// ---------------------------------------------------------------------------
#define AST 72
#define ATILE (64*AST)
#define ATT_SMEM (8*ATILE*2)

__global__ void __launch_bounds__(128) attn_f16_kernel(
    const __half* __restrict__ Q,  const __half* __restrict__ K,
    const __half* __restrict__ TK, const __half* __restrict__ V,
    const float* __restrict__ Jat, __half* __restrict__ O,
    const float* __restrict__ lam_p)
{
    extern __shared__ __half smh[];
    const uint32_t su = (uint32_t)__cvta_generic_to_shared(smh);
    const uint32_t Qb = su;
    const uint32_t Tb = Qb + ATILE * 2;
    const uint32_t Pb = Tb + ATILE * 2;
    const uint32_t K0 = Pb + ATILE * 2;
    const uint32_t G0 = K0 + ATILE * 2;
    const uint32_t K1 = G0 + ATILE * 2;
    const uint32_t G1 = K1 + ATILE * 2;
    const uint32_t Vb = G1 + ATILE * 2;
    __half* sm = smh;

    const int tid = threadIdx.x;
    const int wid = tid >> 5, lane = tid & 31;
    const int gid = lane >> 2, tig = lane & 3;
    const int mrow = wid * 16;
    const int bh = blockIdx.y, b = bh >> 4, h = bh & 15;
    const int q0 = blockIdx.x << 6;
    const float lam = __ldg(lam_p);

    const int t7 = lane & 7;
    const uint32_t aro = ((lane >> 3) & 1) * 8 + t7, ak8 = ((lane >> 4) & 1) * 8;
    const uint32_t bro = ((lane >> 4) & 1) * 8 + t7, bk8 = ((lane >> 3) & 1) * 8;
    const uint32_t vko = ((lane >> 3) & 1) * 8 + t7, vn8 = ((lane >> 4) & 1) * 8;

    // ---- prologue: stage Q, stage J[h] fp16 (into K0), T = tanh(Q) @ J ----
    for (int i = tid; i < 512; i += 128) {
        int r = i >> 3, c8 = i & 7;
        cp16(Qb + (r * AST + c8 * 8) * 2,
             &Q[((size_t)(b * SS + q0 + r)) * DD + h * HD + c8 * 8]);
    }
    cp_commit();

    for (int i = tid; i < 1024; i += 128) {
        int d = i >> 4, e4 = (i & 15) << 2;
        float4 v = *(const float4*)&Jat[(size_t)h * HD * HD + d * HD + e4];
        *(half2*)&sm[(K0 - su) / 2 + d * AST + e4]     = __floats2half2_rn(v.x, v.y);
        *(half2*)&sm[(K0 - su) / 2 + d * AST + e4 + 2] = __floats2half2_rn(v.z, v.w);
    }
    cp_wait<0>();
    __syncthreads();

    for (int i = tid; i < 2048; i += 128) {
        int r = i >> 5, c2 = (i & 31) << 1;
        half2 q = *(half2*)&sm[(Qb - su) / 2 + r * AST + c2];
        *(half2*)&sm[(Pb - su) / 2 + r * AST + c2] =
            __floats2half2_rn(tanhf(__half2float(q.x)), tanhf(__half2float(q.y)));
    }
    __syncthreads();

    {
        float ct[8][4] = {};
        #pragma unroll
        for (int ks = 0; ks < 4; ks++) {
            uint32_t ap[4], bj[4][4];
            ldsm4(ap, Pb + ((mrow + aro) * AST + ks * 16 + ak8) * 2);
            #pragma unroll
            for (int p = 0; p < 4; p++)
                ldsm4t(bj[p], K0 + ((ks * 16 + vko) * AST + p * 16 + vn8) * 2);
            #pragma unroll
            for (int nt = 0; nt < 8; nt++)
                mma16(ct[nt], ap, bj[nt >> 1][(nt & 1) * 2], bj[nt >> 1][(nt & 1) * 2 + 1]);
        }
        __half* Ts = sm + (Tb - su) / 2;
        #pragma unroll
        for (int nt = 0; nt < 8; nt++) {
            int col = nt * 8 + tig * 2;
            *(half2*)&Ts[(mrow + gid    ) * AST + col] =
                __floats2half2_rn(ct[nt][0], ct[nt][1]);
            *(half2*)&Ts[(mrow + gid + 8) * AST + col] =
                __floats2half2_rn(ct[nt][2], ct[nt][3]);
        }
    }
    __syncthreads();   // all warps done reading J (K0) before KG(0) overwrites

    // ---- pipelined mainloop ----
    auto load_kg = [&](int k0t, int st) {
        uint32_t kb = st ? K1 : K0, gb = st ? G1 : G0;
        for (int i = tid; i < 512; i += 128) {
            int r = i >> 3, c8 = i & 7;
            size_t g = ((size_t)(b * SS + k0t + r)) * DD + h * HD + c8 * 8;
            uint32_t off = (r * AST + c8 * 8) * 2;
            cp16(kb + off, &K[g]);
            cp16(gb + off, &TK[g]);
        }
        cp_commit();
    };
    auto load_v = [&](int k0t) {
        for (int i = tid; i < 512; i += 128) {
            int r = i >> 3, c8 = i & 7;
            cp16(Vb + (r * AST + c8 * 8) * 2,
                 &V[((size_t)(b * SS + k0t + r)) * DD + h * HD + c8 * 8]);
        }
        cp_commit();
    };

    __half* Ps = sm + (Pb - su) / 2;

    load_kg(0, 0);                       // pending: [KG0]

    float m0 = -1e30f, m1 = -1e30f, l0 = 0.f, l1 = 0.f;
    float o[8][4] = {};

    const int KT = SS / 64;
    for (int kt = 0; kt < KT; kt++) {
        int s = kt & 1;
        load_v(kt * 64);                 // pending += V(kt)
        if (kt + 1 < KT) load_kg((kt + 1) * 64, s ^ 1);   // pending += KG(kt+1)

        if (kt + 1 < KT) cp_wait<2>(); else cp_wait<1>(); // KG(kt) ready
        __syncthreads();

        uint32_t Kb = s ? K1 : K0, Gb = s ? G1 : G0;

        float cs[8][4] = {}, cd[8][4] = {};
        #pragma unroll
        for (int ks = 0; ks < 4; ks++) {
            uint32_t aq[4], at[4], bk[4][4], bt[4][4];
            ldsm4(aq, Qb + ((mrow + aro) * AST + ks * 16 + ak8) * 2);
            ldsm4(at, Tb + ((mrow + aro) * AST + ks * 16 + ak8) * 2);
            #pragma unroll
            for (int p = 0; p < 4; p++) {
                uint32_t off = ((p * 16 + bro) * AST + ks * 16 + bk8) * 2;
                ldsm4(bk[p], Kb + off);
                ldsm4(bt[p], Gb + off);
            }
            #pragma unroll
            for (int nt = 0; nt < 8; nt++) {
                mma16(cs[nt], aq, bk[nt >> 1][(nt & 1) * 2], bk[nt >> 1][(nt & 1) * 2 + 1]);
                mma16(cd[nt], at, bt[nt >> 1][(nt & 1) * 2], bt[nt >> 1][(nt & 1) * 2 + 1]);
            }
        }

        float sarr[8][4];
        float mx0 = -1e30f, mx1 = -1e30f;
        #pragma unroll
        for (int nt = 0; nt < 8; nt++) {
            #pragma unroll
            for (int e = 0; e < 4; e++)
                sarr[nt][e] = fmaf(lam, cd[nt][e], cs[nt][e] * INV_SCALE);
            mx0 = fmaxf(mx0, fmaxf(sarr[nt][0], sarr[nt][1]));
            mx1 = fmaxf(mx1, fmaxf(sarr[nt][2], sarr[nt][3]));
        }
        mx0 = fmaxf(mx0, __shfl_xor_sync(0xffffffffu, mx0, 1));
        mx0 = fmaxf(mx0, __shfl_xor_sync(0xffffffffu, mx0, 2));
        mx1 = fmaxf(mx1, __shfl_xor_sync(0xffffffffu, mx1, 1));
        mx1 = fmaxf(mx1, __shfl_xor_sync(0xffffffffu, mx1, 2));
        float mn0 = fmaxf(m0, mx0), mn1 = fmaxf(m1, mx1);
        float corr0 = __expf(m0 - mn0), corr1 = __expf(m1 - mn1);
        m0 = mn0; m1 = mn1;
        l0 *= corr0; l1 *= corr1;

        float sum0 = 0.f, sum1 = 0.f;
        #pragma unroll
        for (int nt = 0; nt < 8; nt++) {
            float p00 = __expf(sarr[nt][0] - mn0);
            float p01 = __expf(sarr[nt][1] - mn0);
            float p10 = __expf(sarr[nt][2] - mn1);
            float p11 = __expf(sarr[nt][3] - mn1);
            sum0 += p00 + p01; sum1 += p10 + p11;
            int col = nt * 8 + tig * 2;
            *(half2*)&Ps[(mrow + gid    ) * AST + col] = __floats2half2_rn(p00, p01);
            *(half2*)&Ps[(mrow + gid + 8) * AST + col] = __floats2half2_rn(p10, p11);
        }
        sum0 += __shfl_xor_sync(0xffffffffu, sum0, 1);
        sum0 += __shfl_xor_sync(0xffffffffu, sum0, 2);
        sum1 += __shfl_xor_sync(0xffffffffu, sum1, 1);
        sum1 += __shfl_xor_sync(0xffffffffu, sum1, 2);
        l0 += sum0; l1 += sum1;

        #pragma unroll
        for (int nt = 0; nt < 8; nt++) {
            o[nt][0] *= corr0; o[nt][1] *= corr0;
            o[nt][2] *= corr1; o[nt][3] *= corr1;
        }

        if (kt + 1 < KT) cp_wait<1>(); else cp_wait<0>();  // V(kt) ready
        __syncthreads();

        #pragma unroll
        for (int ks = 0; ks < 4; ks++) {
            uint32_t ap[4], bv[4][4];
            ldsm4(ap, Pb + ((mrow + aro) * AST + ks * 16 + ak8) * 2);
            #pragma unroll
            for (int p = 0; p < 4; p++)
                ldsm4t(bv[p], Vb + ((ks * 16 + vko) * AST + p * 16 + vn8) * 2);
            #pragma unroll
            for (int nt = 0; nt < 8; nt++)
                mma16(o[nt], ap, bv[nt >> 1][(nt & 1) * 2], bv[nt >> 1][(nt & 1) * 2 + 1]);
        }
        __syncthreads();   // all reads of Vb + stage s done before reuse
    }

    float inv0 = 1.f / l0, inv1 = 1.f / l1;
    int row0 = q0 + mrow + gid, row1 = row0 + 8;
    #pragma unroll
    for (int nt = 0; nt < 8; nt++) {
        int col = nt * 8 + tig * 2;
        *(half2*)&O[((size_t)(b * SS + row0)) * DD + h * HD + col] =
            __floats2half2_rn(o[nt][0] * inv0, o[nt][1] * inv0);
        *(half2*)&O[((size_t)(b * SS + row1)) * DD + h * HD + col] =
            __floats2half2_rn(o[nt][2] * inv1, o[nt][3] * inv1);
    }
}

// ---------------- LayerNorm: fp32 in, fp16 out (+opt fp16 tanh out) ----------------
__global__ void __launch_bounds__(256) ln_kernel(
    const float* __restrict__ X, const float* __restrict__ g,
    const float* __restrict__ b, __half* __restrict__ Y,
    __half* __restrict__ YT, int N)
{
    int row = blockIdx.x;
    const float* x = X + (size_t)row * N;
    float s = 0.f, s2 = 0.f;
    for (int i = threadIdx.x; i < N; i += 256) {
        float v = x[i];
        s += v; s2 = fmaf(v, v, s2);
    }
    __shared__ float sh[64];
    for (int o = 16; o > 0; o >>= 1) {
        s  += __shfl_down_sync(0xffffffffu, s,  o);
        s2 += __shfl_down_sync(0xffffffffu, s2, o);
    }
    int wid = threadIdx.x >> 5, lane = threadIdx.x & 31;
    if (lane == 0) { sh[wid] = s; sh[wid + 32] = s2; }
    __syncthreads();
    if (threadIdx.x == 0) {
        float ts = 0.f, ts2 = 0.f;
        for (int w = 0; w < 8; w++) { ts += sh[w]; ts2 += sh[w + 32]; }
        float mu = ts / N, var = ts2 / N - mu * mu;
        sh[0] = mu; sh[1] = rsqrtf(var + 1e-5f);
    }
    __syncthreads();
    float mu = sh[0], rstd = sh[1];
    for (int i = threadIdx.x; i < N; i += 256) {
        float v = (x[i] - mu) * rstd * g[i] + b[i];
        Y[(size_t)row * N + i] = __float2half(v);
        if (YT) YT[(size_t)row * N + i] = __float2half(tanhf(v));
    }
}

// ---------------- QBNN combine + LN + GELU (fp16 ht/dlt in, half2 vec) ------------
__global__ void __launch_bounds__(256) qln_gelu_kernel(
    const __half* __restrict__ HT, const __half* __restrict__ DLT,
    const float* __restrict__ g,  const float* __restrict__ b,
    const float* __restrict__ Res, float* __restrict__ Yf,
    __half* __restrict__ Yh, __half* __restrict__ Yth, int N)
{
    extern __shared__ float rowbuf[];
    __shared__ float sh[64];
    int row = blockIdx.x;
    size_t base = (size_t)row * N;
    int N2 = N >> 1;

    float s = 0.f, s2 = 0.f;
    for (int i = threadIdx.x; i < N2; i += 256) {
        half2 ht2 = *(const half2*)&HT[base + i * 2];
        half2 dl2 = *(const half2*)&DLT[base + i * 2];
        float hx = __half2float(ht2.x), hy = __half2float(ht2.y);
        float vx = fmaf(LAM_EFF * __half2float(dl2.x), tanhf(hx), hx);
        float vy = fmaf(LAM_EFF * __half2float(dl2.y), tanhf(hy), hy);
        rowbuf[i * 2] = vx; rowbuf[i * 2 + 1] = vy;
        s += vx + vy; s2 = fmaf(vx, vx, fmaf(vy, vy, s2));
    }
    for (int o = 16; o > 0; o >>= 1) {
        s  += __shfl_down_sync(0xffffffffu, s,  o);
        s2 += __shfl_down_sync(0xffffffffu, s2, o);
    }
    int wid = threadIdx.x >> 5, lane = threadIdx.x & 31;
    if (lane == 0) { sh[wid] = s; sh[wid + 32] = s2; }
    __syncthreads();
    if (threadIdx.x == 0) {
        float ts = 0.f, ts2 = 0.f;
        for (int w = 0; w < 8; w++) { ts += sh[w]; ts2 += sh[w + 32]; }
        float mu = ts / N, var = ts2 / N - mu * mu;
        sh[0] = mu; sh[1] = rsqrtf(var + 1e-5f);
    }
    __syncthreads();
    float mu = sh[0], rstd = sh[1];
    for (int i = threadIdx.x; i < N2; i += 256) {
        float2 gg = *(const float2*)&g[i * 2];
        float2 bb = *(const float2*)&b[i * 2];
        float vx = (rowbuf[i * 2]     - mu) * rstd * gg.x + bb.x;
        float vy = (rowbuf[i * 2 + 1] - mu) * rstd * gg.y + bb.y;
        float gex = vx * normcdff(vx), gey = vy * normcdff(vy);
        float ox = gex, oy = gey;
        if (Res) {
            float2 rr = *(const float2*)&Res[base + i * 2];
            ox += rr.x; oy += rr.y;
        }
        if (Yf)  *(float2*)&Yf[base + i * 2] = make_float2(ox, oy);
        if (Yh)  *(half2*)&Yh[base + i * 2] = __floats2half2_rn(ox, oy);
        if (Yth) *(half2*)&Yth[base + i * 2] =
                     __floats2half2_rn(tanhf(ox), tanhf(oy));
    }
}

// ---------------- host ----------------
template<typename T> static T* symaddr(const void* s)
{
    void* p = nullptr;
    cudaGetSymbolAddress(&p, s);
    return (T*)p;
}

extern "C" void kernel_launch(void* const* d_in, const int* in_sizes, int n_in,
                              void* d_out, int out_size)
{
    (void)in_sizes; (void)n_in; (void)out_size;

    const float* x   = (const float*)d_in[0];
    const float* wq  = (const float*)d_in[1];
    const float* bq  = (const float*)d_in[2];
    const float* wk  = (const float*)d_in[3];
    const float* bk  = (const float*)d_in[4];
    const float* wv  = (const float*)d_in[5];
    const float* bv  = (const float*)d_in[6];
    const float* wo  = (const float*)d_in[7];
    const float* bo  = (const float*)d_in[8];
    const float* Jat = (const float*)d_in[9];
    const float* lam = (const float*)d_in[10];
    const float* gat = (const float*)d_in[11];
    const float* bat = (const float*)d_in[12];
    const float* W1  = (const float*)d_in[13];
    const float* b1  = (const float*)d_in[14];
    const float* J1  = (const float*)d_in[15];
    const float* g1  = (const float*)d_in[17];
    const float* be1 = (const float*)d_in[18];
    const float* W2  = (const float*)d_in[19];
    const float* b2  = (const float*)d_in[20];
    const float* J2  = (const float*)d_in[21];
    const float* g2  = (const float*)d_in[23];
    const float* be2 = (const float*)d_in[24];
    const float* gf  = (const float*)d_in[25];
    const float* bf  = (const float*)d_in[26];
    float* out = (float*)d_out;

    __half* p_xn  = symaddr<__half>(h_xn);
    __half* p_Q   = symaddr<__half>(h_Q);
    __half* p_K   = symaddr<__half>(h_K);
    __half* p_tK  = symaddr<__half>(h_tK);
    __half* p_V   = symaddr<__half>(h_V);
    __half* p_ao  = symaddr<__half>(h_ao);
    float*  p_x1  = symaddr<float>(f_x1);
    __half* p_th  = symaddr<__half>(h_th);
    __half* p_hh  = symaddr<__half>(h_hh);
    __half* p_dl  = symaddr<__half>(h_dl);
    __half* p_h1  = symaddr<__half>(h_h1);
    __half* p_th1 = symaddr<__half>(h_th1);
    __half* p_wq  = symaddr<__half>(h_wq);
    __half* p_wk  = symaddr<__half>(h_wk);
    __half* p_wv  = symaddr<__half>(h_wv);
    __half* p_wo  = symaddr<__half>(h_wo);
    __half* p_W1  = symaddr<__half>(h_W1);
    __half* p_J1  = symaddr<__half>(h_J1);
    __half* p_W2  = symaddr<__half>(h_W2);
    __half* p_J2  = symaddr<__half>(h_J2);

    cudaFuncSetAttribute(attn_f16_kernel,
                         cudaFuncAttributeMaxDynamicSharedMemorySize, ATT_SMEM);
    cudaFuncSetAttribute(gemm_qkv_kernel,
                         cudaFuncAttributeMaxDynamicSharedMemorySize, GEMM_SMEM);
    cudaFuncSetAttribute(gemm_ffdual_kernel,
                         cudaFuncAttributeMaxDynamicSharedMemorySize, GEMM_SMEM);
    cudaFuncSetAttribute(gemm_f16_kernel<true, true, false>,
                         cudaFuncAttributeMaxDynamicSharedMemorySize, GEMM_SMEM);

    convert_all_kernel<<<CVT_TOTAL4 / 256, 256>>>(
        wq, wk, wv, wo, W1, J1, W2, J2,
        p_wq, p_wk, p_wv, p_wo, p_W1, p_J1, p_W2, p_J2);

    // --- attention branch ---
    ln_kernel<<<NT, 256>>>(x, gat, bat, p_xn, nullptr, DD);

    gemm_qkv_kernel<<<dim3(24, NT / 128), 256, GEMM_SMEM>>>(
        p_xn, p_wq, p_wk, p_wv, bq, bk, bv, p_Q, p_K, p_V, p_tK);

    attn_f16_kernel<<<dim3(SS / 64, BB * HH), 128, ATT_SMEM>>>(
        p_Q, p_K, p_tK, p_V, Jat, p_ao, lam);

    gemm_f16_kernel<true, true, false><<<dim3(8, NT / 128), 256, GEMM_SMEM>>>(
        p_ao, p_wo, bo, x, p_x1, nullptr, NT, DD, DD);

    // --- QBNN FFN layer 1 (merged dual GEMM) ---
    ln_kernel<<<NT, 256>>>(p_x1, gf, bf, p_xn, p_th, DD);

    gemm_ffdual_kernel<<<dim3(2 * FFD / 128, NT / 128), 256, GEMM_SMEM>>>(
        p_xn, p_th, p_W1, p_J1, b1, p_hh, p_dl, FFD, DD);

    qln_gelu_kernel<<<NT, 256, FFD * sizeof(float)>>>(
        p_hh, p_dl, g1, be1, nullptr, nullptr, p_h1, p_th1, FFD);

    // --- QBNN FFN layer 2 (merged dual GEMM) ---
    gemm_ffdual_kernel<<<dim3(2 * DD / 128, NT / 128), 256, GEMM_SMEM>>>(
        p_h1, p_th1, p_W2, p_J2, b2, p_hh, p_dl, DD, FFD);

    qln_gelu_kernel<<<NT, 256, DD * sizeof(float)>>>(
        p_hh, p_dl, g2, be2, p_x1, out, nullptr, nullptr, DD);
}